// round 4
// baseline (speedup 1.0000x reference)
#include <cuda_runtime.h>
#include <cuda_bf16.h>
#include <math.h>

// Problem constants
#define B_  2
#define N_  2048
#define DIM_ 1024
#define H_  16
#define DH_ 64
#define BH_ (B_*H_)            // 32
#define ROWS_ (B_*N_)          // 4096
#define EPS_ 1.1920929e-07f

// ---------------------------------------------------------------------------
// Scratch (allocation-free: __device__ globals)
// ---------------------------------------------------------------------------
__device__ float g_x[(size_t)ROWS_*DIM_];          // rmsnorm'd tokens
__device__ float g_q[(size_t)BH_*N_*DH_];          // (b,h,n,d)
__device__ float g_k[(size_t)3*BH_*N_*DH_];        // (e,b,h,n,d)
__device__ float g_v[(size_t)3*BH_*N_*DH_];
__device__ float g_n[(size_t)3*BH_*N_*DH_];        // nq|nk|nv slabs
__device__ float g_o[(size_t)BH_*N_*DH_];          // outer attend output
__device__ float g_cos[N_*32];
__device__ float g_sin[N_*32];

// ---------------------------------------------------------------------------
// RMSNorm over DIM=1024 (one block per row)
// ---------------------------------------------------------------------------
__global__ void rmsnorm_dim_kernel(const float* __restrict__ in,
                                   const float* __restrict__ w,
                                   float* __restrict__ out) {
    int row = blockIdx.x;
    const float* p = in + (size_t)row * DIM_;
    float s = 0.f;
    for (int i = threadIdx.x; i < DIM_; i += 256) { float v = p[i]; s += v*v; }
    __shared__ float sm[8];
    for (int o = 16; o > 0; o >>= 1) s += __shfl_xor_sync(~0u, s, o);
    if ((threadIdx.x & 31) == 0) sm[threadIdx.x >> 5] = s;
    __syncthreads();
    if (threadIdx.x < 8) {
        s = sm[threadIdx.x];
        for (int o = 4; o > 0; o >>= 1) s += __shfl_xor_sync(0xffu, s, o);
        if (threadIdx.x == 0) sm[0] = s;
    }
    __syncthreads();
    float inv = rsqrtf(sm[0] * (1.f/DIM_) + EPS_);
    for (int i = threadIdx.x; i < DIM_; i += 256)
        out[(size_t)row*DIM_ + i] = p[i] * inv * w[i];
}

// ---------------------------------------------------------------------------
// RMSNorm over DH=64 (one warp per row), optional per-slab weight
// ---------------------------------------------------------------------------
__global__ void rmsnorm_dh_kernel(float* __restrict__ x, const float* __restrict__ w,
                                  int use_e, int total_rows) {
    int warp = (blockIdx.x * blockDim.x + threadIdx.x) >> 5;
    if (warp >= total_rows) return;
    int lane = threadIdx.x & 31;
    float* p = x + (size_t)warp * DH_;
    float a = p[lane], b = p[lane + 32];
    float s = a*a + b*b;
    for (int o = 16; o > 0; o >>= 1) s += __shfl_xor_sync(~0u, s, o);
    float inv = rsqrtf(s * (1.f/DH_) + EPS_);
    const float* ww = w + (use_e ? (warp / (BH_*N_)) * DH_ : 0);
    p[lane]      = a * inv * ww[lane];
    p[lane + 32] = b * inv * ww[lane + 32];
}

// ---------------------------------------------------------------------------
// RoPE table + in-place RoPE apply
// ---------------------------------------------------------------------------
__global__ void rope_table_kernel() {
    int idx = blockIdx.x * blockDim.x + threadIdx.x;
    if (idx >= N_*32) return;
    int n = idx >> 5, t = idx & 31;
    float inv_freq = powf(10000.f, -(2.f * (float)t) / 64.f);
    float ang = (float)n * inv_freq;
    g_cos[idx] = cosf(ang);
    g_sin[idx] = sinf(ang);
}

__global__ void rope_kernel(float* __restrict__ x, int total_rows) {
    int idx = blockIdx.x * blockDim.x + threadIdx.x;
    if (idx >= total_rows * 32) return;
    int row = idx >> 5, t = idx & 31;
    int n = row & (N_-1);
    float c = g_cos[(n<<5) + t], s = g_sin[(n<<5) + t];
    float* p = x + ((size_t)row << 6) + (t << 1);
    float2 v = *(float2*)p;
    float2 r; r.x = v.x*c - v.y*s; r.y = v.y*c + v.x*s;
    *(float2*)p = r;
}

// ---------------------------------------------------------------------------
// SGEMM v2: 128x128 block tile, 256 threads, 8x8 micro-tile, K-step 8,
// register-prefetch software pipeline.
// AMODE: 0 = A row-major (M x K), 1 = gather from (b,h,n,d) -> (bn, hd)
// CMODE: 0 = row-major, 1 = q layout (b,h,n,d), 2 = kv layout (e,b,h,n,d)
// ---------------------------------------------------------------------------
template<int AMODE, int CMODE>
__global__ __launch_bounds__(256) void sgemm2_kernel(const float* __restrict__ A,
                                                     const float* __restrict__ Bm,
                                                     float* __restrict__ C,
                                                     int M, int K, int Nc) {
    __shared__ float As[8][128];
    __shared__ float Bs[8][128];
    int tx = threadIdx.x;
    int brow = blockIdx.y * 128, bcol = blockIdx.x * 128;

    int ar = tx >> 1,  ac = (tx & 1) << 2;    // A tile: row 0..127, k 0 or 4
    int brk = tx >> 5, bc = (tx & 31) << 2;   // B tile: k 0..7, col 0..124
    int ty = tx >> 4,  tcx = tx & 15;         // compute: 16x16 thread grid

    float acc[8][8];
    #pragma unroll
    for (int i = 0; i < 8; i++)
        #pragma unroll
        for (int j = 0; j < 8; j++) acc[i][j] = 0.f;

    auto loadA = [&](int k0) -> float4 {
        if (AMODE == 0)
            return *(const float4*)&A[(size_t)(brow + ar) * K + k0 + ac];
        int row = brow + ar;
        int b = row >> 11, n = row & (N_-1);
        int kk = k0 + ac;
        int h = kk >> 6, d = kk & 63;
        return *(const float4*)&A[((((size_t)b*H_ + h)*N_ + n) << 6) + d];
    };

    float4 apre = loadA(0);
    float4 bpre = *(const float4*)&Bm[(size_t)brk * Nc + bcol + bc];

    for (int k0 = 0; k0 < K; k0 += 8) {
        As[ac+0][ar] = apre.x; As[ac+1][ar] = apre.y;
        As[ac+2][ar] = apre.z; As[ac+3][ar] = apre.w;
        *(float4*)&Bs[brk][bc] = bpre;
        __syncthreads();
        if (k0 + 8 < K) {
            apre = loadA(k0 + 8);
            bpre = *(const float4*)&Bm[(size_t)(k0 + 8 + brk) * Nc + bcol + bc];
        }
        #pragma unroll
        for (int k = 0; k < 8; k++) {
            float4 a0 = *(float4*)&As[k][ty*8];
            float4 a1 = *(float4*)&As[k][ty*8 + 4];
            float4 b0 = *(float4*)&Bs[k][tcx*8];
            float4 b1 = *(float4*)&Bs[k][tcx*8 + 4];
            float av[8] = {a0.x,a0.y,a0.z,a0.w,a1.x,a1.y,a1.z,a1.w};
            float bv[8] = {b0.x,b0.y,b0.z,b0.w,b1.x,b1.y,b1.z,b1.w};
            #pragma unroll
            for (int i = 0; i < 8; i++)
                #pragma unroll
                for (int j = 0; j < 8; j++) acc[i][j] += av[i]*bv[j];
        }
        __syncthreads();
    }

    int col0 = bcol + tcx*8;
    #pragma unroll
    for (int i = 0; i < 8; i++) {
        int row = brow + ty*8 + i;
        int b = row >> 11, n = row & (N_-1);
        float4 v0 = make_float4(acc[i][0], acc[i][1], acc[i][2], acc[i][3]);
        float4 v1 = make_float4(acc[i][4], acc[i][5], acc[i][6], acc[i][7]);
        float* p;
        if (CMODE == 0) {
            p = &C[(size_t)row * Nc + col0];
        } else if (CMODE == 1) {
            int h = col0 >> 6, d = col0 & 63;
            p = &C[((((size_t)b*H_ + h)*N_ + n) << 6) + d];
        } else {
            int e = col0 >> 10, h = (col0 >> 6) & 15, d = col0 & 63;
            p = &C[(((((size_t)e*B_ + b)*H_ + h)*N_ + n) << 6) + d];
        }
        *(float4*)p = v0;
        *(float4*)(p + 4) = v1;
    }
}

// ---------------------------------------------------------------------------
// Causal flash attention v2: 256 threads/block, 128 q-rows, 2 threads per
// q-row each owning 32 of the 64 head dims; dot completed by shfl_xor(1).
// K/V tiles 32x64 in smem, online softmax per 16-key subtile.
// grid = (N/128, BH, n_e). Q indexed by blockIdx.y only (shared across e).
// ---------------------------------------------------------------------------
__global__ __launch_bounds__(256) void attn2_kernel(const float* __restrict__ Q,
                                                    const float* __restrict__ K,
                                                    const float* __restrict__ V,
                                                    float* __restrict__ O) {
    __shared__ float ks[32*64];
    __shared__ float vs[32*64];
    size_t mat = blockIdx.y + (size_t)blockIdx.z * BH_;
    const float* q = Q + ((size_t)blockIdx.y << 17);
    const float* k = K + (mat << 17);
    const float* v = V + (mat << 17);
    float*       o = O + (mat << 17);
    int tid = threadIdx.x;
    int qi = blockIdx.x * 128 + (tid >> 1);
    int dh = (tid & 1) << 5;   // which 32-dim half this thread owns

    float qr[32];
    #pragma unroll
    for (int d = 0; d < 32; d += 4) {
        float4 t = *(const float4*)&q[((size_t)qi << 6) + dh + d];
        qr[d] = t.x; qr[d+1] = t.y; qr[d+2] = t.z; qr[d+3] = t.w;
    }
    float m = -INFINITY, l = 0.f;
    float acc[32];
    #pragma unroll
    for (int d = 0; d < 32; d++) acc[d] = 0.f;

    int kend = blockIdx.x * 128 + 128;
    for (int k0 = 0; k0 < kend; k0 += 32) {
        __syncthreads();
        #pragma unroll
        for (int i = tid * 4; i < 32*64; i += 256*4) {
            *(float4*)&ks[i] = *(const float4*)&k[((size_t)k0 << 6) + i];
            *(float4*)&vs[i] = *(const float4*)&v[((size_t)k0 << 6) + i];
        }
        __syncthreads();
        #pragma unroll
        for (int sub = 0; sub < 32; sub += 16) {
            float s[16];
            float mt = m;
            #pragma unroll
            for (int j = 0; j < 16; j++) {
                float dot = 0.f;
                const float* kr = &ks[((sub + j) << 6) + dh];
                #pragma unroll
                for (int d = 0; d < 32; d += 4) {
                    float4 kk = *(const float4*)&kr[d];
                    dot += qr[d]*kk.x + qr[d+1]*kk.y + qr[d+2]*kk.z + qr[d+3]*kk.w;
                }
                dot += __shfl_xor_sync(~0u, dot, 1);
                s[j] = (k0 + sub + j <= qi) ? dot * 0.125f : -INFINITY;
                mt = fmaxf(mt, s[j]);
            }
            float corr = __expf(m - mt);
            m = mt;
            l *= corr;
            #pragma unroll
            for (int d = 0; d < 32; d++) acc[d] *= corr;
            #pragma unroll
            for (int j = 0; j < 16; j++) {
                float p = __expf(s[j] - m);
                l += p;
                const float* vr = &vs[((sub + j) << 6) + dh];
                #pragma unroll
                for (int d = 0; d < 32; d += 4) {
                    float4 vv = *(const float4*)&vr[d];
                    acc[d]   += p*vv.x; acc[d+1] += p*vv.y;
                    acc[d+2] += p*vv.z; acc[d+3] += p*vv.w;
                }
            }
        }
    }
    float inv = 1.f / l;
    #pragma unroll
    for (int d = 0; d < 32; d += 4) {
        float4 t;
        t.x = acc[d]*inv; t.y = acc[d+1]*inv; t.z = acc[d+2]*inv; t.w = acc[d+3]*inv;
        *(float4*)&o[((size_t)qi << 6) + dh + d] = t;
    }
}

// ---------------------------------------------------------------------------
// Launch
// ---------------------------------------------------------------------------
extern "C" void kernel_launch(void* const* d_in, const int* in_sizes, int n_in,
                              void* d_out, int out_size) {
    const float* tokens        = (const float*)d_in[0];
    const float* w_norm        = (const float*)d_in[1];
    const float* w_q           = (const float*)d_in[2];
    const float* w_k           = (const float*)d_in[3];
    const float* w_v           = (const float*)d_in[4];
    const float* w_key_norms   = (const float*)d_in[5];
    const float* w_nested_knorm= (const float*)d_in[6];
    const float* w_out         = (const float*)d_in[7];
    float* out = (float*)d_out;

    float *px, *pq, *pk, *pv, *pn, *po;
    cudaGetSymbolAddress((void**)&px, g_x);
    cudaGetSymbolAddress((void**)&pq, g_q);
    cudaGetSymbolAddress((void**)&pk, g_k);
    cudaGetSymbolAddress((void**)&pv, g_v);
    cudaGetSymbolAddress((void**)&pn, g_n);
    cudaGetSymbolAddress((void**)&po, g_o);

    // 1) x = rmsnorm(tokens)
    rmsnorm_dim_kernel<<<ROWS_, 256>>>(tokens, w_norm, px);
    // 2) rope tables
    rope_table_kernel<<<(N_*32 + 255)/256, 256>>>();
    // 3) q/k/v projections with layout-transposing epilogues
    sgemm2_kernel<0,1><<<dim3(DIM_/128, ROWS_/128), 256>>>(px, w_q, pq, ROWS_, DIM_, DIM_);
    sgemm2_kernel<0,2><<<dim3(3*DIM_/128, ROWS_/128), 256>>>(px, w_k, pk, ROWS_, DIM_, 3*DIM_);
    sgemm2_kernel<0,2><<<dim3(3*DIM_/128, ROWS_/128), 256>>>(px, w_v, pv, ROWS_, DIM_, 3*DIM_);
    // 4) key rmsnorm (per-slab weight), then rope q and all k slabs
    {
        int rows = 3*BH_*N_;
        rmsnorm_dh_kernel<<<(rows*32 + 255)/256, 256>>>(pk, w_key_norms, 1, rows);
        rope_kernel<<<(BH_*N_*32 + 255)/256, 256>>>(pq, BH_*N_);
        rope_kernel<<<(rows*32 + 255)/256, 256>>>(pk, rows);
    }
    // 5) three inner causal attentions -> nq|nk|nv
    attn2_kernel<<<dim3(N_/128, BH_, 3), 256>>>(pq, pk, pv, pn);
    // 6) nk rmsnorm, rope nq & nk
    {
        float* pnq = pn;
        float* pnk = pn + (size_t)BH_*N_*DH_;
        int rows = BH_*N_;
        rmsnorm_dh_kernel<<<(rows*32 + 255)/256, 256>>>(pnk, w_nested_knorm, 0, rows);
        rope_kernel<<<(rows*32 + 255)/256, 256>>>(pnq, rows);
        rope_kernel<<<(rows*32 + 255)/256, 256>>>(pnk, rows);
    }
    // 7) outer causal attention: attend(nq, nk, nv) -> g_o
    {
        float* pnq = pn;
        float* pnk = pn + (size_t)BH_*N_*DH_;
        float* pnv = pn + (size_t)2*BH_*N_*DH_;
        attn2_kernel<<<dim3(N_/128, BH_, 1), 256>>>(pnq, pnk, pnv, po);
    }
    // 8) output projection with gathered A (transpose fold)
    sgemm2_kernel<1,0><<<dim3(DIM_/128, ROWS_/128), 256>>>(po, w_out, out, ROWS_, DIM_, DIM_);
}

// round 5
// speedup vs baseline: 1.6438x; 1.6438x over previous
#include <cuda_runtime.h>
#include <cuda_bf16.h>
#include <math.h>

// Problem constants
#define B_  2
#define N_  2048
#define DIM_ 1024
#define H_  16
#define DH_ 64
#define BH_ (B_*H_)            // 32
#define ROWS_ (B_*N_)          // 4096
#define EPS_ 1.1920929e-07f

// ---------------------------------------------------------------------------
// Scratch (allocation-free: __device__ globals)
// ---------------------------------------------------------------------------
__device__ float g_x[(size_t)ROWS_*DIM_];          // rmsnorm'd tokens
__device__ float g_q[(size_t)BH_*N_*DH_];          // (b,h,n,d)
__device__ float g_k[(size_t)3*BH_*N_*DH_];        // (e,b,h,n,d)
__device__ float g_v[(size_t)3*BH_*N_*DH_];
__device__ float g_n[(size_t)3*BH_*N_*DH_];        // nq|nk|nv slabs
__device__ float g_o[(size_t)BH_*N_*DH_];          // outer attend output
__device__ float g_cos[N_*32];
__device__ float g_sin[N_*32];

// ---------------------------------------------------------------------------
// RMSNorm over DIM=1024 (one block per row)
// ---------------------------------------------------------------------------
__global__ void rmsnorm_dim_kernel(const float* __restrict__ in,
                                   const float* __restrict__ w,
                                   float* __restrict__ out) {
    int row = blockIdx.x;
    const float* p = in + (size_t)row * DIM_;
    float s = 0.f;
    for (int i = threadIdx.x; i < DIM_; i += 256) { float v = p[i]; s += v*v; }
    __shared__ float sm[8];
    for (int o = 16; o > 0; o >>= 1) s += __shfl_xor_sync(~0u, s, o);
    if ((threadIdx.x & 31) == 0) sm[threadIdx.x >> 5] = s;
    __syncthreads();
    if (threadIdx.x < 8) {
        s = sm[threadIdx.x];
        for (int o = 4; o > 0; o >>= 1) s += __shfl_xor_sync(0xffu, s, o);
        if (threadIdx.x == 0) sm[0] = s;
    }
    __syncthreads();
    float inv = rsqrtf(sm[0] * (1.f/DIM_) + EPS_);
    for (int i = threadIdx.x; i < DIM_; i += 256)
        out[(size_t)row*DIM_ + i] = p[i] * inv * w[i];
}

// ---------------------------------------------------------------------------
// RMSNorm over DH=64 (one warp per row), optional per-slab weight
// ---------------------------------------------------------------------------
__global__ void rmsnorm_dh_kernel(float* __restrict__ x, const float* __restrict__ w,
                                  int use_e, int total_rows) {
    int warp = (blockIdx.x * blockDim.x + threadIdx.x) >> 5;
    if (warp >= total_rows) return;
    int lane = threadIdx.x & 31;
    float* p = x + (size_t)warp * DH_;
    float a = p[lane], b = p[lane + 32];
    float s = a*a + b*b;
    for (int o = 16; o > 0; o >>= 1) s += __shfl_xor_sync(~0u, s, o);
    float inv = rsqrtf(s * (1.f/DH_) + EPS_);
    const float* ww = w + (use_e ? (warp / (BH_*N_)) * DH_ : 0);
    p[lane]      = a * inv * ww[lane];
    p[lane + 32] = b * inv * ww[lane + 32];
}

// ---------------------------------------------------------------------------
// RoPE table + in-place RoPE apply
// ---------------------------------------------------------------------------
__global__ void rope_table_kernel() {
    int idx = blockIdx.x * blockDim.x + threadIdx.x;
    if (idx >= N_*32) return;
    int n = idx >> 5, t = idx & 31;
    float inv_freq = powf(10000.f, -(2.f * (float)t) / 64.f);
    float ang = (float)n * inv_freq;
    g_cos[idx] = cosf(ang);
    g_sin[idx] = sinf(ang);
}

__global__ void rope_kernel(float* __restrict__ x, int total_rows) {
    int idx = blockIdx.x * blockDim.x + threadIdx.x;
    if (idx >= total_rows * 32) return;
    int row = idx >> 5, t = idx & 31;
    int n = row & (N_-1);
    float c = g_cos[(n<<5) + t], s = g_sin[(n<<5) + t];
    float* p = x + ((size_t)row << 6) + (t << 1);
    float2 v = *(float2*)p;
    float2 r; r.x = v.x*c - v.y*s; r.y = v.y*c + v.x*s;
    *(float2*)p = r;
}

// ---------------------------------------------------------------------------
// SGEMM v2: 128x128 block tile, 256 threads, 8x8 micro-tile, K-step 8.
// ---------------------------------------------------------------------------
template<int AMODE, int CMODE>
__global__ __launch_bounds__(256) void sgemm2_kernel(const float* __restrict__ A,
                                                     const float* __restrict__ Bm,
                                                     float* __restrict__ C,
                                                     int M, int K, int Nc) {
    __shared__ float As[8][128];
    __shared__ float Bs[8][128];
    int tx = threadIdx.x;
    int brow = blockIdx.y * 128, bcol = blockIdx.x * 128;

    int ar = tx >> 1,  ac = (tx & 1) << 2;
    int brk = tx >> 5, bc = (tx & 31) << 2;
    int ty = tx >> 4,  tcx = tx & 15;

    float acc[8][8];
    #pragma unroll
    for (int i = 0; i < 8; i++)
        #pragma unroll
        for (int j = 0; j < 8; j++) acc[i][j] = 0.f;

    auto loadA = [&](int k0) -> float4 {
        if (AMODE == 0)
            return *(const float4*)&A[(size_t)(brow + ar) * K + k0 + ac];
        int row = brow + ar;
        int b = row >> 11, n = row & (N_-1);
        int kk = k0 + ac;
        int h = kk >> 6, d = kk & 63;
        return *(const float4*)&A[((((size_t)b*H_ + h)*N_ + n) << 6) + d];
    };

    float4 apre = loadA(0);
    float4 bpre = *(const float4*)&Bm[(size_t)brk * Nc + bcol + bc];

    for (int k0 = 0; k0 < K; k0 += 8) {
        As[ac+0][ar] = apre.x; As[ac+1][ar] = apre.y;
        As[ac+2][ar] = apre.z; As[ac+3][ar] = apre.w;
        *(float4*)&Bs[brk][bc] = bpre;
        __syncthreads();
        if (k0 + 8 < K) {
            apre = loadA(k0 + 8);
            bpre = *(const float4*)&Bm[(size_t)(k0 + 8 + brk) * Nc + bcol + bc];
        }
        #pragma unroll
        for (int k = 0; k < 8; k++) {
            float4 a0 = *(float4*)&As[k][ty*8];
            float4 a1 = *(float4*)&As[k][ty*8 + 4];
            float4 b0 = *(float4*)&Bs[k][tcx*8];
            float4 b1 = *(float4*)&Bs[k][tcx*8 + 4];
            float av[8] = {a0.x,a0.y,a0.z,a0.w,a1.x,a1.y,a1.z,a1.w};
            float bv[8] = {b0.x,b0.y,b0.z,b0.w,b1.x,b1.y,b1.z,b1.w};
            #pragma unroll
            for (int i = 0; i < 8; i++)
                #pragma unroll
                for (int j = 0; j < 8; j++) acc[i][j] += av[i]*bv[j];
        }
        __syncthreads();
    }

    int col0 = bcol + tcx*8;
    #pragma unroll
    for (int i = 0; i < 8; i++) {
        int row = brow + ty*8 + i;
        int b = row >> 11, n = row & (N_-1);
        float4 v0 = make_float4(acc[i][0], acc[i][1], acc[i][2], acc[i][3]);
        float4 v1 = make_float4(acc[i][4], acc[i][5], acc[i][6], acc[i][7]);
        float* p;
        if (CMODE == 0) {
            p = &C[(size_t)row * Nc + col0];
        } else if (CMODE == 1) {
            int h = col0 >> 6, d = col0 & 63;
            p = &C[((((size_t)b*H_ + h)*N_ + n) << 6) + d];
        } else {
            int e = col0 >> 10, h = (col0 >> 6) & 15, d = col0 & 63;
            p = &C[(((((size_t)e*B_ + b)*H_ + h)*N_ + n) << 6) + d];
        }
        *(float4*)p = v0;
        *(float4*)(p + 4) = v1;
    }
}

// ---------------------------------------------------------------------------
// Causal flash attention v3: GEMM-structured.
// Block: 128 q-rows, 256 threads (16x16), 64-key tiles.
// S-phase: 8x4 micro-tile GEMM over Qs^T/Ks^T in smem.
// Softmax: online, per 16-lane row group via shfl_xor.
// O-phase: 8x4 micro-tile GEMM over P (natural layout) and V in smem.
// Dynamic smem: Qs[64][132] + Ks[64][68] + Vs[64][68] + Ps[128][68]
// ---------------------------------------------------------------------------
#define QS_OFF 0
#define KS_OFF 8448
#define VS_OFF 12800
#define PS_OFF 17152
#define ATTN_SMEM_FLOATS 25856
#define ATTN_SMEM_BYTES (ATTN_SMEM_FLOATS*4)

__global__ __launch_bounds__(256, 2) void attn3_kernel(const float* __restrict__ Q,
                                                       const float* __restrict__ K,
                                                       const float* __restrict__ V,
                                                       float* __restrict__ O) {
    extern __shared__ float smf[];
    float* Qs = smf + QS_OFF;   // [64][132] transposed: Qs[d][i]
    float* Ks = smf + KS_OFF;   // [64][68]  transposed: Ks[d][j]
    float* Vs = smf + VS_OFF;   // [64][68]  natural:    Vs[j][d]
    float* Ps = smf + PS_OFF;   // [128][68] natural:    Ps[i][j]

    size_t mat = blockIdx.y + (size_t)blockIdx.z * BH_;
    const float* q = Q + ((size_t)blockIdx.y << 17);
    const float* k = K + (mat << 17);
    const float* v = V + (mat << 17);
    float*       o = O + (mat << 17);

    int tid = threadIdx.x;
    int ty = tid >> 4, tx = tid & 15;
    int r0 = ty << 3;          // 8 q-rows owned (local)
    int c0 = tx << 2;          // 4 keys owned in S (local) / 4 O-dims owned
    int q0 = blockIdx.x * 128;

    // Load Q tile transposed: 128 rows x 64 dims
    #pragma unroll
    for (int idx = tid; idx < 128*16; idx += 256) {
        int i = idx >> 4, dc = (idx & 15) << 2;
        float4 t = *(const float4*)&q[((size_t)(q0 + i) << 6) + dc];
        Qs[(dc+0)*132 + i] = t.x;
        Qs[(dc+1)*132 + i] = t.y;
        Qs[(dc+2)*132 + i] = t.z;
        Qs[(dc+3)*132 + i] = t.w;
    }

    float m[8], l[8], acc[8][4];
    #pragma unroll
    for (int i = 0; i < 8; i++) {
        m[i] = -INFINITY; l[i] = 0.f;
        acc[i][0] = acc[i][1] = acc[i][2] = acc[i][3] = 0.f;
    }

    for (int k0 = 0; k0 <= q0 + 64; k0 += 64) {
        __syncthreads();   // protect Ks/Vs/Ps from previous iteration readers
        // Load K tile transposed + V tile natural (64 keys x 64 dims each)
        #pragma unroll
        for (int idx = tid; idx < 64*16; idx += 256) {
            int j = idx >> 4, dc = (idx & 15) << 2;
            float4 kk = *(const float4*)&k[((size_t)(k0 + j) << 6) + dc];
            Ks[(dc+0)*68 + j] = kk.x;
            Ks[(dc+1)*68 + j] = kk.y;
            Ks[(dc+2)*68 + j] = kk.z;
            Ks[(dc+3)*68 + j] = kk.w;
            float4 vv = *(const float4*)&v[((size_t)(k0 + j) << 6) + dc];
            *(float4*)&Vs[j*68 + dc] = vv;
        }
        __syncthreads();

        // S micro-GEMM: s[8][4] = Q_tile(8 rows) . K_tile(4 keys)
        float s[8][4];
        #pragma unroll
        for (int i = 0; i < 8; i++)
            s[i][0] = s[i][1] = s[i][2] = s[i][3] = 0.f;
        #pragma unroll 8
        for (int d = 0; d < 64; d++) {
            float4 a0 = *(float4*)&Qs[d*132 + r0];
            float4 a1 = *(float4*)&Qs[d*132 + r0 + 4];
            float4 b  = *(float4*)&Ks[d*68 + c0];
            float av[8] = {a0.x,a0.y,a0.z,a0.w,a1.x,a1.y,a1.z,a1.w};
            #pragma unroll
            for (int i = 0; i < 8; i++) {
                s[i][0] += av[i]*b.x; s[i][1] += av[i]*b.y;
                s[i][2] += av[i]*b.z; s[i][3] += av[i]*b.w;
            }
        }

        bool needm = (k0 + 63 > q0);
        // Online softmax per row (group of 16 lanes shares a row set)
        #pragma unroll
        for (int i = 0; i < 8; i++) {
            float mt = m[i];
            if (needm) {
                int rowg = q0 + r0 + i;
                #pragma unroll
                for (int j = 0; j < 4; j++) {
                    s[i][j] = (k0 + c0 + j <= rowg) ? s[i][j]*0.125f : -INFINITY;
                    mt = fmaxf(mt, s[i][j]);
                }
            } else {
                #pragma unroll
                for (int j = 0; j < 4; j++) {
                    s[i][j] *= 0.125f;
                    mt = fmaxf(mt, s[i][j]);
                }
            }
            mt = fmaxf(mt, __shfl_xor_sync(~0u, mt, 1));
            mt = fmaxf(mt, __shfl_xor_sync(~0u, mt, 2));
            mt = fmaxf(mt, __shfl_xor_sync(~0u, mt, 4));
            mt = fmaxf(mt, __shfl_xor_sync(~0u, mt, 8));
            float corr = __expf(m[i] - mt);
            m[i] = mt;
            float ps = 0.f;
            #pragma unroll
            for (int j = 0; j < 4; j++) {
                float p = __expf(s[i][j] - mt);
                s[i][j] = p;
                ps += p;
            }
            l[i] = l[i]*corr + ps;
            acc[i][0] *= corr; acc[i][1] *= corr;
            acc[i][2] *= corr; acc[i][3] *= corr;
        }
        // Write P (natural layout [i][j]) — 8 STS.128, conflict-floor
        #pragma unroll
        for (int i = 0; i < 8; i++)
            *(float4*)&Ps[(r0+i)*68 + c0] = make_float4(s[i][0], s[i][1], s[i][2], s[i][3]);
        __syncthreads();

        // O micro-GEMM: acc[8][4] += P(8 rows x 64 keys) . V(64 keys x 4 dims)
        #pragma unroll 4
        for (int j0 = 0; j0 < 64; j0 += 4) {
            float4 v0 = *(float4*)&Vs[(j0+0)*68 + c0];
            float4 v1 = *(float4*)&Vs[(j0+1)*68 + c0];
            float4 v2 = *(float4*)&Vs[(j0+2)*68 + c0];
            float4 v3 = *(float4*)&Vs[(j0+3)*68 + c0];
            #pragma unroll
            for (int i = 0; i < 8; i++) {
                float4 pp = *(float4*)&Ps[(r0+i)*68 + j0];
                acc[i][0] += pp.x*v0.x + pp.y*v1.x + pp.z*v2.x + pp.w*v3.x;
                acc[i][1] += pp.x*v0.y + pp.y*v1.y + pp.z*v2.y + pp.w*v3.y;
                acc[i][2] += pp.x*v0.z + pp.y*v1.z + pp.z*v2.z + pp.w*v3.z;
                acc[i][3] += pp.x*v0.w + pp.y*v1.w + pp.z*v2.w + pp.w*v3.w;
            }
        }
    }

    // Finalize: reduce l across the 16-lane row group, scale, store
    #pragma unroll
    for (int i = 0; i < 8; i++) {
        float ls = l[i];
        ls += __shfl_xor_sync(~0u, ls, 1);
        ls += __shfl_xor_sync(~0u, ls, 2);
        ls += __shfl_xor_sync(~0u, ls, 4);
        ls += __shfl_xor_sync(~0u, ls, 8);
        float inv = 1.f / ls;
        float4 r = make_float4(acc[i][0]*inv, acc[i][1]*inv, acc[i][2]*inv, acc[i][3]*inv);
        *(float4*)&o[((size_t)(q0 + r0 + i) << 6) + c0] = r;
    }
}

// ---------------------------------------------------------------------------
// Launch
// ---------------------------------------------------------------------------
extern "C" void kernel_launch(void* const* d_in, const int* in_sizes, int n_in,
                              void* d_out, int out_size) {
    const float* tokens        = (const float*)d_in[0];
    const float* w_norm        = (const float*)d_in[1];
    const float* w_q           = (const float*)d_in[2];
    const float* w_k           = (const float*)d_in[3];
    const float* w_v           = (const float*)d_in[4];
    const float* w_key_norms   = (const float*)d_in[5];
    const float* w_nested_knorm= (const float*)d_in[6];
    const float* w_out         = (const float*)d_in[7];
    float* out = (float*)d_out;

    float *px, *pq, *pk, *pv, *pn, *po;
    cudaGetSymbolAddress((void**)&px, g_x);
    cudaGetSymbolAddress((void**)&pq, g_q);
    cudaGetSymbolAddress((void**)&pk, g_k);
    cudaGetSymbolAddress((void**)&pv, g_v);
    cudaGetSymbolAddress((void**)&pn, g_n);
    cudaGetSymbolAddress((void**)&po, g_o);

    static int smem_set = 0;
    if (!smem_set) {
        cudaFuncSetAttribute(attn3_kernel, cudaFuncAttributeMaxDynamicSharedMemorySize,
                             ATTN_SMEM_BYTES);
        smem_set = 1;
    }

    // 1) x = rmsnorm(tokens)
    rmsnorm_dim_kernel<<<ROWS_, 256>>>(tokens, w_norm, px);
    // 2) rope tables
    rope_table_kernel<<<(N_*32 + 255)/256, 256>>>();
    // 3) q/k/v projections with layout-transposing epilogues
    sgemm2_kernel<0,1><<<dim3(DIM_/128, ROWS_/128), 256>>>(px, w_q, pq, ROWS_, DIM_, DIM_);
    sgemm2_kernel<0,2><<<dim3(3*DIM_/128, ROWS_/128), 256>>>(px, w_k, pk, ROWS_, DIM_, 3*DIM_);
    sgemm2_kernel<0,2><<<dim3(3*DIM_/128, ROWS_/128), 256>>>(px, w_v, pv, ROWS_, DIM_, 3*DIM_);
    // 4) key rmsnorm (per-slab weight), then rope q and all k slabs
    {
        int rows = 3*BH_*N_;
        rmsnorm_dh_kernel<<<(rows*32 + 255)/256, 256>>>(pk, w_key_norms, 1, rows);
        rope_kernel<<<(BH_*N_*32 + 255)/256, 256>>>(pq, BH_*N_);
        rope_kernel<<<(rows*32 + 255)/256, 256>>>(pk, rows);
    }
    // 5) three inner causal attentions -> nq|nk|nv
    attn3_kernel<<<dim3(N_/128, BH_, 3), 256, ATTN_SMEM_BYTES>>>(pq, pk, pv, pn);
    // 6) nk rmsnorm, rope nq & nk
    {
        float* pnq = pn;
        float* pnk = pn + (size_t)BH_*N_*DH_;
        int rows = BH_*N_;
        rmsnorm_dh_kernel<<<(rows*32 + 255)/256, 256>>>(pnk, w_nested_knorm, 0, rows);
        rope_kernel<<<(rows*32 + 255)/256, 256>>>(pnq, rows);
        rope_kernel<<<(rows*32 + 255)/256, 256>>>(pnk, rows);
    }
    // 7) outer causal attention: attend(nq, nk, nv) -> g_o
    {
        float* pnq = pn;
        float* pnk = pn + (size_t)BH_*N_*DH_;
        float* pnv = pn + (size_t)2*BH_*N_*DH_;
        attn3_kernel<<<dim3(N_/128, BH_, 1), 256, ATTN_SMEM_BYTES>>>(pnq, pnk, pnv, po);
    }
    // 8) output projection with gathered A (transpose fold)
    sgemm2_kernel<1,0><<<dim3(DIM_/128, ROWS_/128), 256>>>(po, w_out, out, ROWS_, DIM_, DIM_);
}

// round 7
// speedup vs baseline: 2.1291x; 1.2952x over previous
#include <cuda_runtime.h>
#include <cuda_bf16.h>
#include <math.h>
#include <stdint.h>

// Problem constants
#define B_  2
#define N_  2048
#define DIM_ 1024
#define H_  16
#define DH_ 64
#define BH_ (B_*H_)            // 32
#define ROWS_ (B_*N_)          // 4096
#define EPS_ 1.1920929e-07f

// ---------------------------------------------------------------------------
// Scratch (allocation-free: __device__ globals)
// ---------------------------------------------------------------------------
__device__ float g_q[(size_t)BH_*N_*DH_];          // (b,h,n,d)
__device__ float g_k[(size_t)3*BH_*N_*DH_];        // (e,b,h,n,d)
__device__ float g_v[(size_t)3*BH_*N_*DH_];
__device__ float g_n[(size_t)3*BH_*N_*DH_];        // nq|nk|nv slabs
__device__ float g_o[(size_t)BH_*N_*DH_];          // outer attend output
__device__ float g_cos[N_*32];
__device__ float g_sin[N_*32];
// bf16 hi/lo splits
__device__ __nv_bfloat16 g_xh[(size_t)ROWS_*DIM_];
__device__ __nv_bfloat16 g_xl[(size_t)ROWS_*DIM_];
__device__ __nv_bfloat16 g_wh[8388608];            // wq|wk|wv|wout
__device__ __nv_bfloat16 g_wl[8388608];
__device__ __nv_bfloat16 g_oh[(size_t)ROWS_*DIM_]; // gathered (bn, hd)
__device__ __nv_bfloat16 g_ol[(size_t)ROWS_*DIM_];

#define WQ_OFF 0
#define WK_OFF 1048576
#define WV_OFF 4194304
#define WO_OFF 7340032

// ---------------------------------------------------------------------------
// PTX helpers (ldmatrix / mma.sync, plain sm_103-compatible)
// ---------------------------------------------------------------------------
__device__ __forceinline__ uint32_t smem_u32(const void* p) {
    uint32_t a;
    asm("{ .reg .u64 t; cvta.to.shared.u64 t, %1; cvt.u32.u64 %0, t; }" : "=r"(a) : "l"(p));
    return a;
}
__device__ __forceinline__ void ldsm4(uint32_t* r, uint32_t addr) {
    asm volatile("ldmatrix.sync.aligned.m8n8.x4.shared.b16 {%0,%1,%2,%3}, [%4];"
                 : "=r"(r[0]), "=r"(r[1]), "=r"(r[2]), "=r"(r[3]) : "r"(addr));
}
__device__ __forceinline__ void ldsm2t(uint32_t* r, uint32_t addr) {
    asm volatile("ldmatrix.sync.aligned.m8n8.x2.trans.shared.b16 {%0,%1}, [%2];"
                 : "=r"(r[0]), "=r"(r[1]) : "r"(addr));
}
__device__ __forceinline__ void mma16816(float* c, const uint32_t* a, const uint32_t* b) {
    asm volatile("mma.sync.aligned.m16n8k16.row.col.f32.bf16.bf16.f32 "
                 "{%0,%1,%2,%3}, {%4,%5,%6,%7}, {%8,%9}, {%0,%1,%2,%3};"
                 : "+f"(c[0]), "+f"(c[1]), "+f"(c[2]), "+f"(c[3])
                 : "r"(a[0]), "r"(a[1]), "r"(a[2]), "r"(a[3]), "r"(b[0]), "r"(b[1]));
}
__device__ __forceinline__ void split1(float f, __nv_bfloat16& h, __nv_bfloat16& l) {
    h = __float2bfloat16(f);
    l = __float2bfloat16(f - __bfloat162float(h));
}

// ---------------------------------------------------------------------------
// RMSNorm over DIM=1024 -> bf16 hi/lo splits (one block per row)
// ---------------------------------------------------------------------------
__global__ void rmsnorm_split_kernel(const float* __restrict__ in,
                                     const float* __restrict__ w,
                                     __nv_bfloat16* __restrict__ xh,
                                     __nv_bfloat16* __restrict__ xl) {
    int row = blockIdx.x;
    int i4 = threadIdx.x << 2;
    float4 v = *(const float4*)&in[(size_t)row*DIM_ + i4];
    float s = v.x*v.x + v.y*v.y + v.z*v.z + v.w*v.w;
    __shared__ float sm[8];
    for (int o = 16; o > 0; o >>= 1) s += __shfl_xor_sync(~0u, s, o);
    if ((threadIdx.x & 31) == 0) sm[threadIdx.x >> 5] = s;
    __syncthreads();
    if (threadIdx.x < 8) {
        s = sm[threadIdx.x];
        for (int o = 4; o > 0; o >>= 1) s += __shfl_xor_sync(0xffu, s, o);
        if (threadIdx.x == 0) sm[0] = s;
    }
    __syncthreads();
    float inv = rsqrtf(sm[0] * (1.f/DIM_) + EPS_);
    float4 wv = *(const float4*)&w[i4];
    float f[4] = {v.x*inv*wv.x, v.y*inv*wv.y, v.z*inv*wv.z, v.w*inv*wv.w};
    __nv_bfloat16 h[4], l[4];
    #pragma unroll
    for (int j = 0; j < 4; j++) split1(f[j], h[j], l[j]);
    *(uint2*)&xh[(size_t)row*DIM_ + i4] = *(uint2*)h;
    *(uint2*)&xl[(size_t)row*DIM_ + i4] = *(uint2*)l;
}

// ---------------------------------------------------------------------------
// Elementwise fp32 -> bf16 hi/lo split (weights)
// ---------------------------------------------------------------------------
__global__ void split_kernel(const float* __restrict__ in,
                             __nv_bfloat16* __restrict__ hi,
                             __nv_bfloat16* __restrict__ lo, int n4) {
    int i = blockIdx.x*256 + threadIdx.x;
    if (i >= n4) return;
    float4 v = ((const float4*)in)[i];
    float f[4] = {v.x, v.y, v.z, v.w};
    __nv_bfloat16 h[4], l[4];
    #pragma unroll
    for (int j = 0; j < 4; j++) split1(f[j], h[j], l[j]);
    *(uint2*)&hi[(size_t)i*4] = *(uint2*)h;
    *(uint2*)&lo[(size_t)i*4] = *(uint2*)l;
}

// ---------------------------------------------------------------------------
// Gather g_o (b,h,n,d) -> row-major (b*n, h*d) + bf16 split
// ---------------------------------------------------------------------------
__global__ void oconv_kernel(const float* __restrict__ o,
                             __nv_bfloat16* __restrict__ hi,
                             __nv_bfloat16* __restrict__ lo) {
    int i = blockIdx.x*256 + threadIdx.x;     // i < ROWS_*DIM_/4
    int linear = i << 2;
    int d = linear & 63, n = (linear >> 6) & 2047;
    int h = (linear >> 17) & 15, b = linear >> 21;
    float4 v = *(const float4*)&o[linear];
    float f[4] = {v.x, v.y, v.z, v.w};
    __nv_bfloat16 hh[4], ll[4];
    #pragma unroll
    for (int j = 0; j < 4; j++) split1(f[j], hh[j], ll[j]);
    size_t oc = ((size_t)b*N_ + n)*DIM_ + h*64 + d;
    *(uint2*)&hi[oc] = *(uint2*)hh;
    *(uint2*)&lo[oc] = *(uint2*)ll;
}

// ---------------------------------------------------------------------------
// RMSNorm over DH=64 (one warp per row), optional per-slab weight
// ---------------------------------------------------------------------------
__global__ void rmsnorm_dh_kernel(float* __restrict__ x, const float* __restrict__ w,
                                  int use_e, int total_rows) {
    int warp = (blockIdx.x * blockDim.x + threadIdx.x) >> 5;
    if (warp >= total_rows) return;
    int lane = threadIdx.x & 31;
    float* p = x + (size_t)warp * DH_;
    float a = p[lane], b = p[lane + 32];
    float s = a*a + b*b;
    for (int o = 16; o > 0; o >>= 1) s += __shfl_xor_sync(~0u, s, o);
    float inv = rsqrtf(s * (1.f/DH_) + EPS_);
    const float* ww = w + (use_e ? (warp / (BH_*N_)) * DH_ : 0);
    p[lane]      = a * inv * ww[lane];
    p[lane + 32] = b * inv * ww[lane + 32];
}

// ---------------------------------------------------------------------------
// RoPE table + in-place RoPE apply
// ---------------------------------------------------------------------------
__global__ void rope_table_kernel() {
    int idx = blockIdx.x * blockDim.x + threadIdx.x;
    if (idx >= N_*32) return;
    int n = idx >> 5, t = idx & 31;
    float inv_freq = powf(10000.f, -(2.f * (float)t) / 64.f);
    float ang = (float)n * inv_freq;
    g_cos[idx] = cosf(ang);
    g_sin[idx] = sinf(ang);
}

__global__ void rope_kernel(float* __restrict__ x, int total_rows) {
    int idx = blockIdx.x * blockDim.x + threadIdx.x;
    if (idx >= total_rows * 32) return;
    int row = idx >> 5, t = idx & 31;
    int n = row & (N_-1);
    float c = g_cos[(n<<5) + t], s = g_sin[(n<<5) + t];
    float* p = x + ((size_t)row << 6) + (t << 1);
    float2 v = *(float2*)p;
    float2 r; r.x = v.x*c - v.y*s; r.y = v.y*c + v.x*s;
    *(float2*)p = r;
}

// ---------------------------------------------------------------------------
// HMMA GEMM: C[M,Nc] = A[M,K] * W[K,Nc] in fp32 via bf16 2-way split
// (hi*hi + hi*lo + lo*hi). A,W pre-split bf16 row-major.
// CTA 128x128, 8 warps (2x4), warp tile 64x32, mma.m16n8k16.
// SMEM: A hi/lo [128][72] bf16, B hi/lo [64][136] bf16 (natural [k][n]).
// CMODE: 0 = row-major, 1 = q layout (b,h,n,d), 2 = kv layout (e,b,h,n,d)
// ---------------------------------------------------------------------------
#define HG_SMEM ((128*72*2 + 64*136*2)*2)   // 71680 bytes

template<int CMODE>
__global__ __launch_bounds__(256) void hgemm_kernel(
    const __nv_bfloat16* __restrict__ Ah, const __nv_bfloat16* __restrict__ Al,
    const __nv_bfloat16* __restrict__ Wh, const __nv_bfloat16* __restrict__ Wl,
    float* __restrict__ C, int K, int Nc) {
    extern __shared__ __nv_bfloat16 smb[];
    __nv_bfloat16* sAh = smb;                        // [128][72]
    __nv_bfloat16* sAl = smb + 128*72;
    __nv_bfloat16* sBh = smb + 2*128*72;             // [64][136]
    __nv_bfloat16* sBl = smb + 2*128*72 + 64*136;

    int tid = threadIdx.x, lane = tid & 31, wid = tid >> 5;
    int wr = wid & 1, wc = wid >> 1;
    int brow = blockIdx.y*128, bcol = blockIdx.x*128;

    uint32_t sAh_u = smem_u32(sAh), sAl_u = smem_u32(sAl);
    uint32_t sBh_u = smem_u32(sBh), sBl_u = smem_u32(sBl);

    float acc[4][4][4];
    #pragma unroll
    for (int mi = 0; mi < 4; mi++)
        #pragma unroll
        for (int ni = 0; ni < 4; ni++)
            #pragma unroll
            for (int j = 0; j < 4; j++) acc[mi][ni][j] = 0.f;

    // lane-dependent ldmatrix coordinates
    int arow = wr*64 + (lane & 15);         // + mi*16
    int acol = (lane >> 4) << 3;            // + k0
    int brl  = lane & 15;                   // + k0 (B k-row)

    int nchunks = K >> 6;
    for (int c = 0; c < nchunks; c++) {
        __syncthreads();
        #pragma unroll
        for (int it = 0; it < 4; it++) {
            int idx = tid + it*256;
            int r = idx >> 3, kc = (idx & 7) << 3;
            size_t ga = (size_t)(brow + r)*K + c*64 + kc;
            *(uint4*)(sAh + r*72 + kc) = *(const uint4*)(Ah + ga);
            *(uint4*)(sAl + r*72 + kc) = *(const uint4*)(Al + ga);
            int kb = idx >> 4, nc2 = (idx & 15) << 3;
            size_t gb = (size_t)(c*64 + kb)*Nc + bcol + nc2;
            *(uint4*)(sBh + kb*136 + nc2) = *(const uint4*)(Wh + gb);
            *(uint4*)(sBl + kb*136 + nc2) = *(const uint4*)(Wl + gb);
        }
        __syncthreads();
        #pragma unroll
        for (int kk = 0; kk < 4; kk++) {
            int k0 = kk << 4;
            uint32_t ah[4][4], al[4][4], bh[4][2], bl[4][2];
            #pragma unroll
            for (int mi = 0; mi < 4; mi++) {
                uint32_t off = (uint32_t)(((arow + mi*16)*72 + k0 + acol) << 1);
                ldsm4(ah[mi], sAh_u + off);
                ldsm4(al[mi], sAl_u + off);
            }
            #pragma unroll
            for (int ni = 0; ni < 4; ni++) {
                uint32_t off = (uint32_t)((((k0 + brl)*136) + wc*32 + ni*8) << 1);
                ldsm2t(bh[ni], sBh_u + off);
                ldsm2t(bl[ni], sBl_u + off);
            }
            #pragma unroll
            for (int mi = 0; mi < 4; mi++)
                #pragma unroll
                for (int ni = 0; ni < 4; ni++) {
                    mma16816(acc[mi][ni], ah[mi], bh[ni]);
                    mma16816(acc[mi][ni], ah[mi], bl[ni]);
                    mma16816(acc[mi][ni], al[mi], bh[ni]);
                }
        }
    }

    // Epilogue: c0,c1 = (row g, col 2t'..+1); c2,c3 = (row g+8, same cols)
    int g = lane >> 2, t2 = (lane & 3) << 1;
    #pragma unroll
    for (int mi = 0; mi < 4; mi++) {
        int row = brow + wr*64 + mi*16 + g;
        #pragma unroll
        for (int ni = 0; ni < 4; ni++) {
            int col = bcol + wc*32 + ni*8 + t2;
            float* p0; float* p1;
            if (CMODE == 0) {
                p0 = &C[(size_t)row * Nc + col];
                p1 = &C[(size_t)(row+8) * Nc + col];
            } else if (CMODE == 1) {
                int b = row >> 11, n = row & 2047;
                int h = col >> 6, d = col & 63;
                p0 = &C[((((size_t)b*H_ + h)*N_ + n) << 6) + d];
                p1 = p0 + (8 << 6);
            } else {
                int b = row >> 11, n = row & 2047;
                int e = col >> 10, h = (col >> 6) & 15, d = col & 63;
                p0 = &C[(((((size_t)e*B_ + b)*H_ + h)*N_ + n) << 6) + d];
                p1 = p0 + (8 << 6);
            }
            *(float2*)p0 = make_float2(acc[mi][ni][0], acc[mi][ni][1]);
            *(float2*)p1 = make_float2(acc[mi][ni][2], acc[mi][ni][3]);
        }
    }
}

// ---------------------------------------------------------------------------
// Causal flash attention v3 (unchanged, passing at 3876): GEMM-structured FFMA
// ---------------------------------------------------------------------------
#define QS_OFF 0
#define KS_OFF 8448
#define VS_OFF 12800
#define PS_OFF 17152
#define ATTN_SMEM_FLOATS 25856
#define ATTN_SMEM_BYTES (ATTN_SMEM_FLOATS*4)

__global__ __launch_bounds__(256, 2) void attn3_kernel(const float* __restrict__ Q,
                                                       const float* __restrict__ K,
                                                       const float* __restrict__ V,
                                                       float* __restrict__ O) {
    extern __shared__ float smf[];
    float* Qs = smf + QS_OFF;
    float* Ks = smf + KS_OFF;
    float* Vs = smf + VS_OFF;
    float* Ps = smf + PS_OFF;

    size_t mat = blockIdx.y + (size_t)blockIdx.z * BH_;
    const float* q = Q + ((size_t)blockIdx.y << 17);
    const float* k = K + (mat << 17);
    const float* v = V + (mat << 17);
    float*       o = O + (mat << 17);

    int tid = threadIdx.x;
    int ty = tid >> 4, tx = tid & 15;
    int r0 = ty << 3;
    int c0 = tx << 2;
    int q0 = blockIdx.x * 128;

    #pragma unroll
    for (int idx = tid; idx < 128*16; idx += 256) {
        int i = idx >> 4, dc = (idx & 15) << 2;
        float4 t = *(const float4*)&q[((size_t)(q0 + i) << 6) + dc];
        Qs[(dc+0)*132 + i] = t.x;
        Qs[(dc+1)*132 + i] = t.y;
        Qs[(dc+2)*132 + i] = t.z;
        Qs[(dc+3)*132 + i] = t.w;
    }

    float m[8], l[8], acc[8][4];
    #pragma unroll
    for (int i = 0; i < 8; i++) {
        m[i] = -INFINITY; l[i] = 0.f;
        acc[i][0] = acc[i][1] = acc[i][2] = acc[i][3] = 0.f;
    }

    for (int k0 = 0; k0 <= q0 + 64; k0 += 64) {
        __syncthreads();
        #pragma unroll
        for (int idx = tid; idx < 64*16; idx += 256) {
            int j = idx >> 4, dc = (idx & 15) << 2;
            float4 kk = *(const float4*)&k[((size_t)(k0 + j) << 6) + dc];
            Ks[(dc+0)*68 + j] = kk.x;
            Ks[(dc+1)*68 + j] = kk.y;
            Ks[(dc+2)*68 + j] = kk.z;
            Ks[(dc+3)*68 + j] = kk.w;
            float4 vv = *(const float4*)&v[((size_t)(k0 + j) << 6) + dc];
            *(float4*)&Vs[j*68 + dc] = vv;
        }
        __syncthreads();

        float s[8][4];
        #pragma unroll
        for (int i = 0; i < 8; i++)
            s[i][0] = s[i][1] = s[i][2] = s[i][3] = 0.f;
        #pragma unroll 8
        for (int d = 0; d < 64; d++) {
            float4 a0 = *(float4*)&Qs[d*132 + r0];
            float4 a1 = *(float4*)&Qs[d*132 + r0 + 4];
            float4 b  = *(float4*)&Ks[d*68 + c0];
            float av[8] = {a0.x,a0.y,a0.z,a0.w,a1.x,a1.y,a1.z,a1.w};
            #pragma unroll
            for (int i = 0; i < 8; i++) {
                s[i][0] += av[i]*b.x; s[i][1] += av[i]*b.y;
                s[i][2] += av[i]*b.z; s[i][3] += av[i]*b.w;
            }
        }

        bool needm = (k0 + 63 > q0);
        #pragma unroll
        for (int i = 0; i < 8; i++) {
            float mt = m[i];
            if (needm) {
                int rowg = q0 + r0 + i;
                #pragma unroll
                for (int j = 0; j < 4; j++) {
                    s[i][j] = (k0 + c0 + j <= rowg) ? s[i][j]*0.125f : -INFINITY;
                    mt = fmaxf(mt, s[i][j]);
                }
            } else {
                #pragma unroll
                for (int j = 0; j < 4; j++) {
                    s[i][j] *= 0.125f;
                    mt = fmaxf(mt, s[i][j]);
                }
            }
            mt = fmaxf(mt, __shfl_xor_sync(~0u, mt, 1));
            mt = fmaxf(mt, __shfl_xor_sync(~0u, mt, 2));
            mt = fmaxf(mt, __shfl_xor_sync(~0u, mt, 4));
            mt = fmaxf(mt, __shfl_xor_sync(~0u, mt, 8));
            float corr = __expf(m[i] - mt);
            m[i] = mt;
            float ps = 0.f;
            #pragma unroll
            for (int j = 0; j < 4; j++) {
                float p = __expf(s[i][j] - mt);
                s[i][j] = p;
                ps += p;
            }
            l[i] = l[i]*corr + ps;
            acc[i][0] *= corr; acc[i][1] *= corr;
            acc[i][2] *= corr; acc[i][3] *= corr;
        }
        #pragma unroll
        for (int i = 0; i < 8; i++)
            *(float4*)&Ps[(r0+i)*68 + c0] = make_float4(s[i][0], s[i][1], s[i][2], s[i][3]);
        __syncthreads();

        #pragma unroll 4
        for (int j0 = 0; j0 < 64; j0 += 4) {
            float4 v0 = *(float4*)&Vs[(j0+0)*68 + c0];
            float4 v1 = *(float4*)&Vs[(j0+1)*68 + c0];
            float4 v2 = *(float4*)&Vs[(j0+2)*68 + c0];
            float4 v3 = *(float4*)&Vs[(j0+3)*68 + c0];
            #pragma unroll
            for (int i = 0; i < 8; i++) {
                float4 pp = *(float4*)&Ps[(r0+i)*68 + j0];
                acc[i][0] += pp.x*v0.x + pp.y*v1.x + pp.z*v2.x + pp.w*v3.x;
                acc[i][1] += pp.x*v0.y + pp.y*v1.y + pp.z*v2.y + pp.w*v3.y;
                acc[i][2] += pp.x*v0.z + pp.y*v1.z + pp.z*v2.z + pp.w*v3.z;
                acc[i][3] += pp.x*v0.w + pp.y*v1.w + pp.z*v2.w + pp.w*v3.w;
            }
        }
    }

    #pragma unroll
    for (int i = 0; i < 8; i++) {
        float ls = l[i];
        ls += __shfl_xor_sync(~0u, ls, 1);
        ls += __shfl_xor_sync(~0u, ls, 2);
        ls += __shfl_xor_sync(~0u, ls, 4);
        ls += __shfl_xor_sync(~0u, ls, 8);
        float inv = 1.f / ls;
        float4 r = make_float4(acc[i][0]*inv, acc[i][1]*inv, acc[i][2]*inv, acc[i][3]*inv);
        *(float4*)&o[((size_t)(q0 + r0 + i) << 6) + c0] = r;
    }
}

// ---------------------------------------------------------------------------
// Launch
// ---------------------------------------------------------------------------
extern "C" void kernel_launch(void* const* d_in, const int* in_sizes, int n_in,
                              void* d_out, int out_size) {
    const float* tokens        = (const float*)d_in[0];
    const float* w_norm        = (const float*)d_in[1];
    const float* w_q           = (const float*)d_in[2];
    const float* w_k           = (const float*)d_in[3];
    const float* w_v           = (const float*)d_in[4];
    const float* w_key_norms   = (const float*)d_in[5];
    const float* w_nested_knorm= (const float*)d_in[6];
    const float* w_out         = (const float*)d_in[7];
    float* out = (float*)d_out;

    float *pq, *pk, *pv, *pn, *po;
    __nv_bfloat16 *pxh, *pxl, *pwh, *pwl, *poh, *pol;
    cudaGetSymbolAddress((void**)&pq, g_q);
    cudaGetSymbolAddress((void**)&pk, g_k);
    cudaGetSymbolAddress((void**)&pv, g_v);
    cudaGetSymbolAddress((void**)&pn, g_n);
    cudaGetSymbolAddress((void**)&po, g_o);
    cudaGetSymbolAddress((void**)&pxh, g_xh);
    cudaGetSymbolAddress((void**)&pxl, g_xl);
    cudaGetSymbolAddress((void**)&pwh, g_wh);
    cudaGetSymbolAddress((void**)&pwl, g_wl);
    cudaGetSymbolAddress((void**)&poh, g_oh);
    cudaGetSymbolAddress((void**)&pol, g_ol);

    static int attr_set = 0;
    if (!attr_set) {
        cudaFuncSetAttribute(attn3_kernel, cudaFuncAttributeMaxDynamicSharedMemorySize,
                             ATTN_SMEM_BYTES);
        cudaFuncSetAttribute(hgemm_kernel<0>, cudaFuncAttributeMaxDynamicSharedMemorySize, HG_SMEM);
        cudaFuncSetAttribute(hgemm_kernel<1>, cudaFuncAttributeMaxDynamicSharedMemorySize, HG_SMEM);
        cudaFuncSetAttribute(hgemm_kernel<2>, cudaFuncAttributeMaxDynamicSharedMemorySize, HG_SMEM);
        attr_set = 1;
    }

    // 1) x = rmsnorm(tokens), split to bf16 hi/lo
    rmsnorm_split_kernel<<<ROWS_, 256>>>(tokens, w_norm, pxh, pxl);
    // 2) rope tables + weight splits
    rope_table_kernel<<<(N_*32 + 255)/256, 256>>>();
    split_kernel<<<1024, 256>>>(w_q,   pwh + WQ_OFF, pwl + WQ_OFF, 262144);
    split_kernel<<<3072, 256>>>(w_k,   pwh + WK_OFF, pwl + WK_OFF, 786432);
    split_kernel<<<3072, 256>>>(w_v,   pwh + WV_OFF, pwl + WV_OFF, 786432);
    split_kernel<<<1024, 256>>>(w_out, pwh + WO_OFF, pwl + WO_OFF, 262144);
    // 3) q/k/v projections (HMMA, bf16 3-term split) with layout epilogues
    hgemm_kernel<1><<<dim3(8, 32),  256, HG_SMEM>>>(pxh, pxl, pwh + WQ_OFF, pwl + WQ_OFF, pq, DIM_, DIM_);
    hgemm_kernel<2><<<dim3(24, 32), 256, HG_SMEM>>>(pxh, pxl, pwh + WK_OFF, pwl + WK_OFF, pk, DIM_, 3*DIM_);
    hgemm_kernel<2><<<dim3(24, 32), 256, HG_SMEM>>>(pxh, pxl, pwh + WV_OFF, pwl + WV_OFF, pv, DIM_, 3*DIM_);
    // 4) key rmsnorm (per-slab weight), then rope q and all k slabs
    {
        int rows = 3*BH_*N_;
        rmsnorm_dh_kernel<<<(rows*32 + 255)/256, 256>>>(pk, w_key_norms, 1, rows);
        rope_kernel<<<(BH_*N_*32 + 255)/256, 256>>>(pq, BH_*N_);
        rope_kernel<<<(rows*32 + 255)/256, 256>>>(pk, rows);
    }
    // 5) three inner causal attentions -> nq|nk|nv
    attn3_kernel<<<dim3(N_/128, BH_, 3), 256, ATTN_SMEM_BYTES>>>(pq, pk, pv, pn);
    // 6) nk rmsnorm, rope nq & nk
    {
        float* pnq = pn;
        float* pnk = pn + (size_t)BH_*N_*DH_;
        int rows = BH_*N_;
        rmsnorm_dh_kernel<<<(rows*32 + 255)/256, 256>>>(pnk, w_nested_knorm, 0, rows);
        rope_kernel<<<(rows*32 + 255)/256, 256>>>(pnq, rows);
        rope_kernel<<<(rows*32 + 255)/256, 256>>>(pnk, rows);
    }
    // 7) outer causal attention: attend(nq, nk, nv) -> g_o
    {
        float* pnq = pn;
        float* pnk = pn + (size_t)BH_*N_*DH_;
        float* pnv = pn + (size_t)2*BH_*N_*DH_;
        attn3_kernel<<<dim3(N_/128, BH_, 1), 256, ATTN_SMEM_BYTES>>>(pnq, pnk, pnv, po);
    }
    // 8) gather+split attention output, then output projection (HMMA)
    oconv_kernel<<<4096, 256>>>(po, poh, pol);
    hgemm_kernel<0><<<dim3(8, 32), 256, HG_SMEM>>>(poh, pol, pwh + WO_OFF, pwl + WO_OFF, out, DIM_, DIM_);
}

// round 8
// speedup vs baseline: 4.1359x; 1.9426x over previous
#include <cuda_runtime.h>
#include <cuda_bf16.h>
#include <math.h>
#include <stdint.h>

// Problem constants
#define B_  2
#define N_  2048
#define DIM_ 1024
#define H_  16
#define DH_ 64
#define BH_ (B_*H_)            // 32
#define ROWS_ (B_*N_)          // 4096
#define EPS_ 1.1920929e-07f

// ---------------------------------------------------------------------------
// Scratch (allocation-free: __device__ globals)
// ---------------------------------------------------------------------------
__device__ float g_q[(size_t)BH_*N_*DH_];          // (b,h,n,d) fp32
__device__ float g_k[(size_t)3*BH_*N_*DH_];        // (e,b,h,n,d) fp32
__device__ float g_v[(size_t)3*BH_*N_*DH_];
__device__ float g_n[(size_t)3*BH_*N_*DH_];        // nq|nk|nv fp32
__device__ float g_o[(size_t)BH_*N_*DH_];          // outer attend output
__device__ float g_cos[N_*32];
__device__ float g_sin[N_*32];
// bf16 hi/lo splits
__device__ __nv_bfloat16 g_xh[(size_t)ROWS_*DIM_];
__device__ __nv_bfloat16 g_xl[(size_t)ROWS_*DIM_];
__device__ __nv_bfloat16 g_wh[8388608];            // wq|wk|wv|wout
__device__ __nv_bfloat16 g_wl[8388608];
__device__ __nv_bfloat16 g_oh[(size_t)ROWS_*DIM_]; // gathered (bn, hd)
__device__ __nv_bfloat16 g_ol[(size_t)ROWS_*DIM_];
// attention operand splits
__device__ __nv_bfloat16 g_qh[4194304],  g_ql[4194304];
__device__ __nv_bfloat16 g_kh[12582912], g_kl[12582912];
__device__ __nv_bfloat16 g_vh[12582912], g_vl[12582912];
__device__ __nv_bfloat16 g_nh[12582912], g_nl[12582912];  // nq|nk|nv splits

#define WQ_OFF 0
#define WK_OFF 1048576
#define WV_OFF 4194304
#define WO_OFF 7340032
#define SLAB_ 4194304

// ---------------------------------------------------------------------------
// PTX helpers (ldmatrix / mma.sync, plain sm_103-compatible)
// ---------------------------------------------------------------------------
__device__ __forceinline__ uint32_t smem_u32(const void* p) {
    uint32_t a;
    asm("{ .reg .u64 t; cvta.to.shared.u64 t, %1; cvt.u32.u64 %0, t; }" : "=r"(a) : "l"(p));
    return a;
}
__device__ __forceinline__ void ldsm4(uint32_t* r, uint32_t addr) {
    asm volatile("ldmatrix.sync.aligned.m8n8.x4.shared.b16 {%0,%1,%2,%3}, [%4];"
                 : "=r"(r[0]), "=r"(r[1]), "=r"(r[2]), "=r"(r[3]) : "r"(addr));
}
__device__ __forceinline__ void ldsm2t(uint32_t* r, uint32_t addr) {
    asm volatile("ldmatrix.sync.aligned.m8n8.x2.trans.shared.b16 {%0,%1}, [%2];"
                 : "=r"(r[0]), "=r"(r[1]) : "r"(addr));
}
__device__ __forceinline__ void mma16816(float* c, const uint32_t* a, const uint32_t* b) {
    asm volatile("mma.sync.aligned.m16n8k16.row.col.f32.bf16.bf16.f32 "
                 "{%0,%1,%2,%3}, {%4,%5,%6,%7}, {%8,%9}, {%0,%1,%2,%3};"
                 : "+f"(c[0]), "+f"(c[1]), "+f"(c[2]), "+f"(c[3])
                 : "r"(a[0]), "r"(a[1]), "r"(a[2]), "r"(a[3]), "r"(b[0]), "r"(b[1]));
}
__device__ __forceinline__ void split1(float f, __nv_bfloat16& h, __nv_bfloat16& l) {
    h = __float2bfloat16(f);
    l = __float2bfloat16(f - __bfloat162float(h));
}
__device__ __forceinline__ uint32_t packbf(float a, float b) {
    __nv_bfloat162 t = __floats2bfloat162_rn(a, b);
    return *reinterpret_cast<uint32_t*>(&t);
}

// ---------------------------------------------------------------------------
// RMSNorm over DIM=1024 -> bf16 hi/lo splits (one block per row)
// ---------------------------------------------------------------------------
__global__ void rmsnorm_split_kernel(const float* __restrict__ in,
                                     const float* __restrict__ w,
                                     __nv_bfloat16* __restrict__ xh,
                                     __nv_bfloat16* __restrict__ xl) {
    int row = blockIdx.x;
    int i4 = threadIdx.x << 2;
    float4 v = *(const float4*)&in[(size_t)row*DIM_ + i4];
    float s = v.x*v.x + v.y*v.y + v.z*v.z + v.w*v.w;
    __shared__ float sm[8];
    for (int o = 16; o > 0; o >>= 1) s += __shfl_xor_sync(~0u, s, o);
    if ((threadIdx.x & 31) == 0) sm[threadIdx.x >> 5] = s;
    __syncthreads();
    if (threadIdx.x < 8) {
        s = sm[threadIdx.x];
        for (int o = 4; o > 0; o >>= 1) s += __shfl_xor_sync(0xffu, s, o);
        if (threadIdx.x == 0) sm[0] = s;
    }
    __syncthreads();
    float inv = rsqrtf(sm[0] * (1.f/DIM_) + EPS_);
    float4 wv = *(const float4*)&w[i4];
    float f[4] = {v.x*inv*wv.x, v.y*inv*wv.y, v.z*inv*wv.z, v.w*inv*wv.w};
    __nv_bfloat16 h[4], l[4];
    #pragma unroll
    for (int j = 0; j < 4; j++) split1(f[j], h[j], l[j]);
    *(uint2*)&xh[(size_t)row*DIM_ + i4] = *(uint2*)h;
    *(uint2*)&xl[(size_t)row*DIM_ + i4] = *(uint2*)l;
}

// ---------------------------------------------------------------------------
// Elementwise fp32 -> bf16 hi/lo split
// ---------------------------------------------------------------------------
__global__ void split_kernel(const float* __restrict__ in,
                             __nv_bfloat16* __restrict__ hi,
                             __nv_bfloat16* __restrict__ lo, int n4) {
    int i = blockIdx.x*256 + threadIdx.x;
    if (i >= n4) return;
    float4 v = ((const float4*)in)[i];
    float f[4] = {v.x, v.y, v.z, v.w};
    __nv_bfloat16 h[4], l[4];
    #pragma unroll
    for (int j = 0; j < 4; j++) split1(f[j], h[j], l[j]);
    *(uint2*)&hi[(size_t)i*4] = *(uint2*)h;
    *(uint2*)&lo[(size_t)i*4] = *(uint2*)l;
}

// ---------------------------------------------------------------------------
// Gather g_o (b,h,n,d) -> row-major (b*n, h*d) + bf16 split
// ---------------------------------------------------------------------------
__global__ void oconv_kernel(const float* __restrict__ o,
                             __nv_bfloat16* __restrict__ hi,
                             __nv_bfloat16* __restrict__ lo) {
    int i = blockIdx.x*256 + threadIdx.x;
    int linear = i << 2;
    int d = linear & 63, n = (linear >> 6) & 2047;
    int h = (linear >> 17) & 15, b = linear >> 21;
    float4 v = *(const float4*)&o[linear];
    float f[4] = {v.x, v.y, v.z, v.w};
    __nv_bfloat16 hh[4], ll[4];
    #pragma unroll
    for (int j = 0; j < 4; j++) split1(f[j], hh[j], ll[j]);
    size_t oc = ((size_t)b*N_ + n)*DIM_ + h*64 + d;
    *(uint2*)&hi[oc] = *(uint2*)hh;
    *(uint2*)&lo[oc] = *(uint2*)ll;
}

// ---------------------------------------------------------------------------
// RMSNorm over DH=64 (one warp per row), optional per-slab weight
// ---------------------------------------------------------------------------
__global__ void rmsnorm_dh_kernel(float* __restrict__ x, const float* __restrict__ w,
                                  int use_e, int total_rows) {
    int warp = (blockIdx.x * blockDim.x + threadIdx.x) >> 5;
    if (warp >= total_rows) return;
    int lane = threadIdx.x & 31;
    float* p = x + (size_t)warp * DH_;
    float a = p[lane], b = p[lane + 32];
    float s = a*a + b*b;
    for (int o = 16; o > 0; o >>= 1) s += __shfl_xor_sync(~0u, s, o);
    float inv = rsqrtf(s * (1.f/DH_) + EPS_);
    const float* ww = w + (use_e ? (warp / (BH_*N_)) * DH_ : 0);
    p[lane]      = a * inv * ww[lane];
    p[lane + 32] = b * inv * ww[lane + 32];
}

// ---------------------------------------------------------------------------
// RoPE table + in-place RoPE apply
// ---------------------------------------------------------------------------
__global__ void rope_table_kernel() {
    int idx = blockIdx.x * blockDim.x + threadIdx.x;
    if (idx >= N_*32) return;
    int n = idx >> 5, t = idx & 31;
    float inv_freq = powf(10000.f, -(2.f * (float)t) / 64.f);
    float ang = (float)n * inv_freq;
    g_cos[idx] = cosf(ang);
    g_sin[idx] = sinf(ang);
}

__global__ void rope_kernel(float* __restrict__ x, int total_rows) {
    int idx = blockIdx.x * blockDim.x + threadIdx.x;
    if (idx >= total_rows * 32) return;
    int row = idx >> 5, t = idx & 31;
    int n = row & (N_-1);
    float c = g_cos[(n<<5) + t], s = g_sin[(n<<5) + t];
    float* p = x + ((size_t)row << 6) + (t << 1);
    float2 v = *(float2*)p;
    float2 r; r.x = v.x*c - v.y*s; r.y = v.y*c + v.x*s;
    *(float2*)p = r;
}

// ---------------------------------------------------------------------------
// HMMA GEMM (unchanged from R6): bf16 3-term split, CTA 128x128, 8 warps.
// ---------------------------------------------------------------------------
#define HG_SMEM ((128*72*2 + 64*136*2)*2)

template<int CMODE>
__global__ __launch_bounds__(256) void hgemm_kernel(
    const __nv_bfloat16* __restrict__ Ah, const __nv_bfloat16* __restrict__ Al,
    const __nv_bfloat16* __restrict__ Wh, const __nv_bfloat16* __restrict__ Wl,
    float* __restrict__ C, int K, int Nc) {
    extern __shared__ __nv_bfloat16 smb[];
    __nv_bfloat16* sAh = smb;
    __nv_bfloat16* sAl = smb + 128*72;
    __nv_bfloat16* sBh = smb + 2*128*72;
    __nv_bfloat16* sBl = smb + 2*128*72 + 64*136;

    int tid = threadIdx.x, lane = tid & 31, wid = tid >> 5;
    int wr = wid & 1, wc = wid >> 1;
    int brow = blockIdx.y*128, bcol = blockIdx.x*128;

    uint32_t sAh_u = smem_u32(sAh), sAl_u = smem_u32(sAl);
    uint32_t sBh_u = smem_u32(sBh), sBl_u = smem_u32(sBl);

    float acc[4][4][4];
    #pragma unroll
    for (int mi = 0; mi < 4; mi++)
        #pragma unroll
        for (int ni = 0; ni < 4; ni++)
            #pragma unroll
            for (int j = 0; j < 4; j++) acc[mi][ni][j] = 0.f;

    int arow = wr*64 + (lane & 15);
    int acol = (lane >> 4) << 3;
    int brl  = lane & 15;

    int nchunks = K >> 6;
    for (int c = 0; c < nchunks; c++) {
        __syncthreads();
        #pragma unroll
        for (int it = 0; it < 4; it++) {
            int idx = tid + it*256;
            int r = idx >> 3, kc = (idx & 7) << 3;
            size_t ga = (size_t)(brow + r)*K + c*64 + kc;
            *(uint4*)(sAh + r*72 + kc) = *(const uint4*)(Ah + ga);
            *(uint4*)(sAl + r*72 + kc) = *(const uint4*)(Al + ga);
            int kb = idx >> 4, nc2 = (idx & 15) << 3;
            size_t gb = (size_t)(c*64 + kb)*Nc + bcol + nc2;
            *(uint4*)(sBh + kb*136 + nc2) = *(const uint4*)(Wh + gb);
            *(uint4*)(sBl + kb*136 + nc2) = *(const uint4*)(Wl + gb);
        }
        __syncthreads();
        #pragma unroll
        for (int kk = 0; kk < 4; kk++) {
            int k0 = kk << 4;
            uint32_t ah[4][4], al[4][4], bh[4][2], bl[4][2];
            #pragma unroll
            for (int mi = 0; mi < 4; mi++) {
                uint32_t off = (uint32_t)(((arow + mi*16)*72 + k0 + acol) << 1);
                ldsm4(ah[mi], sAh_u + off);
                ldsm4(al[mi], sAl_u + off);
            }
            #pragma unroll
            for (int ni = 0; ni < 4; ni++) {
                uint32_t off = (uint32_t)((((k0 + brl)*136) + wc*32 + ni*8) << 1);
                ldsm2t(bh[ni], sBh_u + off);
                ldsm2t(bl[ni], sBl_u + off);
            }
            #pragma unroll
            for (int mi = 0; mi < 4; mi++)
                #pragma unroll
                for (int ni = 0; ni < 4; ni++) {
                    mma16816(acc[mi][ni], ah[mi], bh[ni]);
                    mma16816(acc[mi][ni], ah[mi], bl[ni]);
                    mma16816(acc[mi][ni], al[mi], bh[ni]);
                }
        }
    }

    int g = lane >> 2, t2 = (lane & 3) << 1;
    #pragma unroll
    for (int mi = 0; mi < 4; mi++) {
        int row = brow + wr*64 + mi*16 + g;
        #pragma unroll
        for (int ni = 0; ni < 4; ni++) {
            int col = bcol + wc*32 + ni*8 + t2;
            float* p0; float* p1;
            if (CMODE == 0) {
                p0 = &C[(size_t)row * Nc + col];
                p1 = &C[(size_t)(row+8) * Nc + col];
            } else if (CMODE == 1) {
                int b = row >> 11, n = row & 2047;
                int h = col >> 6, d = col & 63;
                p0 = &C[((((size_t)b*H_ + h)*N_ + n) << 6) + d];
                p1 = p0 + (8 << 6);
            } else {
                int b = row >> 11, n = row & 2047;
                int e = col >> 10, h = (col >> 6) & 15, d = col & 63;
                p0 = &C[(((((size_t)e*B_ + b)*H_ + h)*N_ + n) << 6) + d];
                p1 = p0 + (8 << 6);
            }
            *(float2*)p0 = make_float2(acc[mi][ni][0], acc[mi][ni][1]);
            *(float2*)p1 = make_float2(acc[mi][ni][2], acc[mi][ni][3]);
        }
    }
}

// ---------------------------------------------------------------------------
// HMMA causal flash attention (attn4): 128 q-rows/block, 8 warps, 64-key tiles.
// S = Qh*Kh + Qh*Kl + Ql*Kh (3-term split); P (bf16) * (Vh + Vl).
// P stays in registers (S-accumulator layout == A-fragment layout).
// SMEM: Kh/Kl/Vh/Vl [64][72] bf16; Q staged through same buffer pre-loop.
// ---------------------------------------------------------------------------
__global__ __launch_bounds__(256) void attn4_kernel(
    const __nv_bfloat16* __restrict__ Qh, const __nv_bfloat16* __restrict__ Ql,
    const __nv_bfloat16* __restrict__ Kh, const __nv_bfloat16* __restrict__ Kl,
    const __nv_bfloat16* __restrict__ Vh, const __nv_bfloat16* __restrict__ Vl,
    float* __restrict__ O) {
    __shared__ __nv_bfloat16 sm[4*64*72];
    __nv_bfloat16* sKh = sm;
    __nv_bfloat16* sKl = sm + 4608;
    __nv_bfloat16* sVh = sm + 9216;
    __nv_bfloat16* sVl = sm + 13824;

    int tid = threadIdx.x, lane = tid & 31, w = tid >> 5;
    size_t matq = blockIdx.y;
    size_t mat  = blockIdx.y + (size_t)blockIdx.z * BH_;
    const __nv_bfloat16* qh = Qh + (matq << 17);
    const __nv_bfloat16* ql = Ql + (matq << 17);
    const __nv_bfloat16* kh = Kh + (mat << 17);
    const __nv_bfloat16* kl = Kl + (mat << 17);
    const __nv_bfloat16* vh = Vh + (mat << 17);
    const __nv_bfloat16* vl = Vl + (mat << 17);
    float* o = O + (mat << 17);
    int q0 = blockIdx.x * 128;

    // Stage Q hi/lo ([128][72] overlaid on the 4 K/V buffers), lift to regs.
    #pragma unroll
    for (int it = 0; it < 4; it++) {
        int idx = tid + it*256;
        int r = idx >> 3, c8 = (idx & 7) << 3;
        *(uint4*)(sm + r*72 + c8)        = *(const uint4*)(qh + ((size_t)(q0 + r) << 6) + c8);
        *(uint4*)(sm + 9216 + r*72 + c8) = *(const uint4*)(ql + ((size_t)(q0 + r) << 6) + c8);
    }
    __syncthreads();
    uint32_t qfh[4][4], qfl[4][4];
    {
        uint32_t b0 = smem_u32(sm);
        int ar = w*16 + (lane & 15);
        int ac = (lane >> 4) << 3;
        #pragma unroll
        for (int kc = 0; kc < 4; kc++) {
            uint32_t off = (uint32_t)((ar*72 + kc*16 + ac) << 1);
            ldsm4(qfh[kc], b0 + off);
            ldsm4(qfl[kc], b0 + 18432 + off);
        }
    }

    float m0 = -INFINITY, m1 = -INFINITY, l0 = 0.f, l1 = 0.f;
    float oa[8][4];
    #pragma unroll
    for (int dt = 0; dt < 8; dt++)
        #pragma unroll
        for (int j = 0; j < 4; j++) oa[dt][j] = 0.f;

    int g = lane >> 2;
    int qr0 = q0 + w*16 + g, qr1 = qr0 + 8;
    int cbase = (lane & 3) << 1;

    uint32_t skh_u = smem_u32(sKh), skl_u = smem_u32(sKl);
    uint32_t svh_u = smem_u32(sVh), svl_u = smem_u32(sVl);
    int br = lane & 15, bc = (lane >> 4) << 3;

    for (int k0 = 0; k0 <= q0 + 64; k0 += 64) {
        __syncthreads();
        #pragma unroll
        for (int it = 0; it < 2; it++) {
            int idx = tid + it*256;
            int r = idx >> 3, c8 = (idx & 7) << 3;
            size_t gi = ((size_t)(k0 + r) << 6) + c8;
            *(uint4*)(sKh + r*72 + c8) = *(const uint4*)(kh + gi);
            *(uint4*)(sKl + r*72 + c8) = *(const uint4*)(kl + gi);
            *(uint4*)(sVh + r*72 + c8) = *(const uint4*)(vh + gi);
            *(uint4*)(sVl + r*72 + c8) = *(const uint4*)(vl + gi);
        }
        __syncthreads();

        // --- S phase ---
        float s[8][4];
        #pragma unroll
        for (int nt = 0; nt < 8; nt++)
            #pragma unroll
            for (int j = 0; j < 4; j++) s[nt][j] = 0.f;
        #pragma unroll
        for (int ntp = 0; ntp < 4; ntp++) {
            #pragma unroll
            for (int kc = 0; kc < 4; kc++) {
                uint32_t r4h[4], r4l[4];
                uint32_t off = (uint32_t)(((ntp*16 + br)*72 + kc*16 + bc) << 1);
                ldsm4(r4h, skh_u + off);
                ldsm4(r4l, skl_u + off);
                uint32_t be[2]  = {r4h[0], r4h[2]}, bo[2]  = {r4h[1], r4h[3]};
                uint32_t bel[2] = {r4l[0], r4l[2]}, bol[2] = {r4l[1], r4l[3]};
                mma16816(s[2*ntp],   qfh[kc], be);
                mma16816(s[2*ntp],   qfh[kc], bel);
                mma16816(s[2*ntp],   qfl[kc], be);
                mma16816(s[2*ntp+1], qfh[kc], bo);
                mma16816(s[2*ntp+1], qfh[kc], bol);
                mma16816(s[2*ntp+1], qfl[kc], bo);
            }
        }

        // --- softmax ---
        if (k0 + 63 > q0) {
            #pragma unroll
            for (int nt = 0; nt < 8; nt++) {
                int key = k0 + nt*8 + cbase;
                s[nt][0] = (key   <= qr0) ? s[nt][0]*0.125f : -INFINITY;
                s[nt][1] = (key+1 <= qr0) ? s[nt][1]*0.125f : -INFINITY;
                s[nt][2] = (key   <= qr1) ? s[nt][2]*0.125f : -INFINITY;
                s[nt][3] = (key+1 <= qr1) ? s[nt][3]*0.125f : -INFINITY;
            }
        } else {
            #pragma unroll
            for (int nt = 0; nt < 8; nt++)
                #pragma unroll
                for (int j = 0; j < 4; j++) s[nt][j] *= 0.125f;
        }
        float mt0 = m0, mt1 = m1;
        #pragma unroll
        for (int nt = 0; nt < 8; nt++) {
            mt0 = fmaxf(mt0, fmaxf(s[nt][0], s[nt][1]));
            mt1 = fmaxf(mt1, fmaxf(s[nt][2], s[nt][3]));
        }
        mt0 = fmaxf(mt0, __shfl_xor_sync(~0u, mt0, 1));
        mt0 = fmaxf(mt0, __shfl_xor_sync(~0u, mt0, 2));
        mt1 = fmaxf(mt1, __shfl_xor_sync(~0u, mt1, 1));
        mt1 = fmaxf(mt1, __shfl_xor_sync(~0u, mt1, 2));
        float c0 = __expf(m0 - mt0), c1 = __expf(m1 - mt1);
        m0 = mt0; m1 = mt1;
        float ps0 = 0.f, ps1 = 0.f;
        uint32_t pf[4][4];
        #pragma unroll
        for (int kp = 0; kp < 4; kp++) {
            float p00 = __expf(s[2*kp][0]   - m0), p01 = __expf(s[2*kp][1]   - m0);
            float p10 = __expf(s[2*kp][2]   - m1), p11 = __expf(s[2*kp][3]   - m1);
            float p20 = __expf(s[2*kp+1][0] - m0), p21 = __expf(s[2*kp+1][1] - m0);
            float p30 = __expf(s[2*kp+1][2] - m1), p31 = __expf(s[2*kp+1][3] - m1);
            ps0 += p00 + p01 + p20 + p21;
            ps1 += p10 + p11 + p30 + p31;
            pf[kp][0] = packbf(p00, p01);
            pf[kp][1] = packbf(p10, p11);
            pf[kp][2] = packbf(p20, p21);
            pf[kp][3] = packbf(p30, p31);
        }
        l0 = l0*c0 + ps0;
        l1 = l1*c1 + ps1;
        #pragma unroll
        for (int dt = 0; dt < 8; dt++) {
            oa[dt][0] *= c0; oa[dt][1] *= c0;
            oa[dt][2] *= c1; oa[dt][3] *= c1;
        }

        // --- PV phase: oa += P * (Vh + Vl) ---
        #pragma unroll
        for (int dt = 0; dt < 8; dt++) {
            #pragma unroll
            for (int kc = 0; kc < 4; kc++) {
                uint32_t vb[2], vbl[2];
                uint32_t off = (uint32_t)(((kc*16 + br)*72 + dt*8) << 1);
                ldsm2t(vb,  svh_u + off);
                ldsm2t(vbl, svl_u + off);
                mma16816(oa[dt], pf[kc], vb);
                mma16816(oa[dt], pf[kc], vbl);
            }
        }
    }

    l0 += __shfl_xor_sync(~0u, l0, 1);
    l0 += __shfl_xor_sync(~0u, l0, 2);
    l1 += __shfl_xor_sync(~0u, l1, 1);
    l1 += __shfl_xor_sync(~0u, l1, 2);
    float i0 = 1.f / l0, i1 = 1.f / l1;
    #pragma unroll
    for (int dt = 0; dt < 8; dt++) {
        int col = dt*8 + cbase;
        *(float2*)&o[((size_t)qr0 << 6) + col] = make_float2(oa[dt][0]*i0, oa[dt][1]*i0);
        *(float2*)&o[((size_t)qr1 << 6) + col] = make_float2(oa[dt][2]*i1, oa[dt][3]*i1);
    }
}

// ---------------------------------------------------------------------------
// Launch
// ---------------------------------------------------------------------------
extern "C" void kernel_launch(void* const* d_in, const int* in_sizes, int n_in,
                              void* d_out, int out_size) {
    const float* tokens        = (const float*)d_in[0];
    const float* w_norm        = (const float*)d_in[1];
    const float* w_q           = (const float*)d_in[2];
    const float* w_k           = (const float*)d_in[3];
    const float* w_v           = (const float*)d_in[4];
    const float* w_key_norms   = (const float*)d_in[5];
    const float* w_nested_knorm= (const float*)d_in[6];
    const float* w_out         = (const float*)d_in[7];
    float* out = (float*)d_out;

    float *pq, *pk, *pv, *pn, *po;
    __nv_bfloat16 *pxh, *pxl, *pwh, *pwl, *poh, *pol;
    __nv_bfloat16 *pqh, *pql, *pkh, *pkl, *pvh, *pvl, *pnh, *pnl;
    cudaGetSymbolAddress((void**)&pq, g_q);
    cudaGetSymbolAddress((void**)&pk, g_k);
    cudaGetSymbolAddress((void**)&pv, g_v);
    cudaGetSymbolAddress((void**)&pn, g_n);
    cudaGetSymbolAddress((void**)&po, g_o);
    cudaGetSymbolAddress((void**)&pxh, g_xh);
    cudaGetSymbolAddress((void**)&pxl, g_xl);
    cudaGetSymbolAddress((void**)&pwh, g_wh);
    cudaGetSymbolAddress((void**)&pwl, g_wl);
    cudaGetSymbolAddress((void**)&poh, g_oh);
    cudaGetSymbolAddress((void**)&pol, g_ol);
    cudaGetSymbolAddress((void**)&pqh, g_qh);
    cudaGetSymbolAddress((void**)&pql, g_ql);
    cudaGetSymbolAddress((void**)&pkh, g_kh);
    cudaGetSymbolAddress((void**)&pkl, g_kl);
    cudaGetSymbolAddress((void**)&pvh, g_vh);
    cudaGetSymbolAddress((void**)&pvl, g_vl);
    cudaGetSymbolAddress((void**)&pnh, g_nh);
    cudaGetSymbolAddress((void**)&pnl, g_nl);

    static int attr_set = 0;
    if (!attr_set) {
        cudaFuncSetAttribute(hgemm_kernel<0>, cudaFuncAttributeMaxDynamicSharedMemorySize, HG_SMEM);
        cudaFuncSetAttribute(hgemm_kernel<1>, cudaFuncAttributeMaxDynamicSharedMemorySize, HG_SMEM);
        cudaFuncSetAttribute(hgemm_kernel<2>, cudaFuncAttributeMaxDynamicSharedMemorySize, HG_SMEM);
        attr_set = 1;
    }

    // 1) x = rmsnorm(tokens), split to bf16 hi/lo
    rmsnorm_split_kernel<<<ROWS_, 256>>>(tokens, w_norm, pxh, pxl);
    // 2) rope tables + weight splits
    rope_table_kernel<<<(N_*32 + 255)/256, 256>>>();
    split_kernel<<<1024, 256>>>(w_q,   pwh + WQ_OFF, pwl + WQ_OFF, 262144);
    split_kernel<<<3072, 256>>>(w_k,   pwh + WK_OFF, pwl + WK_OFF, 786432);
    split_kernel<<<3072, 256>>>(w_v,   pwh + WV_OFF, pwl + WV_OFF, 786432);
    split_kernel<<<1024, 256>>>(w_out, pwh + WO_OFF, pwl + WO_OFF, 262144);
    // 3) q/k/v projections (HMMA)
    hgemm_kernel<1><<<dim3(8, 32),  256, HG_SMEM>>>(pxh, pxl, pwh + WQ_OFF, pwl + WQ_OFF, pq, DIM_, DIM_);
    hgemm_kernel<2><<<dim3(24, 32), 256, HG_SMEM>>>(pxh, pxl, pwh + WK_OFF, pwl + WK_OFF, pk, DIM_, 3*DIM_);
    hgemm_kernel<2><<<dim3(24, 32), 256, HG_SMEM>>>(pxh, pxl, pwh + WV_OFF, pwl + WV_OFF, pv, DIM_, 3*DIM_);
    // 4) key rmsnorm + rope, then split q/k/v to bf16 hi/lo
    {
        int rows = 3*BH_*N_;
        rmsnorm_dh_kernel<<<(rows*32 + 255)/256, 256>>>(pk, w_key_norms, 1, rows);
        rope_kernel<<<(BH_*N_*32 + 255)/256, 256>>>(pq, BH_*N_);
        rope_kernel<<<(rows*32 + 255)/256, 256>>>(pk, rows);
        split_kernel<<<4096, 256>>>(pq, pqh, pql, 1048576);
        split_kernel<<<12288, 256>>>(pk, pkh, pkl, 3145728);
        split_kernel<<<12288, 256>>>(pv, pvh, pvl, 3145728);
    }
    // 5) three inner causal attentions (HMMA) -> nq|nk|nv fp32
    attn4_kernel<<<dim3(N_/128, BH_, 3), 256>>>(pqh, pql, pkh, pkl, pvh, pvl, pn);
    // 6) nk rmsnorm, rope nq & nk, split all three slabs
    {
        float* pnk = pn + SLAB_;
        int rows = BH_*N_;
        rmsnorm_dh_kernel<<<(rows*32 + 255)/256, 256>>>(pnk, w_nested_knorm, 0, rows);
        rope_kernel<<<(rows*32 + 255)/256, 256>>>(pn, rows);
        rope_kernel<<<(rows*32 + 255)/256, 256>>>(pnk, rows);
        split_kernel<<<4096, 256>>>(pn,           pnh,           pnl,           1048576);
        split_kernel<<<4096, 256>>>(pn + SLAB_,   pnh + SLAB_,   pnl + SLAB_,   1048576);
        split_kernel<<<4096, 256>>>(pn + 2*SLAB_, pnh + 2*SLAB_, pnl + 2*SLAB_, 1048576);
    }
    // 7) outer causal attention (HMMA): attend(nq, nk, nv) -> g_o
    attn4_kernel<<<dim3(N_/128, BH_, 1), 256>>>(pnh, pnl, pnh + SLAB_, pnl + SLAB_,
                                                pnh + 2*SLAB_, pnl + 2*SLAB_, po);
    // 8) gather+split attention output, then output projection (HMMA)
    oconv_kernel<<<4096, 256>>>(po, poh, pol);
    hgemm_kernel<0><<<dim3(8, 32), 256, HG_SMEM>>>(poh, pol, pwh + WO_OFF, pwl + WO_OFF, out, DIM_, DIM_);
}

// round 9
// speedup vs baseline: 4.5705x; 1.1051x over previous
#include <cuda_runtime.h>
#include <cuda_bf16.h>
#include <math.h>
#include <stdint.h>

// Problem constants
#define B_  2
#define N_  2048
#define DIM_ 1024
#define H_  16
#define DH_ 64
#define BH_ (B_*H_)            // 32
#define ROWS_ (B_*N_)          // 4096
#define EPS_ 1.1920929e-07f

// ---------------------------------------------------------------------------
// Scratch (allocation-free: __device__ globals)
// ---------------------------------------------------------------------------
__device__ float g_q[(size_t)BH_*N_*DH_];          // (b,h,n,d) fp32
__device__ float g_k[(size_t)3*BH_*N_*DH_];        // (e,b,h,n,d) fp32
__device__ float g_n[(size_t)3*BH_*N_*DH_];        // nq|nk (fp32; nv unused)
__device__ float g_o[(size_t)BH_*N_*DH_];          // outer attend output
__device__ float g_cos[N_*32];
__device__ float g_sin[N_*32];
// bf16 hi/lo splits
__device__ __nv_bfloat16 g_xh[(size_t)ROWS_*DIM_];
__device__ __nv_bfloat16 g_xl[(size_t)ROWS_*DIM_];
__device__ __nv_bfloat16 g_wh[8388608];            // wq|wk|wv|wout
__device__ __nv_bfloat16 g_wl[8388608];
__device__ __nv_bfloat16 g_oh[(size_t)ROWS_*DIM_]; // gathered (bn, hd)
__device__ __nv_bfloat16 g_ol[(size_t)ROWS_*DIM_];
__device__ __nv_bfloat16 g_qh[4194304],  g_ql[4194304];
__device__ __nv_bfloat16 g_kh[12582912], g_kl[12582912];
__device__ __nv_bfloat16 g_vh[12582912], g_vl[12582912];
__device__ __nv_bfloat16 g_nh[12582912], g_nl[12582912];  // nq|nk|nv splits

#define WQ_OFF 0
#define WK_OFF 1048576
#define WV_OFF 4194304
#define WO_OFF 7340032
#define SLAB_ 4194304

// ---------------------------------------------------------------------------
// PTX helpers
// ---------------------------------------------------------------------------
__device__ __forceinline__ uint32_t smem_u32(const void* p) {
    uint32_t a;
    asm("{ .reg .u64 t; cvta.to.shared.u64 t, %1; cvt.u32.u64 %0, t; }" : "=r"(a) : "l"(p));
    return a;
}
__device__ __forceinline__ void ldsm4(uint32_t* r, uint32_t addr) {
    asm volatile("ldmatrix.sync.aligned.m8n8.x4.shared.b16 {%0,%1,%2,%3}, [%4];"
                 : "=r"(r[0]), "=r"(r[1]), "=r"(r[2]), "=r"(r[3]) : "r"(addr));
}
__device__ __forceinline__ void ldsm4t(uint32_t* r, uint32_t addr) {
    asm volatile("ldmatrix.sync.aligned.m8n8.x4.trans.shared.b16 {%0,%1,%2,%3}, [%4];"
                 : "=r"(r[0]), "=r"(r[1]), "=r"(r[2]), "=r"(r[3]) : "r"(addr));
}
__device__ __forceinline__ void mma16816(float* c, const uint32_t* a, const uint32_t* b) {
    asm volatile("mma.sync.aligned.m16n8k16.row.col.f32.bf16.bf16.f32 "
                 "{%0,%1,%2,%3}, {%4,%5,%6,%7}, {%8,%9}, {%0,%1,%2,%3};"
                 : "+f"(c[0]), "+f"(c[1]), "+f"(c[2]), "+f"(c[3])
                 : "r"(a[0]), "r"(a[1]), "r"(a[2]), "r"(a[3]), "r"(b[0]), "r"(b[1]));
}
__device__ __forceinline__ void cpa16(uint32_t saddr, const void* g) {
    asm volatile("cp.async.cg.shared.global [%0], [%1], 16;" :: "r"(saddr), "l"(g));
}
#define CP_COMMIT() asm volatile("cp.async.commit_group;")
#define CP_WAIT0()  asm volatile("cp.async.wait_group 0;")
__device__ __forceinline__ void split1(float f, __nv_bfloat16& h, __nv_bfloat16& l) {
    h = __float2bfloat16(f);
    l = __float2bfloat16(f - __bfloat162float(h));
}
__device__ __forceinline__ uint32_t packbf(float a, float b) {
    __nv_bfloat162 t = __floats2bfloat162_rn(a, b);
    return *reinterpret_cast<uint32_t*>(&t);
}
__device__ __forceinline__ uint32_t pack2(__nv_bfloat16 a, __nv_bfloat16 b) {
    uint32_t r = (uint32_t)*reinterpret_cast<unsigned short*>(&a)
               | ((uint32_t)*reinterpret_cast<unsigned short*>(&b) << 16);
    return r;
}

// ---------------------------------------------------------------------------
// RMSNorm over DIM=1024 -> bf16 hi/lo splits (one block per row)
// ---------------------------------------------------------------------------
__global__ void rmsnorm_split_kernel(const float* __restrict__ in,
                                     const float* __restrict__ w,
                                     __nv_bfloat16* __restrict__ xh,
                                     __nv_bfloat16* __restrict__ xl) {
    int row = blockIdx.x;
    int i4 = threadIdx.x << 2;
    float4 v = *(const float4*)&in[(size_t)row*DIM_ + i4];
    float s = v.x*v.x + v.y*v.y + v.z*v.z + v.w*v.w;
    __shared__ float sm[8];
    for (int o = 16; o > 0; o >>= 1) s += __shfl_xor_sync(~0u, s, o);
    if ((threadIdx.x & 31) == 0) sm[threadIdx.x >> 5] = s;
    __syncthreads();
    if (threadIdx.x < 8) {
        s = sm[threadIdx.x];
        for (int o = 4; o > 0; o >>= 1) s += __shfl_xor_sync(0xffu, s, o);
        if (threadIdx.x == 0) sm[0] = s;
    }
    __syncthreads();
    float inv = rsqrtf(sm[0] * (1.f/DIM_) + EPS_);
    float4 wv = *(const float4*)&w[i4];
    float f[4] = {v.x*inv*wv.x, v.y*inv*wv.y, v.z*inv*wv.z, v.w*inv*wv.w};
    __nv_bfloat16 h[4], l[4];
    #pragma unroll
    for (int j = 0; j < 4; j++) split1(f[j], h[j], l[j]);
    *(uint2*)&xh[(size_t)row*DIM_ + i4] = *(uint2*)h;
    *(uint2*)&xl[(size_t)row*DIM_ + i4] = *(uint2*)l;
}

// ---------------------------------------------------------------------------
// Elementwise fp32 -> bf16 hi/lo split (weights only now)
// ---------------------------------------------------------------------------
__global__ void split_kernel(const float* __restrict__ in,
                             __nv_bfloat16* __restrict__ hi,
                             __nv_bfloat16* __restrict__ lo, int n4) {
    int i = blockIdx.x*256 + threadIdx.x;
    if (i >= n4) return;
    float4 v = ((const float4*)in)[i];
    float f[4] = {v.x, v.y, v.z, v.w};
    __nv_bfloat16 h[4], l[4];
    #pragma unroll
    for (int j = 0; j < 4; j++) split1(f[j], h[j], l[j]);
    *(uint2*)&hi[(size_t)i*4] = *(uint2*)h;
    *(uint2*)&lo[(size_t)i*4] = *(uint2*)l;
}

// ---------------------------------------------------------------------------
// Fused (optional rmsnorm_dh) + rope + bf16 split. One warp per row of 64.
// ---------------------------------------------------------------------------
__global__ void fused_rrs_kernel(const float* __restrict__ x, const float* __restrict__ w,
                                 int do_norm, int use_e, int total_rows,
                                 __nv_bfloat16* __restrict__ hi,
                                 __nv_bfloat16* __restrict__ lo) {
    int warp = (blockIdx.x * blockDim.x + threadIdx.x) >> 5;
    if (warp >= total_rows) return;
    int lane = threadIdx.x & 31;
    float2 v = ((const float2*)(x + ((size_t)warp << 6)))[lane];
    if (do_norm) {
        float s = v.x*v.x + v.y*v.y;
        for (int o = 16; o > 0; o >>= 1) s += __shfl_xor_sync(~0u, s, o);
        float inv = rsqrtf(s * (1.f/DH_) + EPS_);
        const float* ww = w + (use_e ? (warp / (BH_*N_)) * DH_ : 0);
        v.x *= inv * ww[2*lane];
        v.y *= inv * ww[2*lane+1];
    }
    int n = warp & (N_-1);
    float c = g_cos[(n<<5) + lane], sn = g_sin[(n<<5) + lane];
    float rx = v.x*c - v.y*sn, ry = v.y*c + v.x*sn;
    __nv_bfloat16 hx, lx, hy, ly;
    split1(rx, hx, lx);
    split1(ry, hy, ly);
    ((uint32_t*)hi)[(warp << 5) + lane] = pack2(hx, hy);
    ((uint32_t*)lo)[(warp << 5) + lane] = pack2(lx, ly);
}

// ---------------------------------------------------------------------------
// Gather g_o (b,h,n,d) -> row-major (b*n, h*d) + bf16 split
// ---------------------------------------------------------------------------
__global__ void oconv_kernel(const float* __restrict__ o,
                             __nv_bfloat16* __restrict__ hi,
                             __nv_bfloat16* __restrict__ lo) {
    int i = blockIdx.x*256 + threadIdx.x;
    int linear = i << 2;
    int d = linear & 63, n = (linear >> 6) & 2047;
    int h = (linear >> 17) & 15, b = linear >> 21;
    float4 v = *(const float4*)&o[linear];
    float f[4] = {v.x, v.y, v.z, v.w};
    __nv_bfloat16 hh[4], ll[4];
    #pragma unroll
    for (int j = 0; j < 4; j++) split1(f[j], hh[j], ll[j]);
    size_t oc = ((size_t)b*N_ + n)*DIM_ + h*64 + d;
    *(uint2*)&hi[oc] = *(uint2*)hh;
    *(uint2*)&lo[oc] = *(uint2*)ll;
}

// ---------------------------------------------------------------------------
// RoPE table
// ---------------------------------------------------------------------------
__global__ void rope_table_kernel() {
    int idx = blockIdx.x * blockDim.x + threadIdx.x;
    if (idx >= N_*32) return;
    int n = idx >> 5, t = idx & 31;
    float inv_freq = powf(10000.f, -(2.f * (float)t) / 64.f);
    float ang = (float)n * inv_freq;
    g_cos[idx] = cosf(ang);
    g_sin[idx] = sinf(ang);
}

// ---------------------------------------------------------------------------
// HMMA GEMM: bf16 3-term split, CTA 128x128, 8 warps (2x4),
// cp.async double-buffered 64-K chunks, ldsm4t for B.
// CMODE: 0 = row-major fp32, 1 = q layout fp32, 2 = kv layout fp32,
//        3 = kv layout bf16 hi/lo split (Ch/Cl)
// Buffer layout (elems): Ah[128*72] | Al[128*72] | Bh[64*136] | Bl[64*136]
// ---------------------------------------------------------------------------
#define HGBUF_ 35840
#define HG_SMEM (HGBUF_*2*2)     // 143360 bytes

template<int CMODE>
__global__ __launch_bounds__(256) void hgemm_kernel(
    const __nv_bfloat16* __restrict__ Ah, const __nv_bfloat16* __restrict__ Al,
    const __nv_bfloat16* __restrict__ Wh, const __nv_bfloat16* __restrict__ Wl,
    float* __restrict__ C, __nv_bfloat16* __restrict__ Ch, __nv_bfloat16* __restrict__ Cl,
    int K, int Nc) {
    extern __shared__ __nv_bfloat16 smb[];
    int tid = threadIdx.x, lane = tid & 31, wid = tid >> 5;
    int wr = wid & 1, wc = wid >> 1;
    int brow = blockIdx.y*128, bcol = blockIdx.x*128;
    uint32_t sbase = smem_u32(smb);

    float acc[4][4][4];
    #pragma unroll
    for (int mi = 0; mi < 4; mi++)
        #pragma unroll
        for (int ni = 0; ni < 4; ni++)
            #pragma unroll
            for (int j = 0; j < 4; j++) acc[mi][ni][j] = 0.f;

    int arow = wr*64 + (lane & 15);
    int acol = (lane >> 4) << 3;
    int brl  = lane & 15;
    int bq8  = (lane >> 4) << 3;

    auto issue = [&](int c, int buf) {
        uint32_t bu = sbase + buf*(HGBUF_*2);
        #pragma unroll
        for (int it = 0; it < 4; it++) {
            int idx = tid + it*256;
            int r = idx >> 3, kc = (idx & 7) << 3;
            size_t ga = (size_t)(brow + r)*K + c*64 + kc;
            cpa16(bu + ((r*72 + kc) << 1),           Ah + ga);
            cpa16(bu + 18432 + ((r*72 + kc) << 1),   Al + ga);
            int kb = idx >> 4, nc2 = (idx & 15) << 3;
            size_t gb = (size_t)(c*64 + kb)*Nc + bcol + nc2;
            cpa16(bu + 36864 + ((kb*136 + nc2) << 1), Wh + gb);
            cpa16(bu + 54272 + ((kb*136 + nc2) << 1), Wl + gb);
        }
        CP_COMMIT();
    };

    int nchunks = K >> 6;
    issue(0, 0);
    for (int c = 0; c < nchunks; c++) {
        CP_WAIT0();
        __syncthreads();
        if (c + 1 < nchunks) issue(c + 1, (c + 1) & 1);
        uint32_t bu = sbase + (c & 1)*(HGBUF_*2);
        uint32_t sa_h = bu, sa_l = bu + 18432, sb_h = bu + 36864, sb_l = bu + 54272;
        #pragma unroll
        for (int kk = 0; kk < 4; kk++) {
            int k0 = kk << 4;
            uint32_t ah[4][4], al[4][4];
            #pragma unroll
            for (int mi = 0; mi < 4; mi++) {
                uint32_t off = (uint32_t)(((arow + mi*16)*72 + k0 + acol) << 1);
                ldsm4(ah[mi], sa_h + off);
                ldsm4(al[mi], sa_l + off);
            }
            #pragma unroll
            for (int nip = 0; nip < 2; nip++) {
                uint32_t t4h[4], t4l[4];
                uint32_t off = (uint32_t)((((k0 + brl)*136) + wc*32 + nip*16 + bq8) << 1);
                ldsm4t(t4h, sb_h + off);
                ldsm4t(t4l, sb_l + off);
                uint32_t b0h[2] = {t4h[0], t4h[1]}, b1h[2] = {t4h[2], t4h[3]};
                uint32_t b0l[2] = {t4l[0], t4l[1]}, b1l[2] = {t4l[2], t4l[3]};
                #pragma unroll
                for (int mi = 0; mi < 4; mi++) {
                    mma16816(acc[mi][2*nip],   ah[mi], b0h);
                    mma16816(acc[mi][2*nip],   ah[mi], b0l);
                    mma16816(acc[mi][2*nip],   al[mi], b0h);
                    mma16816(acc[mi][2*nip+1], ah[mi], b1h);
                    mma16816(acc[mi][2*nip+1], ah[mi], b1l);
                    mma16816(acc[mi][2*nip+1], al[mi], b1h);
                }
            }
        }
        __syncthreads();
    }

    int g = lane >> 2, t2 = (lane & 3) << 1;
    #pragma unroll
    for (int mi = 0; mi < 4; mi++) {
        int row = brow + wr*64 + mi*16 + g;
        #pragma unroll
        for (int ni = 0; ni < 4; ni++) {
            int col = bcol + wc*32 + ni*8 + t2;
            if (CMODE == 3) {
                int b = row >> 11, n = row & 2047;
                int e = col >> 10, h = (col >> 6) & 15, d = col & 63;
                size_t i0 = (((((size_t)e*B_ + b)*H_ + h)*N_ + n) << 6) + d;
                __nv_bfloat16 h0, l0, h1, l1, h2, l2, h3, l3;
                split1(acc[mi][ni][0], h0, l0);
                split1(acc[mi][ni][1], h1, l1);
                split1(acc[mi][ni][2], h2, l2);
                split1(acc[mi][ni][3], h3, l3);
                *(uint32_t*)&Ch[i0] = pack2(h0, h1);
                *(uint32_t*)&Cl[i0] = pack2(l0, l1);
                *(uint32_t*)&Ch[i0 + (8 << 6)] = pack2(h2, h3);
                *(uint32_t*)&Cl[i0 + (8 << 6)] = pack2(l2, l3);
            } else {
                float* p0; float* p1;
                if (CMODE == 0) {
                    p0 = &C[(size_t)row * Nc + col];
                    p1 = &C[(size_t)(row+8) * Nc + col];
                } else if (CMODE == 1) {
                    int b = row >> 11, n = row & 2047;
                    int h = col >> 6, d = col & 63;
                    p0 = &C[((((size_t)b*H_ + h)*N_ + n) << 6) + d];
                    p1 = p0 + (8 << 6);
                } else {
                    int b = row >> 11, n = row & 2047;
                    int e = col >> 10, h = (col >> 6) & 15, d = col & 63;
                    p0 = &C[(((((size_t)e*B_ + b)*H_ + h)*N_ + n) << 6) + d];
                    p1 = p0 + (8 << 6);
                }
                *(float2*)p0 = make_float2(acc[mi][ni][0], acc[mi][ni][1]);
                *(float2*)p1 = make_float2(acc[mi][ni][2], acc[mi][ni][3]);
            }
        }
    }
}

// ---------------------------------------------------------------------------
// HMMA causal flash attention: 128 q-rows/block, 8 warps, 64-key tiles,
// cp.async double-buffered K/V, ldsm4t for V.
// S = Qh*Kh + Qh*Kl + Ql*Kh; P bf16 * (Vh + Vl).
// If blockIdx.z == zsplit: output written as bf16 hi/lo (OH/OL) else fp32 (O).
// Buffer layout per 36864B buf: Kh[64*72] | Kl | Vh | Vl
// ---------------------------------------------------------------------------
#define ATTN4_SMEM 73728

__global__ __launch_bounds__(256) void attn4_kernel(
    const __nv_bfloat16* __restrict__ Qh, const __nv_bfloat16* __restrict__ Ql,
    const __nv_bfloat16* __restrict__ Kh, const __nv_bfloat16* __restrict__ Kl,
    const __nv_bfloat16* __restrict__ Vh, const __nv_bfloat16* __restrict__ Vl,
    float* __restrict__ O, __nv_bfloat16* __restrict__ OH, __nv_bfloat16* __restrict__ OL,
    int zsplit) {
    extern __shared__ __nv_bfloat16 smb[];
    int tid = threadIdx.x, lane = tid & 31, w = tid >> 5;
    size_t matq = blockIdx.y;
    size_t mat  = blockIdx.y + (size_t)blockIdx.z * BH_;
    const __nv_bfloat16* qh = Qh + (matq << 17);
    const __nv_bfloat16* ql = Ql + (matq << 17);
    const __nv_bfloat16* kh = Kh + (mat << 17);
    const __nv_bfloat16* kl = Kl + (mat << 17);
    const __nv_bfloat16* vh = Vh + (mat << 17);
    const __nv_bfloat16* vl = Vl + (mat << 17);
    int q0 = blockIdx.x * 128;
    uint32_t sbase = smem_u32(smb);

    // Stage Q hi/lo through buffer region, lift to registers
    #pragma unroll
    for (int it = 0; it < 4; it++) {
        int idx = tid + it*256;
        int r = idx >> 3, c8 = (idx & 7) << 3;
        *(uint4*)(smb + r*72 + c8)        = *(const uint4*)(qh + ((size_t)(q0 + r) << 6) + c8);
        *(uint4*)(smb + 9216 + r*72 + c8) = *(const uint4*)(ql + ((size_t)(q0 + r) << 6) + c8);
    }
    __syncthreads();
    uint32_t qfh[4][4], qfl[4][4];
    {
        int ar = w*16 + (lane & 15);
        int ac = (lane >> 4) << 3;
        #pragma unroll
        for (int kc = 0; kc < 4; kc++) {
            uint32_t off = (uint32_t)((ar*72 + kc*16 + ac) << 1);
            ldsm4(qfh[kc], sbase + off);
            ldsm4(qfl[kc], sbase + 18432 + off);
        }
    }
    __syncthreads();

    auto issue = [&](int k0, int buf) {
        uint32_t bu = sbase + buf*36864;
        #pragma unroll
        for (int it = 0; it < 2; it++) {
            int idx = tid + it*256;
            int r = idx >> 3, c8 = (idx & 7) << 3;
            size_t gi = ((size_t)(k0 + r) << 6) + c8;
            uint32_t so = (uint32_t)((r*72 + c8) << 1);
            cpa16(bu + so,          kh + gi);
            cpa16(bu + 9216  + so,  kl + gi);
            cpa16(bu + 18432 + so,  vh + gi);
            cpa16(bu + 27648 + so,  vl + gi);
        }
        CP_COMMIT();
    };

    float m0 = -INFINITY, m1 = -INFINITY, l0 = 0.f, l1 = 0.f;
    float oa[8][4];
    #pragma unroll
    for (int dt = 0; dt < 8; dt++)
        #pragma unroll
        for (int j = 0; j < 4; j++) oa[dt][j] = 0.f;

    int g = lane >> 2;
    int qr0 = q0 + w*16 + g, qr1 = qr0 + 8;
    int cbase = (lane & 3) << 1;
    int br = lane & 15, bc = (lane >> 4) << 3;

    int kend = q0 + 64;
    int ntiles = (q0 >> 6) + 2;
    issue(0, 0);
    for (int t = 0; t < ntiles; t++) {
        int k0 = t << 6;
        CP_WAIT0();
        __syncthreads();
        if (k0 + 64 <= kend) issue(k0 + 64, (t + 1) & 1);
        uint32_t bu = sbase + (t & 1)*36864;
        uint32_t skh_u = bu, skl_u = bu + 9216, svh_u = bu + 18432, svl_u = bu + 27648;

        // --- S phase ---
        float s[8][4];
        #pragma unroll
        for (int nt = 0; nt < 8; nt++)
            #pragma unroll
            for (int j = 0; j < 4; j++) s[nt][j] = 0.f;
        #pragma unroll
        for (int ntp = 0; ntp < 4; ntp++) {
            #pragma unroll
            for (int kc = 0; kc < 4; kc++) {
                uint32_t r4h[4], r4l[4];
                uint32_t off = (uint32_t)(((ntp*16 + br)*72 + kc*16 + bc) << 1);
                ldsm4(r4h, skh_u + off);
                ldsm4(r4l, skl_u + off);
                uint32_t be[2]  = {r4h[0], r4h[2]}, bo[2]  = {r4h[1], r4h[3]};
                uint32_t bel[2] = {r4l[0], r4l[2]}, bol[2] = {r4l[1], r4l[3]};
                mma16816(s[2*ntp],   qfh[kc], be);
                mma16816(s[2*ntp],   qfh[kc], bel);
                mma16816(s[2*ntp],   qfl[kc], be);
                mma16816(s[2*ntp+1], qfh[kc], bo);
                mma16816(s[2*ntp+1], qfh[kc], bol);
                mma16816(s[2*ntp+1], qfl[kc], bo);
            }
        }

        // --- softmax ---
        if (k0 + 63 > q0) {
            #pragma unroll
            for (int nt = 0; nt < 8; nt++) {
                int key = k0 + nt*8 + cbase;
                s[nt][0] = (key   <= qr0) ? s[nt][0]*0.125f : -INFINITY;
                s[nt][1] = (key+1 <= qr0) ? s[nt][1]*0.125f : -INFINITY;
                s[nt][2] = (key   <= qr1) ? s[nt][2]*0.125f : -INFINITY;
                s[nt][3] = (key+1 <= qr1) ? s[nt][3]*0.125f : -INFINITY;
            }
        } else {
            #pragma unroll
            for (int nt = 0; nt < 8; nt++)
                #pragma unroll
                for (int j = 0; j < 4; j++) s[nt][j] *= 0.125f;
        }
        float mt0 = m0, mt1 = m1;
        #pragma unroll
        for (int nt = 0; nt < 8; nt++) {
            mt0 = fmaxf(mt0, fmaxf(s[nt][0], s[nt][1]));
            mt1 = fmaxf(mt1, fmaxf(s[nt][2], s[nt][3]));
        }
        mt0 = fmaxf(mt0, __shfl_xor_sync(~0u, mt0, 1));
        mt0 = fmaxf(mt0, __shfl_xor_sync(~0u, mt0, 2));
        mt1 = fmaxf(mt1, __shfl_xor_sync(~0u, mt1, 1));
        mt1 = fmaxf(mt1, __shfl_xor_sync(~0u, mt1, 2));
        float c0 = __expf(m0 - mt0), c1 = __expf(m1 - mt1);
        m0 = mt0; m1 = mt1;
        float ps0 = 0.f, ps1 = 0.f;
        uint32_t pf[4][4];
        #pragma unroll
        for (int kp = 0; kp < 4; kp++) {
            float p00 = __expf(s[2*kp][0]   - m0), p01 = __expf(s[2*kp][1]   - m0);
            float p10 = __expf(s[2*kp][2]   - m1), p11 = __expf(s[2*kp][3]   - m1);
            float p20 = __expf(s[2*kp+1][0] - m0), p21 = __expf(s[2*kp+1][1] - m0);
            float p30 = __expf(s[2*kp+1][2] - m1), p31 = __expf(s[2*kp+1][3] - m1);
            ps0 += p00 + p01 + p20 + p21;
            ps1 += p10 + p11 + p30 + p31;
            pf[kp][0] = packbf(p00, p01);
            pf[kp][1] = packbf(p10, p11);
            pf[kp][2] = packbf(p20, p21);
            pf[kp][3] = packbf(p30, p31);
        }
        l0 = l0*c0 + ps0;
        l1 = l1*c1 + ps1;
        #pragma unroll
        for (int dt = 0; dt < 8; dt++) {
            oa[dt][0] *= c0; oa[dt][1] *= c0;
            oa[dt][2] *= c1; oa[dt][3] *= c1;
        }

        // --- PV phase (ldsm4t: one load feeds two dt fragments) ---
        #pragma unroll
        for (int dtp = 0; dtp < 4; dtp++) {
            #pragma unroll
            for (int kc = 0; kc < 4; kc++) {
                uint32_t t4h[4], t4l[4];
                uint32_t off = (uint32_t)(((kc*16 + br)*72 + dtp*16 + bc) << 1);
                ldsm4t(t4h, svh_u + off);
                ldsm4t(t4l, svl_u + off);
                uint32_t b0h[2] = {t4h[0], t4h[1]}, b1h[2] = {t4h[2], t4h[3]};
                uint32_t b0l[2] = {t4l[0], t4l[1]}, b1l[2] = {t4l[2], t4l[3]};
                mma16816(oa[2*dtp],   pf[kc], b0h);
                mma16816(oa[2*dtp],   pf[kc], b0l);
                mma16816(oa[2*dtp+1], pf[kc], b1h);
                mma16816(oa[2*dtp+1], pf[kc], b1l);
            }
        }
        __syncthreads();
    }

    l0 += __shfl_xor_sync(~0u, l0, 1);
    l0 += __shfl_xor_sync(~0u, l0, 2);
    l1 += __shfl_xor_sync(~0u, l1, 1);
    l1 += __shfl_xor_sync(~0u, l1, 2);
    float i0 = 1.f / l0, i1 = 1.f / l1;
    if ((int)blockIdx.z == zsplit) {
        __nv_bfloat16* oh = OH + (mat << 17);
        __nv_bfloat16* ol = OL + (mat << 17);
        #pragma unroll
        for (int dt = 0; dt < 8; dt++) {
            int col = dt*8 + cbase;
            __nv_bfloat16 h0, l0b, h1, l1b;
            split1(oa[dt][0]*i0, h0, l0b);
            split1(oa[dt][1]*i0, h1, l1b);
            *(uint32_t*)&oh[((size_t)qr0 << 6) + col] = pack2(h0, h1);
            *(uint32_t*)&ol[((size_t)qr0 << 6) + col] = pack2(l0b, l1b);
            split1(oa[dt][2]*i1, h0, l0b);
            split1(oa[dt][3]*i1, h1, l1b);
            *(uint32_t*)&oh[((size_t)qr1 << 6) + col] = pack2(h0, h1);
            *(uint32_t*)&ol[((size_t)qr1 << 6) + col] = pack2(l0b, l1b);
        }
    } else {
        float* o = O + (mat << 17);
        #pragma unroll
        for (int dt = 0; dt < 8; dt++) {
            int col = dt*8 + cbase;
            *(float2*)&o[((size_t)qr0 << 6) + col] = make_float2(oa[dt][0]*i0, oa[dt][1]*i0);
            *(float2*)&o[((size_t)qr1 << 6) + col] = make_float2(oa[dt][2]*i1, oa[dt][3]*i1);
        }
    }
}

// ---------------------------------------------------------------------------
// Launch
// ---------------------------------------------------------------------------
extern "C" void kernel_launch(void* const* d_in, const int* in_sizes, int n_in,
                              void* d_out, int out_size) {
    const float* tokens        = (const float*)d_in[0];
    const float* w_norm        = (const float*)d_in[1];
    const float* w_q           = (const float*)d_in[2];
    const float* w_k           = (const float*)d_in[3];
    const float* w_v           = (const float*)d_in[4];
    const float* w_key_norms   = (const float*)d_in[5];
    const float* w_nested_knorm= (const float*)d_in[6];
    const float* w_out         = (const float*)d_in[7];
    float* out = (float*)d_out;

    float *pq, *pk, *pn, *po;
    __nv_bfloat16 *pxh, *pxl, *pwh, *pwl, *poh, *pol;
    __nv_bfloat16 *pqh, *pql, *pkh, *pkl, *pvh, *pvl, *pnh, *pnl;
    cudaGetSymbolAddress((void**)&pq, g_q);
    cudaGetSymbolAddress((void**)&pk, g_k);
    cudaGetSymbolAddress((void**)&pn, g_n);
    cudaGetSymbolAddress((void**)&po, g_o);
    cudaGetSymbolAddress((void**)&pxh, g_xh);
    cudaGetSymbolAddress((void**)&pxl, g_xl);
    cudaGetSymbolAddress((void**)&pwh, g_wh);
    cudaGetSymbolAddress((void**)&pwl, g_wl);
    cudaGetSymbolAddress((void**)&poh, g_oh);
    cudaGetSymbolAddress((void**)&pol, g_ol);
    cudaGetSymbolAddress((void**)&pqh, g_qh);
    cudaGetSymbolAddress((void**)&pql, g_ql);
    cudaGetSymbolAddress((void**)&pkh, g_kh);
    cudaGetSymbolAddress((void**)&pkl, g_kl);
    cudaGetSymbolAddress((void**)&pvh, g_vh);
    cudaGetSymbolAddress((void**)&pvl, g_vl);
    cudaGetSymbolAddress((void**)&pnh, g_nh);
    cudaGetSymbolAddress((void**)&pnl, g_nl);

    static int attr_set = 0;
    if (!attr_set) {
        cudaFuncSetAttribute(hgemm_kernel<0>, cudaFuncAttributeMaxDynamicSharedMemorySize, HG_SMEM);
        cudaFuncSetAttribute(hgemm_kernel<1>, cudaFuncAttributeMaxDynamicSharedMemorySize, HG_SMEM);
        cudaFuncSetAttribute(hgemm_kernel<2>, cudaFuncAttributeMaxDynamicSharedMemorySize, HG_SMEM);
        cudaFuncSetAttribute(hgemm_kernel<3>, cudaFuncAttributeMaxDynamicSharedMemorySize, HG_SMEM);
        cudaFuncSetAttribute(attn4_kernel, cudaFuncAttributeMaxDynamicSharedMemorySize, ATTN4_SMEM);
        attr_set = 1;
    }

    // 1) x = rmsnorm(tokens), split to bf16 hi/lo
    rmsnorm_split_kernel<<<ROWS_, 256>>>(tokens, w_norm, pxh, pxl);
    // 2) rope tables + weight splits
    rope_table_kernel<<<(N_*32 + 255)/256, 256>>>();
    split_kernel<<<1024, 256>>>(w_q,   pwh + WQ_OFF, pwl + WQ_OFF, 262144);
    split_kernel<<<3072, 256>>>(w_k,   pwh + WK_OFF, pwl + WK_OFF, 786432);
    split_kernel<<<3072, 256>>>(w_v,   pwh + WV_OFF, pwl + WV_OFF, 786432);
    split_kernel<<<1024, 256>>>(w_out, pwh + WO_OFF, pwl + WO_OFF, 262144);
    // 3) q/k/v projections (HMMA); v written pre-split
    hgemm_kernel<1><<<dim3(8, 32),  256, HG_SMEM>>>(pxh, pxl, pwh + WQ_OFF, pwl + WQ_OFF, pq, nullptr, nullptr, DIM_, DIM_);
    hgemm_kernel<2><<<dim3(24, 32), 256, HG_SMEM>>>(pxh, pxl, pwh + WK_OFF, pwl + WK_OFF, pk, nullptr, nullptr, DIM_, 3*DIM_);
    hgemm_kernel<3><<<dim3(24, 32), 256, HG_SMEM>>>(pxh, pxl, pwh + WV_OFF, pwl + WV_OFF, nullptr, pvh, pvl, DIM_, 3*DIM_);
    // 4) fused rope(+rmsnorm) + split for q, k
    fused_rrs_kernel<<<(BH_*N_*32 + 255)/256, 256>>>(pq, nullptr, 0, 0, BH_*N_, pqh, pql);
    fused_rrs_kernel<<<(3*BH_*N_*32 + 255)/256, 256>>>(pk, w_key_norms, 1, 1, 3*BH_*N_, pkh, pkl);
    // 5) three inner causal attentions (HMMA); nq,nk fp32; nv pre-split (z=2)
    attn4_kernel<<<dim3(N_/128, BH_, 3), 256, ATTN4_SMEM>>>(pqh, pql, pkh, pkl, pvh, pvl,
                                                            pn, pnh, pnl, 2);
    // 6) fused transforms: nq rope+split, nk rmsnorm+rope+split
    fused_rrs_kernel<<<(BH_*N_*32 + 255)/256, 256>>>(pn, nullptr, 0, 0, BH_*N_, pnh, pnl);
    fused_rrs_kernel<<<(BH_*N_*32 + 255)/256, 256>>>(pn + SLAB_, w_nested_knorm, 1, 0, BH_*N_,
                                                     pnh + SLAB_, pnl + SLAB_);
    // 7) outer causal attention (HMMA) -> g_o fp32
    attn4_kernel<<<dim3(N_/128, BH_, 1), 256, ATTN4_SMEM>>>(pnh, pnl, pnh + SLAB_, pnl + SLAB_,
                                                            pnh + 2*SLAB_, pnl + 2*SLAB_,
                                                            po, nullptr, nullptr, -1);
    // 8) gather+split attention output, then output projection (HMMA)
    oconv_kernel<<<4096, 256>>>(po, poh, pol);
    hgemm_kernel<0><<<dim3(8, 32), 256, HG_SMEM>>>(poh, pol, pwh + WO_OFF, pwl + WO_OFF, out, nullptr, nullptr, DIM_, DIM_);
}

// round 10
// speedup vs baseline: 4.6563x; 1.0188x over previous
#include <cuda_runtime.h>
#include <cuda_bf16.h>
#include <math.h>
#include <stdint.h>

// Problem constants
#define B_  2
#define N_  2048
#define DIM_ 1024
#define H_  16
#define DH_ 64
#define BH_ (B_*H_)            // 32
#define ROWS_ (B_*N_)          // 4096
#define EPS_ 1.1920929e-07f

// ---------------------------------------------------------------------------
// Scratch (allocation-free: __device__ globals)
// ---------------------------------------------------------------------------
__device__ float g_q[(size_t)BH_*N_*DH_];          // (b,h,n,d) fp32
__device__ float g_k[(size_t)3*BH_*N_*DH_];        // (e,b,h,n,d) fp32
__device__ float g_cos[N_*32];
__device__ float g_sin[N_*32];
// bf16 hi/lo splits
__device__ __nv_bfloat16 g_xh[(size_t)ROWS_*DIM_];
__device__ __nv_bfloat16 g_xl[(size_t)ROWS_*DIM_];
__device__ __nv_bfloat16 g_wh[8388608];            // wq|wk|wv|wout
__device__ __nv_bfloat16 g_wl[8388608];
__device__ __nv_bfloat16 g_oh[(size_t)ROWS_*DIM_]; // gathered (bn, hd)
__device__ __nv_bfloat16 g_ol[(size_t)ROWS_*DIM_];
__device__ __nv_bfloat16 g_qh[4194304],  g_ql[4194304];
__device__ __nv_bfloat16 g_kh[12582912], g_kl[12582912];
__device__ __nv_bfloat16 g_vh[12582912], g_vl[12582912];
__device__ __nv_bfloat16 g_nh[12582912], g_nl[12582912];  // nq|nk|nv splits

#define WQ_OFF 0
#define WK_OFF 1048576
#define WV_OFF 4194304
#define WO_OFF 7340032
#define SLAB_ 4194304

// ---------------------------------------------------------------------------
// PTX helpers
// ---------------------------------------------------------------------------
__device__ __forceinline__ uint32_t smem_u32(const void* p) {
    uint32_t a;
    asm("{ .reg .u64 t; cvta.to.shared.u64 t, %1; cvt.u32.u64 %0, t; }" : "=r"(a) : "l"(p));
    return a;
}
__device__ __forceinline__ void ldsm4(uint32_t* r, uint32_t addr) {
    asm volatile("ldmatrix.sync.aligned.m8n8.x4.shared.b16 {%0,%1,%2,%3}, [%4];"
                 : "=r"(r[0]), "=r"(r[1]), "=r"(r[2]), "=r"(r[3]) : "r"(addr));
}
__device__ __forceinline__ void ldsm4t(uint32_t* r, uint32_t addr) {
    asm volatile("ldmatrix.sync.aligned.m8n8.x4.trans.shared.b16 {%0,%1,%2,%3}, [%4];"
                 : "=r"(r[0]), "=r"(r[1]), "=r"(r[2]), "=r"(r[3]) : "r"(addr));
}
__device__ __forceinline__ void mma16816(float* c, const uint32_t* a, const uint32_t* b) {
    asm volatile("mma.sync.aligned.m16n8k16.row.col.f32.bf16.bf16.f32 "
                 "{%0,%1,%2,%3}, {%4,%5,%6,%7}, {%8,%9}, {%0,%1,%2,%3};"
                 : "+f"(c[0]), "+f"(c[1]), "+f"(c[2]), "+f"(c[3])
                 : "r"(a[0]), "r"(a[1]), "r"(a[2]), "r"(a[3]), "r"(b[0]), "r"(b[1]));
}
__device__ __forceinline__ void cpa16(uint32_t saddr, const void* g) {
    asm volatile("cp.async.cg.shared.global [%0], [%1], 16;" :: "r"(saddr), "l"(g));
}
#define CP_COMMIT() asm volatile("cp.async.commit_group;")
#define CP_WAIT1()  asm volatile("cp.async.wait_group 1;")
__device__ __forceinline__ void split1(float f, __nv_bfloat16& h, __nv_bfloat16& l) {
    h = __float2bfloat16(f);
    l = __float2bfloat16(f - __bfloat162float(h));
}
__device__ __forceinline__ uint32_t packbf(float a, float b) {
    __nv_bfloat162 t = __floats2bfloat162_rn(a, b);
    return *reinterpret_cast<uint32_t*>(&t);
}
__device__ __forceinline__ uint32_t pack2(__nv_bfloat16 a, __nv_bfloat16 b) {
    uint32_t r = (uint32_t)*reinterpret_cast<unsigned short*>(&a)
               | ((uint32_t)*reinterpret_cast<unsigned short*>(&b) << 16);
    return r;
}
__device__ __forceinline__ uint32_t splitpack_hi(float a, float b, uint32_t& lo) {
    __nv_bfloat16 ha, la, hb, lb;
    split1(a, ha, la);
    split1(b, hb, lb);
    lo = pack2(la, lb);
    return pack2(ha, hb);
}

// ---------------------------------------------------------------------------
// RMSNorm over DIM=1024 -> bf16 hi/lo splits (one block per row)
// ---------------------------------------------------------------------------
__global__ void rmsnorm_split_kernel(const float* __restrict__ in,
                                     const float* __restrict__ w,
                                     __nv_bfloat16* __restrict__ xh,
                                     __nv_bfloat16* __restrict__ xl) {
    int row = blockIdx.x;
    int i4 = threadIdx.x << 2;
    float4 v = *(const float4*)&in[(size_t)row*DIM_ + i4];
    float s = v.x*v.x + v.y*v.y + v.z*v.z + v.w*v.w;
    __shared__ float sm[8];
    for (int o = 16; o > 0; o >>= 1) s += __shfl_xor_sync(~0u, s, o);
    if ((threadIdx.x & 31) == 0) sm[threadIdx.x >> 5] = s;
    __syncthreads();
    if (threadIdx.x < 8) {
        s = sm[threadIdx.x];
        for (int o = 4; o > 0; o >>= 1) s += __shfl_xor_sync(0xffu, s, o);
        if (threadIdx.x == 0) sm[0] = s;
    }
    __syncthreads();
    float inv = rsqrtf(sm[0] * (1.f/DIM_) + EPS_);
    float4 wv = *(const float4*)&w[i4];
    float f[4] = {v.x*inv*wv.x, v.y*inv*wv.y, v.z*inv*wv.z, v.w*inv*wv.w};
    __nv_bfloat16 h[4], l[4];
    #pragma unroll
    for (int j = 0; j < 4; j++) split1(f[j], h[j], l[j]);
    *(uint2*)&xh[(size_t)row*DIM_ + i4] = *(uint2*)h;
    *(uint2*)&xl[(size_t)row*DIM_ + i4] = *(uint2*)l;
}

// ---------------------------------------------------------------------------
// Elementwise fp32 -> bf16 hi/lo split (weights)
// ---------------------------------------------------------------------------
__global__ void split_kernel(const float* __restrict__ in,
                             __nv_bfloat16* __restrict__ hi,
                             __nv_bfloat16* __restrict__ lo, int n4) {
    int i = blockIdx.x*256 + threadIdx.x;
    if (i >= n4) return;
    float4 v = ((const float4*)in)[i];
    float f[4] = {v.x, v.y, v.z, v.w};
    __nv_bfloat16 h[4], l[4];
    #pragma unroll
    for (int j = 0; j < 4; j++) split1(f[j], h[j], l[j]);
    *(uint2*)&hi[(size_t)i*4] = *(uint2*)h;
    *(uint2*)&lo[(size_t)i*4] = *(uint2*)l;
}

// ---------------------------------------------------------------------------
// Fused (optional rmsnorm_dh) + rope + bf16 split. One warp per row of 64.
// ---------------------------------------------------------------------------
__global__ void fused_rrs_kernel(const float* __restrict__ x, const float* __restrict__ w,
                                 int do_norm, int use_e, int total_rows,
                                 __nv_bfloat16* __restrict__ hi,
                                 __nv_bfloat16* __restrict__ lo) {
    int warp = (blockIdx.x * blockDim.x + threadIdx.x) >> 5;
    if (warp >= total_rows) return;
    int lane = threadIdx.x & 31;
    float2 v = ((const float2*)(x + ((size_t)warp << 6)))[lane];
    if (do_norm) {
        float s = v.x*v.x + v.y*v.y;
        for (int o = 16; o > 0; o >>= 1) s += __shfl_xor_sync(~0u, s, o);
        float inv = rsqrtf(s * (1.f/DH_) + EPS_);
        const float* ww = w + (use_e ? (warp / (BH_*N_)) * DH_ : 0);
        v.x *= inv * ww[2*lane];
        v.y *= inv * ww[2*lane+1];
    }
    int n = warp & (N_-1);
    float c = g_cos[(n<<5) + lane], sn = g_sin[(n<<5) + lane];
    float rx = v.x*c - v.y*sn, ry = v.y*c + v.x*sn;
    __nv_bfloat16 hx, lx, hy, ly;
    split1(rx, hx, lx);
    split1(ry, hy, ly);
    ((uint32_t*)hi)[(warp << 5) + lane] = pack2(hx, hy);
    ((uint32_t*)lo)[(warp << 5) + lane] = pack2(lx, ly);
}

// ---------------------------------------------------------------------------
// RoPE table
// ---------------------------------------------------------------------------
__global__ void rope_table_kernel() {
    int idx = blockIdx.x * blockDim.x + threadIdx.x;
    if (idx >= N_*32) return;
    int n = idx >> 5, t = idx & 31;
    float inv_freq = powf(10000.f, -(2.f * (float)t) / 64.f);
    float ang = (float)n * inv_freq;
    g_cos[idx] = cosf(ang);
    g_sin[idx] = sinf(ang);
}

// ---------------------------------------------------------------------------
// HMMA GEMM: bf16 3-term split, CTA 128x128, 8 warps (2x4),
// 3-stage cp.async pipeline (one __syncthreads per 64-K chunk), ldsm4t for B.
// CMODE: 0 = row-major fp32, 1 = q layout fp32, 2 = kv layout fp32,
//        3 = kv layout bf16 hi/lo split (Ch/Cl)
// Stage layout (bytes): Ah[36864) Al[36864,36864+18432)... offsets 0/18432/36864/54272
// ---------------------------------------------------------------------------
#define HGSTAGE_B 71680
#define HG_SMEM (HGSTAGE_B*3)     // 215040 bytes

template<int CMODE>
__global__ __launch_bounds__(256) void hgemm_kernel(
    const __nv_bfloat16* __restrict__ Ah, const __nv_bfloat16* __restrict__ Al,
    const __nv_bfloat16* __restrict__ Wh, const __nv_bfloat16* __restrict__ Wl,
    float* __restrict__ C, __nv_bfloat16* __restrict__ Ch, __nv_bfloat16* __restrict__ Cl,
    int K, int Nc) {
    extern __shared__ __nv_bfloat16 smb[];
    int tid = threadIdx.x, lane = tid & 31, wid = tid >> 5;
    int wr = wid & 1, wc = wid >> 1;
    int brow = blockIdx.y*128, bcol = blockIdx.x*128;
    uint32_t sbase = smem_u32(smb);

    float acc[4][4][4];
    #pragma unroll
    for (int mi = 0; mi < 4; mi++)
        #pragma unroll
        for (int ni = 0; ni < 4; ni++)
            #pragma unroll
            for (int j = 0; j < 4; j++) acc[mi][ni][j] = 0.f;

    int arow = wr*64 + (lane & 15);
    int acol = (lane >> 4) << 3;
    int brl  = lane & 15;
    int bq8  = (lane >> 4) << 3;

    auto issue = [&](int c, int stg) {
        uint32_t bu = sbase + stg*HGSTAGE_B;
        #pragma unroll
        for (int it = 0; it < 4; it++) {
            int idx = tid + it*256;
            int r = idx >> 3, kc = (idx & 7) << 3;
            size_t ga = (size_t)(brow + r)*K + c*64 + kc;
            cpa16(bu + ((r*72 + kc) << 1),           Ah + ga);
            cpa16(bu + 18432 + ((r*72 + kc) << 1),   Al + ga);
            int kb = idx >> 4, nc2 = (idx & 15) << 3;
            size_t gb = (size_t)(c*64 + kb)*Nc + bcol + nc2;
            cpa16(bu + 36864 + ((kb*136 + nc2) << 1), Wh + gb);
            cpa16(bu + 54272 + ((kb*136 + nc2) << 1), Wl + gb);
        }
        CP_COMMIT();
    };

    int nchunks = K >> 6;
    issue(0, 0);
    if (nchunks > 1) issue(1, 1); else CP_COMMIT();
    for (int c = 0; c < nchunks; c++) {
        CP_WAIT1();
        __syncthreads();
        if (c + 2 < nchunks) issue(c + 2, (c + 2) % 3); else CP_COMMIT();
        uint32_t bu = sbase + (c % 3)*HGSTAGE_B;
        uint32_t sa_h = bu, sa_l = bu + 18432, sb_h = bu + 36864, sb_l = bu + 54272;
        #pragma unroll
        for (int kk = 0; kk < 4; kk++) {
            int k0 = kk << 4;
            uint32_t ah[4][4], al[4][4];
            #pragma unroll
            for (int mi = 0; mi < 4; mi++) {
                uint32_t off = (uint32_t)(((arow + mi*16)*72 + k0 + acol) << 1);
                ldsm4(ah[mi], sa_h + off);
                ldsm4(al[mi], sa_l + off);
            }
            #pragma unroll
            for (int nip = 0; nip < 2; nip++) {
                uint32_t t4h[4], t4l[4];
                uint32_t off = (uint32_t)((((k0 + brl)*136) + wc*32 + nip*16 + bq8) << 1);
                ldsm4t(t4h, sb_h + off);
                ldsm4t(t4l, sb_l + off);
                uint32_t b0h[2] = {t4h[0], t4h[1]}, b1h[2] = {t4h[2], t4h[3]};
                uint32_t b0l[2] = {t4l[0], t4l[1]}, b1l[2] = {t4l[2], t4l[3]};
                #pragma unroll
                for (int mi = 0; mi < 4; mi++) {
                    mma16816(acc[mi][2*nip],   ah[mi], b0h);
                    mma16816(acc[mi][2*nip],   ah[mi], b0l);
                    mma16816(acc[mi][2*nip],   al[mi], b0h);
                    mma16816(acc[mi][2*nip+1], ah[mi], b1h);
                    mma16816(acc[mi][2*nip+1], ah[mi], b1l);
                    mma16816(acc[mi][2*nip+1], al[mi], b1h);
                }
            }
        }
    }

    int g = lane >> 2, t2 = (lane & 3) << 1;
    #pragma unroll
    for (int mi = 0; mi < 4; mi++) {
        int row = brow + wr*64 + mi*16 + g;
        #pragma unroll
        for (int ni = 0; ni < 4; ni++) {
            int col = bcol + wc*32 + ni*8 + t2;
            if (CMODE == 3) {
                int b = row >> 11, n = row & 2047;
                int e = col >> 10, h = (col >> 6) & 15, d = col & 63;
                size_t i0 = (((((size_t)e*B_ + b)*H_ + h)*N_ + n) << 6) + d;
                uint32_t lo0, lo1;
                uint32_t hi0 = splitpack_hi(acc[mi][ni][0], acc[mi][ni][1], lo0);
                uint32_t hi1 = splitpack_hi(acc[mi][ni][2], acc[mi][ni][3], lo1);
                *(uint32_t*)&Ch[i0] = hi0;
                *(uint32_t*)&Cl[i0] = lo0;
                *(uint32_t*)&Ch[i0 + (8 << 6)] = hi1;
                *(uint32_t*)&Cl[i0 + (8 << 6)] = lo1;
            } else {
                float* p0; float* p1;
                if (CMODE == 0) {
                    p0 = &C[(size_t)row * Nc + col];
                    p1 = &C[(size_t)(row+8) * Nc + col];
                } else if (CMODE == 1) {
                    int b = row >> 11, n = row & 2047;
                    int h = col >> 6, d = col & 63;
                    p0 = &C[((((size_t)b*H_ + h)*N_ + n) << 6) + d];
                    p1 = p0 + (8 << 6);
                } else {
                    int b = row >> 11, n = row & 2047;
                    int e = col >> 10, h = (col >> 6) & 15, d = col & 63;
                    p0 = &C[(((((size_t)e*B_ + b)*H_ + h)*N_ + n) << 6) + d];
                    p1 = p0 + (8 << 6);
                }
                *(float2*)p0 = make_float2(acc[mi][ni][0], acc[mi][ni][1]);
                *(float2*)p1 = make_float2(acc[mi][ni][2], acc[mi][ni][3]);
            }
        }
    }
}

// ---------------------------------------------------------------------------
// HMMA causal flash attention v5: 64 q-rows/block, 4 warps (128 thr),
// 3-stage cp.async K/V pipeline (one sync per tile), 2 CTAs/SM.
// S = Qh*Kh + Qh*Kl + Ql*Kh; P bf16 * (Vh + Vl).
// Fused epilogue modes (mode = mode_base + blockIdx.z):
//   0: rope + split (slab layout)      [inner nq]
//   1: rmsnorm + rope + split (slab)   [inner nk]
//   2: plain split (slab)              [inner nv]
//   3: gathered (b*n, h*d) split       [outer output]
// Stage layout (bytes): Kh 0 | Kl 9216 | Vh 18432 | Vl 27648  (36864/stage)
// ---------------------------------------------------------------------------
#define ATT_STAGE_B 36864
#define ATTN5_SMEM (ATT_STAGE_B*3)   // 110592

__global__ __launch_bounds__(128) void attn5_kernel(
    const __nv_bfloat16* __restrict__ Qh, const __nv_bfloat16* __restrict__ Ql,
    const __nv_bfloat16* __restrict__ Kh, const __nv_bfloat16* __restrict__ Kl,
    const __nv_bfloat16* __restrict__ Vh, const __nv_bfloat16* __restrict__ Vl,
    __nv_bfloat16* __restrict__ OH, __nv_bfloat16* __restrict__ OL,
    const float* __restrict__ wnorm, int mode_base) {
    extern __shared__ __nv_bfloat16 smb[];
    int tid = threadIdx.x, lane = tid & 31, w = tid >> 5;   // w in 0..3
    size_t matq = blockIdx.y;
    size_t mat  = blockIdx.y + (size_t)blockIdx.z * BH_;
    const __nv_bfloat16* qh = Qh + (matq << 17);
    const __nv_bfloat16* ql = Ql + (matq << 17);
    const __nv_bfloat16* kh = Kh + (mat << 17);
    const __nv_bfloat16* kl = Kl + (mat << 17);
    const __nv_bfloat16* vh = Vh + (mat << 17);
    const __nv_bfloat16* vl = Vl + (mat << 17);
    int q0 = blockIdx.x * 64;
    uint32_t sbase = smem_u32(smb);

    // Stage Q hi/lo (64 rows) into stage-0 area, lift to registers
    #pragma unroll
    for (int it = 0; it < 4; it++) {
        int idx = tid + it*128;
        int r = idx >> 3, c8 = (idx & 7) << 3;
        *(uint4*)(smb + r*72 + c8)        = *(const uint4*)(qh + ((size_t)(q0 + r) << 6) + c8);
        *(uint4*)(smb + 4608 + r*72 + c8) = *(const uint4*)(ql + ((size_t)(q0 + r) << 6) + c8);
    }
    __syncthreads();
    uint32_t qfh[4][4], qfl[4][4];
    {
        int ar = w*16 + (lane & 15);
        int ac = (lane >> 4) << 3;
        #pragma unroll
        for (int kc = 0; kc < 4; kc++) {
            uint32_t off = (uint32_t)((ar*72 + kc*16 + ac) << 1);
            ldsm4(qfh[kc], sbase + off);
            ldsm4(qfl[kc], sbase + 9216 + off);
        }
    }
    __syncthreads();

    auto issue = [&](int k0, int stg) {
        uint32_t bu = sbase + stg*ATT_STAGE_B;
        #pragma unroll
        for (int it = 0; it < 4; it++) {
            int idx = tid + it*128;
            int r = idx >> 3, c8 = (idx & 7) << 3;
            size_t gi = ((size_t)(k0 + r) << 6) + c8;
            uint32_t so = (uint32_t)((r*72 + c8) << 1);
            cpa16(bu + so,          kh + gi);
            cpa16(bu + 9216  + so,  kl + gi);
            cpa16(bu + 18432 + so,  vh + gi);
            cpa16(bu + 27648 + so,  vl + gi);
        }
        CP_COMMIT();
    };

    float m0 = -INFINITY, m1 = -INFINITY, l0 = 0.f, l1 = 0.f;
    float oa[8][4];
    #pragma unroll
    for (int dt = 0; dt < 8; dt++)
        #pragma unroll
        for (int j = 0; j < 4; j++) oa[dt][j] = 0.f;

    int g = lane >> 2;
    int qr0 = q0 + w*16 + g, qr1 = qr0 + 8;
    int cbase = (lane & 3) << 1;
    int br = lane & 15, bc = (lane >> 4) << 3;

    int nt = blockIdx.x + 1;
    issue(0, 0);
    if (nt > 1) issue(64, 1); else CP_COMMIT();
    for (int t = 0; t < nt; t++) {
        int k0 = t << 6;
        CP_WAIT1();
        __syncthreads();
        if (t + 2 < nt) issue((t + 2) << 6, (t + 2) % 3); else CP_COMMIT();
        uint32_t bu = sbase + (t % 3)*ATT_STAGE_B;
        uint32_t skh_u = bu, skl_u = bu + 9216, svh_u = bu + 18432, svl_u = bu + 27648;

        // --- S phase ---
        float s[8][4];
        #pragma unroll
        for (int ntt = 0; ntt < 8; ntt++)
            #pragma unroll
            for (int j = 0; j < 4; j++) s[ntt][j] = 0.f;
        #pragma unroll
        for (int ntp = 0; ntp < 4; ntp++) {
            #pragma unroll
            for (int kc = 0; kc < 4; kc++) {
                uint32_t r4h[4], r4l[4];
                uint32_t off = (uint32_t)(((ntp*16 + br)*72 + kc*16 + bc) << 1);
                ldsm4(r4h, skh_u + off);
                ldsm4(r4l, skl_u + off);
                uint32_t be[2]  = {r4h[0], r4h[2]}, bo[2]  = {r4h[1], r4h[3]};
                uint32_t bel[2] = {r4l[0], r4l[2]}, bol[2] = {r4l[1], r4l[3]};
                mma16816(s[2*ntp],   qfh[kc], be);
                mma16816(s[2*ntp],   qfh[kc], bel);
                mma16816(s[2*ntp],   qfl[kc], be);
                mma16816(s[2*ntp+1], qfh[kc], bo);
                mma16816(s[2*ntp+1], qfh[kc], bol);
                mma16816(s[2*ntp+1], qfl[kc], bo);
            }
        }

        // --- softmax ---
        if (k0 + 63 > q0) {
            #pragma unroll
            for (int ntt = 0; ntt < 8; ntt++) {
                int key = k0 + ntt*8 + cbase;
                s[ntt][0] = (key   <= qr0) ? s[ntt][0]*0.125f : -INFINITY;
                s[ntt][1] = (key+1 <= qr0) ? s[ntt][1]*0.125f : -INFINITY;
                s[ntt][2] = (key   <= qr1) ? s[ntt][2]*0.125f : -INFINITY;
                s[ntt][3] = (key+1 <= qr1) ? s[ntt][3]*0.125f : -INFINITY;
            }
        } else {
            #pragma unroll
            for (int ntt = 0; ntt < 8; ntt++)
                #pragma unroll
                for (int j = 0; j < 4; j++) s[ntt][j] *= 0.125f;
        }
        float mt0 = m0, mt1 = m1;
        #pragma unroll
        for (int ntt = 0; ntt < 8; ntt++) {
            mt0 = fmaxf(mt0, fmaxf(s[ntt][0], s[ntt][1]));
            mt1 = fmaxf(mt1, fmaxf(s[ntt][2], s[ntt][3]));
        }
        mt0 = fmaxf(mt0, __shfl_xor_sync(~0u, mt0, 1));
        mt0 = fmaxf(mt0, __shfl_xor_sync(~0u, mt0, 2));
        mt1 = fmaxf(mt1, __shfl_xor_sync(~0u, mt1, 1));
        mt1 = fmaxf(mt1, __shfl_xor_sync(~0u, mt1, 2));
        float c0 = __expf(m0 - mt0), c1 = __expf(m1 - mt1);
        m0 = mt0; m1 = mt1;
        float ps0 = 0.f, ps1 = 0.f;
        uint32_t pf[4][4];
        #pragma unroll
        for (int kp = 0; kp < 4; kp++) {
            float p00 = __expf(s[2*kp][0]   - m0), p01 = __expf(s[2*kp][1]   - m0);
            float p10 = __expf(s[2*kp][2]   - m1), p11 = __expf(s[2*kp][3]   - m1);
            float p20 = __expf(s[2*kp+1][0] - m0), p21 = __expf(s[2*kp+1][1] - m0);
            float p30 = __expf(s[2*kp+1][2] - m1), p31 = __expf(s[2*kp+1][3] - m1);
            ps0 += p00 + p01 + p20 + p21;
            ps1 += p10 + p11 + p30 + p31;
            pf[kp][0] = packbf(p00, p01);
            pf[kp][1] = packbf(p10, p11);
            pf[kp][2] = packbf(p20, p21);
            pf[kp][3] = packbf(p30, p31);
        }
        l0 = l0*c0 + ps0;
        l1 = l1*c1 + ps1;
        #pragma unroll
        for (int dt = 0; dt < 8; dt++) {
            oa[dt][0] *= c0; oa[dt][1] *= c0;
            oa[dt][2] *= c1; oa[dt][3] *= c1;
        }

        // --- PV phase ---
        #pragma unroll
        for (int dtp = 0; dtp < 4; dtp++) {
            #pragma unroll
            for (int kc = 0; kc < 4; kc++) {
                uint32_t t4h[4], t4l[4];
                uint32_t off = (uint32_t)(((kc*16 + br)*72 + dtp*16 + bc) << 1);
                ldsm4t(t4h, svh_u + off);
                ldsm4t(t4l, svl_u + off);
                uint32_t b0h[2] = {t4h[0], t4h[1]}, b1h[2] = {t4h[2], t4h[3]};
                uint32_t b0l[2] = {t4l[0], t4l[1]}, b1l[2] = {t4l[2], t4l[3]};
                mma16816(oa[2*dtp],   pf[kc], b0h);
                mma16816(oa[2*dtp],   pf[kc], b0l);
                mma16816(oa[2*dtp+1], pf[kc], b1h);
                mma16816(oa[2*dtp+1], pf[kc], b1l);
            }
        }
    }

    l0 += __shfl_xor_sync(~0u, l0, 1);
    l0 += __shfl_xor_sync(~0u, l0, 2);
    l1 += __shfl_xor_sync(~0u, l1, 1);
    l1 += __shfl_xor_sync(~0u, l1, 2);
    float i0 = 1.f / l0, i1 = 1.f / l1;
    int mode = mode_base + blockIdx.z;

    // Normalize into fp32 values
    float xv[8][4];
    #pragma unroll
    for (int dt = 0; dt < 8; dt++) {
        xv[dt][0] = oa[dt][0]*i0; xv[dt][1] = oa[dt][1]*i0;
        xv[dt][2] = oa[dt][2]*i1; xv[dt][3] = oa[dt][3]*i1;
    }

    if (mode == 1) {
        // rmsnorm over the 64-dim row (4 lanes of the g-group hold the row)
        float s0 = 0.f, s1 = 0.f;
        #pragma unroll
        for (int dt = 0; dt < 8; dt++) {
            s0 += xv[dt][0]*xv[dt][0] + xv[dt][1]*xv[dt][1];
            s1 += xv[dt][2]*xv[dt][2] + xv[dt][3]*xv[dt][3];
        }
        s0 += __shfl_xor_sync(~0u, s0, 1);
        s0 += __shfl_xor_sync(~0u, s0, 2);
        s1 += __shfl_xor_sync(~0u, s1, 1);
        s1 += __shfl_xor_sync(~0u, s1, 2);
        float inv0 = rsqrtf(s0 * (1.f/DH_) + EPS_);
        float inv1 = rsqrtf(s1 * (1.f/DH_) + EPS_);
        #pragma unroll
        for (int dt = 0; dt < 8; dt++) {
            int col = dt*8 + cbase;
            float wa = wnorm[col], wb = wnorm[col+1];
            xv[dt][0] *= inv0*wa; xv[dt][1] *= inv0*wb;
            xv[dt][2] *= inv1*wa; xv[dt][3] *= inv1*wb;
        }
    }
    if (mode <= 1) {
        // rope (pairs are exactly the accumulator column pairs)
        #pragma unroll
        for (int dt = 0; dt < 8; dt++) {
            int tt = dt*4 + (lane & 3);
            float ca = g_cos[(qr0 << 5) + tt], sa = g_sin[(qr0 << 5) + tt];
            float cb = g_cos[(qr1 << 5) + tt], sb = g_sin[(qr1 << 5) + tt];
            float x0 = xv[dt][0], y0 = xv[dt][1];
            float x1 = xv[dt][2], y1 = xv[dt][3];
            xv[dt][0] = x0*ca - y0*sa; xv[dt][1] = y0*ca + x0*sa;
            xv[dt][2] = x1*cb - y1*sb; xv[dt][3] = y1*cb + x1*sb;
        }
    }

    if (mode == 3) {
        int b = (int)(mat >> 4), h = (int)(mat & 15);
        size_t base0 = ((size_t)b*N_ + qr0)*DIM_ + h*64;
        size_t base1 = ((size_t)b*N_ + qr1)*DIM_ + h*64;
        #pragma unroll
        for (int dt = 0; dt < 8; dt++) {
            int col = dt*8 + cbase;
            uint32_t lo0, lo1;
            uint32_t hi0 = splitpack_hi(xv[dt][0], xv[dt][1], lo0);
            uint32_t hi1 = splitpack_hi(xv[dt][2], xv[dt][3], lo1);
            *(uint32_t*)&OH[base0 + col] = hi0;
            *(uint32_t*)&OL[base0 + col] = lo0;
            *(uint32_t*)&OH[base1 + col] = hi1;
            *(uint32_t*)&OL[base1 + col] = lo1;
        }
    } else {
        __nv_bfloat16* oh = OH + (mat << 17);
        __nv_bfloat16* ol = OL + (mat << 17);
        #pragma unroll
        for (int dt = 0; dt < 8; dt++) {
            int col = dt*8 + cbase;
            uint32_t lo0, lo1;
            uint32_t hi0 = splitpack_hi(xv[dt][0], xv[dt][1], lo0);
            uint32_t hi1 = splitpack_hi(xv[dt][2], xv[dt][3], lo1);
            *(uint32_t*)&oh[((size_t)qr0 << 6) + col] = hi0;
            *(uint32_t*)&ol[((size_t)qr0 << 6) + col] = lo0;
            *(uint32_t*)&oh[((size_t)qr1 << 6) + col] = hi1;
            *(uint32_t*)&ol[((size_t)qr1 << 6) + col] = lo1;
        }
    }
}

// ---------------------------------------------------------------------------
// Launch
// ---------------------------------------------------------------------------
extern "C" void kernel_launch(void* const* d_in, const int* in_sizes, int n_in,
                              void* d_out, int out_size) {
    const float* tokens        = (const float*)d_in[0];
    const float* w_norm        = (const float*)d_in[1];
    const float* w_q           = (const float*)d_in[2];
    const float* w_k           = (const float*)d_in[3];
    const float* w_v           = (const float*)d_in[4];
    const float* w_key_norms   = (const float*)d_in[5];
    const float* w_nested_knorm= (const float*)d_in[6];
    const float* w_out         = (const float*)d_in[7];
    float* out = (float*)d_out;

    float *pq, *pk;
    __nv_bfloat16 *pxh, *pxl, *pwh, *pwl, *poh, *pol;
    __nv_bfloat16 *pqh, *pql, *pkh, *pkl, *pvh, *pvl, *pnh, *pnl;
    cudaGetSymbolAddress((void**)&pq, g_q);
    cudaGetSymbolAddress((void**)&pk, g_k);
    cudaGetSymbolAddress((void**)&pxh, g_xh);
    cudaGetSymbolAddress((void**)&pxl, g_xl);
    cudaGetSymbolAddress((void**)&pwh, g_wh);
    cudaGetSymbolAddress((void**)&pwl, g_wl);
    cudaGetSymbolAddress((void**)&poh, g_oh);
    cudaGetSymbolAddress((void**)&pol, g_ol);
    cudaGetSymbolAddress((void**)&pqh, g_qh);
    cudaGetSymbolAddress((void**)&pql, g_ql);
    cudaGetSymbolAddress((void**)&pkh, g_kh);
    cudaGetSymbolAddress((void**)&pkl, g_kl);
    cudaGetSymbolAddress((void**)&pvh, g_vh);
    cudaGetSymbolAddress((void**)&pvl, g_vl);
    cudaGetSymbolAddress((void**)&pnh, g_nh);
    cudaGetSymbolAddress((void**)&pnl, g_nl);

    static int attr_set = 0;
    if (!attr_set) {
        cudaFuncSetAttribute(hgemm_kernel<0>, cudaFuncAttributeMaxDynamicSharedMemorySize, HG_SMEM);
        cudaFuncSetAttribute(hgemm_kernel<1>, cudaFuncAttributeMaxDynamicSharedMemorySize, HG_SMEM);
        cudaFuncSetAttribute(hgemm_kernel<2>, cudaFuncAttributeMaxDynamicSharedMemorySize, HG_SMEM);
        cudaFuncSetAttribute(hgemm_kernel<3>, cudaFuncAttributeMaxDynamicSharedMemorySize, HG_SMEM);
        cudaFuncSetAttribute(attn5_kernel, cudaFuncAttributeMaxDynamicSharedMemorySize, ATTN5_SMEM);
        attr_set = 1;
    }

    // 1) x = rmsnorm(tokens), split to bf16 hi/lo
    rmsnorm_split_kernel<<<ROWS_, 256>>>(tokens, w_norm, pxh, pxl);
    // 2) rope tables + weight splits
    rope_table_kernel<<<(N_*32 + 255)/256, 256>>>();
    split_kernel<<<1024, 256>>>(w_q,   pwh + WQ_OFF, pwl + WQ_OFF, 262144);
    split_kernel<<<3072, 256>>>(w_k,   pwh + WK_OFF, pwl + WK_OFF, 786432);
    split_kernel<<<3072, 256>>>(w_v,   pwh + WV_OFF, pwl + WV_OFF, 786432);
    split_kernel<<<1024, 256>>>(w_out, pwh + WO_OFF, pwl + WO_OFF, 262144);
    // 3) q/k/v projections (HMMA); v written pre-split
    hgemm_kernel<1><<<dim3(8, 32),  256, HG_SMEM>>>(pxh, pxl, pwh + WQ_OFF, pwl + WQ_OFF, pq, nullptr, nullptr, DIM_, DIM_);
    hgemm_kernel<2><<<dim3(24, 32), 256, HG_SMEM>>>(pxh, pxl, pwh + WK_OFF, pwl + WK_OFF, pk, nullptr, nullptr, DIM_, 3*DIM_);
    hgemm_kernel<3><<<dim3(24, 32), 256, HG_SMEM>>>(pxh, pxl, pwh + WV_OFF, pwl + WV_OFF, nullptr, pvh, pvl, DIM_, 3*DIM_);
    // 4) fused rope(+rmsnorm) + split for q, k
    fused_rrs_kernel<<<(BH_*N_*32 + 255)/256, 256>>>(pq, nullptr, 0, 0, BH_*N_, pqh, pql);
    fused_rrs_kernel<<<(3*BH_*N_*32 + 255)/256, 256>>>(pk, w_key_norms, 1, 1, 3*BH_*N_, pkh, pkl);
    // 5) three inner causal attentions; fused epilogues write nq(rope)/nk(rmsnorm+rope)/nv
    //    directly as bf16 hi/lo slabs
    attn5_kernel<<<dim3(N_/64, BH_, 3), 128, ATTN5_SMEM>>>(pqh, pql, pkh, pkl, pvh, pvl,
                                                           pnh, pnl, w_nested_knorm, 0);
    // 6) outer causal attention; fused epilogue writes gathered (b*n, h*d) bf16 split
    attn5_kernel<<<dim3(N_/64, BH_, 1), 128, ATTN5_SMEM>>>(pnh, pnl, pnh + SLAB_, pnl + SLAB_,
                                                           pnh + 2*SLAB_, pnl + 2*SLAB_,
                                                           poh, pol, nullptr, 3);
    // 7) output projection (HMMA)
    hgemm_kernel<0><<<dim3(8, 32), 256, HG_SMEM>>>(poh, pol, pwh + WO_OFF, pwl + WO_OFF, out, nullptr, nullptr, DIM_, DIM_);
}

// round 11
// speedup vs baseline: 5.8587x; 1.2582x over previous
#include <cuda_runtime.h>
#include <cuda_fp16.h>
#include <math.h>
#include <stdint.h>

// Problem constants
#define B_  2
#define N_  2048
#define DIM_ 1024
#define H_  16
#define DH_ 64
#define BH_ (B_*H_)            // 32
#define ROWS_ (B_*N_)          // 4096
#define EPS_ 1.1920929e-07f

// ---------------------------------------------------------------------------
// Scratch (allocation-free: __device__ globals)
// ---------------------------------------------------------------------------
__device__ float g_q[(size_t)BH_*N_*DH_];          // (b,h,n,d) fp32
__device__ float g_k[(size_t)3*BH_*N_*DH_];        // (e,b,h,n,d) fp32
__device__ float g_cos[N_*32];
__device__ float g_sin[N_*32];
// fp16 operands
__device__ __half g_xh[(size_t)ROWS_*DIM_];        // rmsnorm'd tokens (single)
__device__ __half g_wh[8388608];                   // wq|wk|wv|wout hi
__device__ __half g_wl[8388608];                   // lo
__device__ __half g_oh[(size_t)ROWS_*DIM_];        // gathered (bn, hd) single
__device__ __half g_qh[4194304],  g_ql[4194304];
__device__ __half g_kh[12582912], g_kl[12582912];
__device__ __half g_vh[12582912];                  // v single fp16
__device__ __half g_nh[12582912];                  // nq|nk|nv hi (nv single)
__device__ __half g_nl[8388608];                   // nq|nk lo

#define WQ_OFF 0
#define WK_OFF 1048576
#define WV_OFF 4194304
#define WO_OFF 7340032
#define SLAB_ 4194304

// ---------------------------------------------------------------------------
// PTX helpers
// ---------------------------------------------------------------------------
__device__ __forceinline__ uint32_t smem_u32(const void* p) {
    uint32_t a;
    asm("{ .reg .u64 t; cvta.to.shared.u64 t, %1; cvt.u32.u64 %0, t; }" : "=r"(a) : "l"(p));
    return a;
}
__device__ __forceinline__ void ldsm4(uint32_t* r, uint32_t addr) {
    asm volatile("ldmatrix.sync.aligned.m8n8.x4.shared.b16 {%0,%1,%2,%3}, [%4];"
                 : "=r"(r[0]), "=r"(r[1]), "=r"(r[2]), "=r"(r[3]) : "r"(addr));
}
__device__ __forceinline__ void ldsm4t(uint32_t* r, uint32_t addr) {
    asm volatile("ldmatrix.sync.aligned.m8n8.x4.trans.shared.b16 {%0,%1,%2,%3}, [%4];"
                 : "=r"(r[0]), "=r"(r[1]), "=r"(r[2]), "=r"(r[3]) : "r"(addr));
}
__device__ __forceinline__ void mma16816(float* c, const uint32_t* a, const uint32_t* b) {
    asm volatile("mma.sync.aligned.m16n8k16.row.col.f32.f16.f16.f32 "
                 "{%0,%1,%2,%3}, {%4,%5,%6,%7}, {%8,%9}, {%0,%1,%2,%3};"
                 : "+f"(c[0]), "+f"(c[1]), "+f"(c[2]), "+f"(c[3])
                 : "r"(a[0]), "r"(a[1]), "r"(a[2]), "r"(a[3]), "r"(b[0]), "r"(b[1]));
}
__device__ __forceinline__ void cpa16(uint32_t saddr, const void* g) {
    asm volatile("cp.async.cg.shared.global [%0], [%1], 16;" :: "r"(saddr), "l"(g));
}
#define CP_COMMIT() asm volatile("cp.async.commit_group;")
#define CP_WAIT1()  asm volatile("cp.async.wait_group 1;")
__device__ __forceinline__ void split1(float f, __half& h, __half& l) {
    h = __float2half_rn(f);
    l = __float2half_rn(f - __half2float(h));
}
__device__ __forceinline__ uint32_t packhf(float a, float b) {
    __half2 t = __floats2half2_rn(a, b);
    return *reinterpret_cast<uint32_t*>(&t);
}
__device__ __forceinline__ uint32_t pack2(__half a, __half b) {
    return (uint32_t)*reinterpret_cast<unsigned short*>(&a)
         | ((uint32_t)*reinterpret_cast<unsigned short*>(&b) << 16);
}
__device__ __forceinline__ uint32_t splitpack_hi(float a, float b, uint32_t& lo) {
    __half ha, la, hb, lb;
    split1(a, ha, la);
    split1(b, hb, lb);
    lo = pack2(la, lb);
    return pack2(ha, hb);
}

// ---------------------------------------------------------------------------
// RMSNorm over DIM=1024 -> single fp16 (one block per row)
// ---------------------------------------------------------------------------
__global__ void rmsnorm_half_kernel(const float* __restrict__ in,
                                    const float* __restrict__ w,
                                    __half* __restrict__ xh) {
    int row = blockIdx.x;
    int i4 = threadIdx.x << 2;
    float4 v = *(const float4*)&in[(size_t)row*DIM_ + i4];
    float s = v.x*v.x + v.y*v.y + v.z*v.z + v.w*v.w;
    __shared__ float sm[8];
    for (int o = 16; o > 0; o >>= 1) s += __shfl_xor_sync(~0u, s, o);
    if ((threadIdx.x & 31) == 0) sm[threadIdx.x >> 5] = s;
    __syncthreads();
    if (threadIdx.x < 8) {
        s = sm[threadIdx.x];
        for (int o = 4; o > 0; o >>= 1) s += __shfl_xor_sync(0xffu, s, o);
        if (threadIdx.x == 0) sm[0] = s;
    }
    __syncthreads();
    float inv = rsqrtf(sm[0] * (1.f/DIM_) + EPS_);
    float4 wv = *(const float4*)&w[i4];
    uint32_t p0 = packhf(v.x*inv*wv.x, v.y*inv*wv.y);
    uint32_t p1 = packhf(v.z*inv*wv.z, v.w*inv*wv.w);
    *(uint2*)&xh[(size_t)row*DIM_ + i4] = make_uint2(p0, p1);
}

// ---------------------------------------------------------------------------
// Elementwise fp32 -> fp16 hi/lo split (weights)
// ---------------------------------------------------------------------------
__global__ void split_kernel(const float* __restrict__ in,
                             __half* __restrict__ hi,
                             __half* __restrict__ lo, int n4) {
    int i = blockIdx.x*256 + threadIdx.x;
    if (i >= n4) return;
    float4 v = ((const float4*)in)[i];
    float f[4] = {v.x, v.y, v.z, v.w};
    __half h[4], l[4];
    #pragma unroll
    for (int j = 0; j < 4; j++) split1(f[j], h[j], l[j]);
    *(uint2*)&hi[(size_t)i*4] = *(uint2*)h;
    *(uint2*)&lo[(size_t)i*4] = *(uint2*)l;
}

// ---------------------------------------------------------------------------
// Fused (optional rmsnorm_dh) + rope + fp16 split. One warp per row of 64.
// ---------------------------------------------------------------------------
__global__ void fused_rrs_kernel(const float* __restrict__ x, const float* __restrict__ w,
                                 int do_norm, int use_e, int total_rows,
                                 __half* __restrict__ hi,
                                 __half* __restrict__ lo) {
    int warp = (blockIdx.x * blockDim.x + threadIdx.x) >> 5;
    if (warp >= total_rows) return;
    int lane = threadIdx.x & 31;
    float2 v = ((const float2*)(x + ((size_t)warp << 6)))[lane];
    if (do_norm) {
        float s = v.x*v.x + v.y*v.y;
        for (int o = 16; o > 0; o >>= 1) s += __shfl_xor_sync(~0u, s, o);
        float inv = rsqrtf(s * (1.f/DH_) + EPS_);
        const float* ww = w + (use_e ? (warp / (BH_*N_)) * DH_ : 0);
        v.x *= inv * ww[2*lane];
        v.y *= inv * ww[2*lane+1];
    }
    int n = warp & (N_-1);
    float c = g_cos[(n<<5) + lane], sn = g_sin[(n<<5) + lane];
    float rx = v.x*c - v.y*sn, ry = v.y*c + v.x*sn;
    uint32_t lop;
    uint32_t hip = splitpack_hi(rx, ry, lop);
    ((uint32_t*)hi)[(warp << 5) + lane] = hip;
    ((uint32_t*)lo)[(warp << 5) + lane] = lop;
}

// ---------------------------------------------------------------------------
// RoPE table
// ---------------------------------------------------------------------------
__global__ void rope_table_kernel() {
    int idx = blockIdx.x * blockDim.x + threadIdx.x;
    if (idx >= N_*32) return;
    int n = idx >> 5, t = idx & 31;
    float inv_freq = powf(10000.f, -(2.f * (float)t) / 64.f);
    float ang = (float)n * inv_freq;
    g_cos[idx] = cosf(ang);
    g_sin[idx] = sinf(ang);
}

// ---------------------------------------------------------------------------
// HMMA GEMM: fp16, A single + W hi/lo (2-term). CTA 128x128, 8 warps (2x4),
// 3-stage cp.async pipeline, ldsm4t for B.
// CMODE: 0 = row-major fp32, 1 = q layout fp32, 2 = kv layout fp32,
//        3 = kv layout single fp16 (Ch)
// Stage layout (bytes): A[0,18432) Wh[18432,35840) Wl[35840,53248)
// ---------------------------------------------------------------------------
#define HGSTAGE_B 53248
#define HG_SMEM (HGSTAGE_B*3)     // 159744 bytes

template<int CMODE>
__global__ __launch_bounds__(256) void hgemm_kernel(
    const __half* __restrict__ Ah,
    const __half* __restrict__ Wh, const __half* __restrict__ Wl,
    float* __restrict__ C, __half* __restrict__ Ch,
    int K, int Nc) {
    extern __shared__ __half smb[];
    int tid = threadIdx.x, lane = tid & 31, wid = tid >> 5;
    int wr = wid & 1, wc = wid >> 1;
    int brow = blockIdx.y*128, bcol = blockIdx.x*128;
    uint32_t sbase = smem_u32(smb);

    float acc[4][4][4];
    #pragma unroll
    for (int mi = 0; mi < 4; mi++)
        #pragma unroll
        for (int ni = 0; ni < 4; ni++)
            #pragma unroll
            for (int j = 0; j < 4; j++) acc[mi][ni][j] = 0.f;

    int arow = wr*64 + (lane & 15);
    int acol = (lane >> 4) << 3;
    int brl  = lane & 15;
    int bq8  = (lane >> 4) << 3;

    auto issue = [&](int c, int stg) {
        uint32_t bu = sbase + stg*HGSTAGE_B;
        #pragma unroll
        for (int it = 0; it < 4; it++) {
            int idx = tid + it*256;
            int r = idx >> 3, kc = (idx & 7) << 3;
            size_t ga = (size_t)(brow + r)*K + c*64 + kc;
            cpa16(bu + ((r*72 + kc) << 1), Ah + ga);
            int kb = idx >> 4, nc2 = (idx & 15) << 3;
            size_t gb = (size_t)(c*64 + kb)*Nc + bcol + nc2;
            cpa16(bu + 18432 + ((kb*136 + nc2) << 1), Wh + gb);
            cpa16(bu + 35840 + ((kb*136 + nc2) << 1), Wl + gb);
        }
        CP_COMMIT();
    };

    int nchunks = K >> 6;
    issue(0, 0);
    if (nchunks > 1) issue(1, 1); else CP_COMMIT();
    for (int c = 0; c < nchunks; c++) {
        CP_WAIT1();
        __syncthreads();
        if (c + 2 < nchunks) issue(c + 2, (c + 2) % 3); else CP_COMMIT();
        uint32_t bu = sbase + (c % 3)*HGSTAGE_B;
        uint32_t sa = bu, sb_h = bu + 18432, sb_l = bu + 35840;
        #pragma unroll
        for (int kk = 0; kk < 4; kk++) {
            int k0 = kk << 4;
            uint32_t ah[4][4];
            #pragma unroll
            for (int mi = 0; mi < 4; mi++) {
                uint32_t off = (uint32_t)(((arow + mi*16)*72 + k0 + acol) << 1);
                ldsm4(ah[mi], sa + off);
            }
            #pragma unroll
            for (int nip = 0; nip < 2; nip++) {
                uint32_t t4h[4], t4l[4];
                uint32_t off = (uint32_t)((((k0 + brl)*136) + wc*32 + nip*16 + bq8) << 1);
                ldsm4t(t4h, sb_h + off);
                ldsm4t(t4l, sb_l + off);
                uint32_t b0h[2] = {t4h[0], t4h[1]}, b1h[2] = {t4h[2], t4h[3]};
                uint32_t b0l[2] = {t4l[0], t4l[1]}, b1l[2] = {t4l[2], t4l[3]};
                #pragma unroll
                for (int mi = 0; mi < 4; mi++) {
                    mma16816(acc[mi][2*nip],   ah[mi], b0h);
                    mma16816(acc[mi][2*nip],   ah[mi], b0l);
                    mma16816(acc[mi][2*nip+1], ah[mi], b1h);
                    mma16816(acc[mi][2*nip+1], ah[mi], b1l);
                }
            }
        }
    }

    int g = lane >> 2, t2 = (lane & 3) << 1;
    #pragma unroll
    for (int mi = 0; mi < 4; mi++) {
        int row = brow + wr*64 + mi*16 + g;
        #pragma unroll
        for (int ni = 0; ni < 4; ni++) {
            int col = bcol + wc*32 + ni*8 + t2;
            if (CMODE == 3) {
                int b = row >> 11, n = row & 2047;
                int e = col >> 10, h = (col >> 6) & 15, d = col & 63;
                size_t i0 = (((((size_t)e*B_ + b)*H_ + h)*N_ + n) << 6) + d;
                *(uint32_t*)&Ch[i0]            = packhf(acc[mi][ni][0], acc[mi][ni][1]);
                *(uint32_t*)&Ch[i0 + (8 << 6)] = packhf(acc[mi][ni][2], acc[mi][ni][3]);
            } else {
                float* p0; float* p1;
                if (CMODE == 0) {
                    p0 = &C[(size_t)row * Nc + col];
                    p1 = &C[(size_t)(row+8) * Nc + col];
                } else if (CMODE == 1) {
                    int b = row >> 11, n = row & 2047;
                    int h = col >> 6, d = col & 63;
                    p0 = &C[((((size_t)b*H_ + h)*N_ + n) << 6) + d];
                    p1 = p0 + (8 << 6);
                } else {
                    int b = row >> 11, n = row & 2047;
                    int e = col >> 10, h = (col >> 6) & 15, d = col & 63;
                    p0 = &C[(((((size_t)e*B_ + b)*H_ + h)*N_ + n) << 6) + d];
                    p1 = p0 + (8 << 6);
                }
                *(float2*)p0 = make_float2(acc[mi][ni][0], acc[mi][ni][1]);
                *(float2*)p1 = make_float2(acc[mi][ni][2], acc[mi][ni][3]);
            }
        }
    }
}

// ---------------------------------------------------------------------------
// HMMA causal flash attention: 64 q-rows/block, 4 warps (128 thr),
// 3-stage cp.async pipeline, 2 CTAs/SM. fp16 operands.
// S = Qh*Kh + Qh*Kl + Ql*Kh; P fp16 * V (single fp16).
// Fused epilogue modes (mode = mode_base + blockIdx.z):
//   0: rope + split (slab)            [inner nq]  -> OH,OL
//   1: rmsnorm + rope + split (slab)  [inner nk]  -> OH,OL
//   2: plain single fp16 (slab)       [inner nv]  -> OH
//   3: gathered (b*n, h*d) single     [outer out] -> OH
// Stage layout (bytes): Kh 0 | Kl 9216 | V 18432  (27648/stage)
// ---------------------------------------------------------------------------
#define ATT_STAGE_B 27648
#define ATTN5_SMEM (ATT_STAGE_B*3)   // 82944

__global__ __launch_bounds__(128) void attn5_kernel(
    const __half* __restrict__ Qh, const __half* __restrict__ Ql,
    const __half* __restrict__ Kh, const __half* __restrict__ Kl,
    const __half* __restrict__ V,
    __half* __restrict__ OH, __half* __restrict__ OL,
    const float* __restrict__ wnorm, int mode_base) {
    extern __shared__ __half smb[];
    int tid = threadIdx.x, lane = tid & 31, w = tid >> 5;   // w in 0..3
    size_t matq = blockIdx.y;
    size_t mat  = blockIdx.y + (size_t)blockIdx.z * BH_;
    const __half* qh = Qh + (matq << 17);
    const __half* ql = Ql + (matq << 17);
    const __half* kh = Kh + (mat << 17);
    const __half* kl = Kl + (mat << 17);
    const __half* v  = V  + (mat << 17);
    int q0 = blockIdx.x * 64;
    uint32_t sbase = smem_u32(smb);

    // Stage Q hi/lo (64 rows) into stage area, lift to registers
    #pragma unroll
    for (int it = 0; it < 4; it++) {
        int idx = tid + it*128;
        int r = idx >> 3, c8 = (idx & 7) << 3;
        *(uint4*)(smb + r*72 + c8)        = *(const uint4*)(qh + ((size_t)(q0 + r) << 6) + c8);
        *(uint4*)(smb + 4608 + r*72 + c8) = *(const uint4*)(ql + ((size_t)(q0 + r) << 6) + c8);
    }
    __syncthreads();
    uint32_t qfh[4][4], qfl[4][4];
    {
        int ar = w*16 + (lane & 15);
        int ac = (lane >> 4) << 3;
        #pragma unroll
        for (int kc = 0; kc < 4; kc++) {
            uint32_t off = (uint32_t)((ar*72 + kc*16 + ac) << 1);
            ldsm4(qfh[kc], sbase + off);
            ldsm4(qfl[kc], sbase + 9216 + off);
        }
    }
    __syncthreads();

    auto issue = [&](int k0, int stg) {
        uint32_t bu = sbase + stg*ATT_STAGE_B;
        #pragma unroll
        for (int it = 0; it < 4; it++) {
            int idx = tid + it*128;
            int r = idx >> 3, c8 = (idx & 7) << 3;
            size_t gi = ((size_t)(k0 + r) << 6) + c8;
            uint32_t so = (uint32_t)((r*72 + c8) << 1);
            cpa16(bu + so,          kh + gi);
            cpa16(bu + 9216  + so,  kl + gi);
            cpa16(bu + 18432 + so,  v  + gi);
        }
        CP_COMMIT();
    };

    float m0 = -INFINITY, m1 = -INFINITY, l0 = 0.f, l1 = 0.f;
    float oa[8][4];
    #pragma unroll
    for (int dt = 0; dt < 8; dt++)
        #pragma unroll
        for (int j = 0; j < 4; j++) oa[dt][j] = 0.f;

    int g = lane >> 2;
    int qr0 = q0 + w*16 + g, qr1 = qr0 + 8;
    int cbase = (lane & 3) << 1;
    int br = lane & 15, bc = (lane >> 4) << 3;

    int nt = blockIdx.x + 1;
    issue(0, 0);
    if (nt > 1) issue(64, 1); else CP_COMMIT();
    for (int t = 0; t < nt; t++) {
        int k0 = t << 6;
        CP_WAIT1();
        __syncthreads();
        if (t + 2 < nt) issue((t + 2) << 6, (t + 2) % 3); else CP_COMMIT();
        uint32_t bu = sbase + (t % 3)*ATT_STAGE_B;
        uint32_t skh_u = bu, skl_u = bu + 9216, sv_u = bu + 18432;

        // --- S phase ---
        float s[8][4];
        #pragma unroll
        for (int ntt = 0; ntt < 8; ntt++)
            #pragma unroll
            for (int j = 0; j < 4; j++) s[ntt][j] = 0.f;
        #pragma unroll
        for (int ntp = 0; ntp < 4; ntp++) {
            #pragma unroll
            for (int kc = 0; kc < 4; kc++) {
                uint32_t r4h[4], r4l[4];
                uint32_t off = (uint32_t)(((ntp*16 + br)*72 + kc*16 + bc) << 1);
                ldsm4(r4h, skh_u + off);
                ldsm4(r4l, skl_u + off);
                uint32_t be[2]  = {r4h[0], r4h[2]}, bo[2]  = {r4h[1], r4h[3]};
                uint32_t bel[2] = {r4l[0], r4l[2]}, bol[2] = {r4l[1], r4l[3]};
                mma16816(s[2*ntp],   qfh[kc], be);
                mma16816(s[2*ntp],   qfh[kc], bel);
                mma16816(s[2*ntp],   qfl[kc], be);
                mma16816(s[2*ntp+1], qfh[kc], bo);
                mma16816(s[2*ntp+1], qfh[kc], bol);
                mma16816(s[2*ntp+1], qfl[kc], bo);
            }
        }

        // --- softmax ---
        if (k0 + 63 > q0) {
            #pragma unroll
            for (int ntt = 0; ntt < 8; ntt++) {
                int key = k0 + ntt*8 + cbase;
                s[ntt][0] = (key   <= qr0) ? s[ntt][0]*0.125f : -INFINITY;
                s[ntt][1] = (key+1 <= qr0) ? s[ntt][1]*0.125f : -INFINITY;
                s[ntt][2] = (key   <= qr1) ? s[ntt][2]*0.125f : -INFINITY;
                s[ntt][3] = (key+1 <= qr1) ? s[ntt][3]*0.125f : -INFINITY;
            }
        } else {
            #pragma unroll
            for (int ntt = 0; ntt < 8; ntt++)
                #pragma unroll
                for (int j = 0; j < 4; j++) s[ntt][j] *= 0.125f;
        }
        float mt0 = m0, mt1 = m1;
        #pragma unroll
        for (int ntt = 0; ntt < 8; ntt++) {
            mt0 = fmaxf(mt0, fmaxf(s[ntt][0], s[ntt][1]));
            mt1 = fmaxf(mt1, fmaxf(s[ntt][2], s[ntt][3]));
        }
        mt0 = fmaxf(mt0, __shfl_xor_sync(~0u, mt0, 1));
        mt0 = fmaxf(mt0, __shfl_xor_sync(~0u, mt0, 2));
        mt1 = fmaxf(mt1, __shfl_xor_sync(~0u, mt1, 1));
        mt1 = fmaxf(mt1, __shfl_xor_sync(~0u, mt1, 2));
        float c0 = __expf(m0 - mt0), c1 = __expf(m1 - mt1);
        m0 = mt0; m1 = mt1;
        float ps0 = 0.f, ps1 = 0.f;
        uint32_t pf[4][4];
        #pragma unroll
        for (int kp = 0; kp < 4; kp++) {
            float p00 = __expf(s[2*kp][0]   - m0), p01 = __expf(s[2*kp][1]   - m0);
            float p10 = __expf(s[2*kp][2]   - m1), p11 = __expf(s[2*kp][3]   - m1);
            float p20 = __expf(s[2*kp+1][0] - m0), p21 = __expf(s[2*kp+1][1] - m0);
            float p30 = __expf(s[2*kp+1][2] - m1), p31 = __expf(s[2*kp+1][3] - m1);
            ps0 += p00 + p01 + p20 + p21;
            ps1 += p10 + p11 + p30 + p31;
            pf[kp][0] = packhf(p00, p01);
            pf[kp][1] = packhf(p10, p11);
            pf[kp][2] = packhf(p20, p21);
            pf[kp][3] = packhf(p30, p31);
        }
        l0 = l0*c0 + ps0;
        l1 = l1*c1 + ps1;
        #pragma unroll
        for (int dt = 0; dt < 8; dt++) {
            oa[dt][0] *= c0; oa[dt][1] *= c0;
            oa[dt][2] *= c1; oa[dt][3] *= c1;
        }

        // --- PV phase: single-V, 2 MMAs per (dtp,kc) ---
        #pragma unroll
        for (int dtp = 0; dtp < 4; dtp++) {
            #pragma unroll
            for (int kc = 0; kc < 4; kc++) {
                uint32_t t4[4];
                uint32_t off = (uint32_t)(((kc*16 + br)*72 + dtp*16 + bc) << 1);
                ldsm4t(t4, sv_u + off);
                uint32_t b0[2] = {t4[0], t4[1]}, b1[2] = {t4[2], t4[3]};
                mma16816(oa[2*dtp],   pf[kc], b0);
                mma16816(oa[2*dtp+1], pf[kc], b1);
            }
        }
    }

    l0 += __shfl_xor_sync(~0u, l0, 1);
    l0 += __shfl_xor_sync(~0u, l0, 2);
    l1 += __shfl_xor_sync(~0u, l1, 1);
    l1 += __shfl_xor_sync(~0u, l1, 2);
    float i0 = 1.f / l0, i1 = 1.f / l1;
    int mode = mode_base + blockIdx.z;

    float xv[8][4];
    #pragma unroll
    for (int dt = 0; dt < 8; dt++) {
        xv[dt][0] = oa[dt][0]*i0; xv[dt][1] = oa[dt][1]*i0;
        xv[dt][2] = oa[dt][2]*i1; xv[dt][3] = oa[dt][3]*i1;
    }

    if (mode == 1) {
        float s0 = 0.f, s1 = 0.f;
        #pragma unroll
        for (int dt = 0; dt < 8; dt++) {
            s0 += xv[dt][0]*xv[dt][0] + xv[dt][1]*xv[dt][1];
            s1 += xv[dt][2]*xv[dt][2] + xv[dt][3]*xv[dt][3];
        }
        s0 += __shfl_xor_sync(~0u, s0, 1);
        s0 += __shfl_xor_sync(~0u, s0, 2);
        s1 += __shfl_xor_sync(~0u, s1, 1);
        s1 += __shfl_xor_sync(~0u, s1, 2);
        float inv0 = rsqrtf(s0 * (1.f/DH_) + EPS_);
        float inv1 = rsqrtf(s1 * (1.f/DH_) + EPS_);
        #pragma unroll
        for (int dt = 0; dt < 8; dt++) {
            int col = dt*8 + cbase;
            float wa = wnorm[col], wb = wnorm[col+1];
            xv[dt][0] *= inv0*wa; xv[dt][1] *= inv0*wb;
            xv[dt][2] *= inv1*wa; xv[dt][3] *= inv1*wb;
        }
    }
    if (mode <= 1) {
        #pragma unroll
        for (int dt = 0; dt < 8; dt++) {
            int tt = dt*4 + (lane & 3);
            float ca = g_cos[(qr0 << 5) + tt], sa = g_sin[(qr0 << 5) + tt];
            float cb = g_cos[(qr1 << 5) + tt], sb = g_sin[(qr1 << 5) + tt];
            float x0 = xv[dt][0], y0 = xv[dt][1];
            float x1 = xv[dt][2], y1 = xv[dt][3];
            xv[dt][0] = x0*ca - y0*sa; xv[dt][1] = y0*ca + x0*sa;
            xv[dt][2] = x1*cb - y1*sb; xv[dt][3] = y1*cb + x1*sb;
        }
        // hi/lo split outputs (slab layout)
        __half* oh = OH + (mat << 17);
        __half* ol = OL + (mat << 17);
        #pragma unroll
        for (int dt = 0; dt < 8; dt++) {
            int col = dt*8 + cbase;
            uint32_t lo0, lo1;
            uint32_t hi0 = splitpack_hi(xv[dt][0], xv[dt][1], lo0);
            uint32_t hi1 = splitpack_hi(xv[dt][2], xv[dt][3], lo1);
            *(uint32_t*)&oh[((size_t)qr0 << 6) + col] = hi0;
            *(uint32_t*)&ol[((size_t)qr0 << 6) + col] = lo0;
            *(uint32_t*)&oh[((size_t)qr1 << 6) + col] = hi1;
            *(uint32_t*)&ol[((size_t)qr1 << 6) + col] = lo1;
        }
    } else if (mode == 2) {
        __half* oh = OH + (mat << 17);
        #pragma unroll
        for (int dt = 0; dt < 8; dt++) {
            int col = dt*8 + cbase;
            *(uint32_t*)&oh[((size_t)qr0 << 6) + col] = packhf(xv[dt][0], xv[dt][1]);
            *(uint32_t*)&oh[((size_t)qr1 << 6) + col] = packhf(xv[dt][2], xv[dt][3]);
        }
    } else {
        int b = (int)(mat >> 4), h = (int)(mat & 15);
        size_t base0 = ((size_t)b*N_ + qr0)*DIM_ + h*64;
        size_t base1 = ((size_t)b*N_ + qr1)*DIM_ + h*64;
        #pragma unroll
        for (int dt = 0; dt < 8; dt++) {
            int col = dt*8 + cbase;
            *(uint32_t*)&OH[base0 + col] = packhf(xv[dt][0], xv[dt][1]);
            *(uint32_t*)&OH[base1 + col] = packhf(xv[dt][2], xv[dt][3]);
        }
    }
}

// ---------------------------------------------------------------------------
// Launch
// ---------------------------------------------------------------------------
extern "C" void kernel_launch(void* const* d_in, const int* in_sizes, int n_in,
                              void* d_out, int out_size) {
    const float* tokens        = (const float*)d_in[0];
    const float* w_norm        = (const float*)d_in[1];
    const float* w_q           = (const float*)d_in[2];
    const float* w_k           = (const float*)d_in[3];
    const float* w_v           = (const float*)d_in[4];
    const float* w_key_norms   = (const float*)d_in[5];
    const float* w_nested_knorm= (const float*)d_in[6];
    const float* w_out         = (const float*)d_in[7];
    float* out = (float*)d_out;

    float *pq, *pk;
    __half *pxh, *pwh, *pwl, *poh;
    __half *pqh, *pql, *pkh, *pkl, *pvh, *pnh, *pnl;
    cudaGetSymbolAddress((void**)&pq, g_q);
    cudaGetSymbolAddress((void**)&pk, g_k);
    cudaGetSymbolAddress((void**)&pxh, g_xh);
    cudaGetSymbolAddress((void**)&pwh, g_wh);
    cudaGetSymbolAddress((void**)&pwl, g_wl);
    cudaGetSymbolAddress((void**)&poh, g_oh);
    cudaGetSymbolAddress((void**)&pqh, g_qh);
    cudaGetSymbolAddress((void**)&pql, g_ql);
    cudaGetSymbolAddress((void**)&pkh, g_kh);
    cudaGetSymbolAddress((void**)&pkl, g_kl);
    cudaGetSymbolAddress((void**)&pvh, g_vh);
    cudaGetSymbolAddress((void**)&pnh, g_nh);
    cudaGetSymbolAddress((void**)&pnl, g_nl);

    static int attr_set = 0;
    if (!attr_set) {
        cudaFuncSetAttribute(hgemm_kernel<0>, cudaFuncAttributeMaxDynamicSharedMemorySize, HG_SMEM);
        cudaFuncSetAttribute(hgemm_kernel<1>, cudaFuncAttributeMaxDynamicSharedMemorySize, HG_SMEM);
        cudaFuncSetAttribute(hgemm_kernel<2>, cudaFuncAttributeMaxDynamicSharedMemorySize, HG_SMEM);
        cudaFuncSetAttribute(hgemm_kernel<3>, cudaFuncAttributeMaxDynamicSharedMemorySize, HG_SMEM);
        cudaFuncSetAttribute(attn5_kernel, cudaFuncAttributeMaxDynamicSharedMemorySize, ATTN5_SMEM);
        attr_set = 1;
    }

    // 1) x = rmsnorm(tokens) -> single fp16
    rmsnorm_half_kernel<<<ROWS_, 256>>>(tokens, w_norm, pxh);
    // 2) rope tables + weight splits (fp16 hi/lo)
    rope_table_kernel<<<(N_*32 + 255)/256, 256>>>();
    split_kernel<<<1024, 256>>>(w_q,   pwh + WQ_OFF, pwl + WQ_OFF, 262144);
    split_kernel<<<3072, 256>>>(w_k,   pwh + WK_OFF, pwl + WK_OFF, 786432);
    split_kernel<<<3072, 256>>>(w_v,   pwh + WV_OFF, pwl + WV_OFF, 786432);
    split_kernel<<<1024, 256>>>(w_out, pwh + WO_OFF, pwl + WO_OFF, 262144);
    // 3) q/k/v projections (HMMA fp16, 2-term); v written single fp16
    hgemm_kernel<1><<<dim3(8, 32),  256, HG_SMEM>>>(pxh, pwh + WQ_OFF, pwl + WQ_OFF, pq, nullptr, DIM_, DIM_);
    hgemm_kernel<2><<<dim3(24, 32), 256, HG_SMEM>>>(pxh, pwh + WK_OFF, pwl + WK_OFF, pk, nullptr, DIM_, 3*DIM_);
    hgemm_kernel<3><<<dim3(24, 32), 256, HG_SMEM>>>(pxh, pwh + WV_OFF, pwl + WV_OFF, nullptr, pvh, DIM_, 3*DIM_);
    // 4) fused rope(+rmsnorm) + fp16 split for q, k
    fused_rrs_kernel<<<(BH_*N_*32 + 255)/256, 256>>>(pq, nullptr, 0, 0, BH_*N_, pqh, pql);
    fused_rrs_kernel<<<(3*BH_*N_*32 + 255)/256, 256>>>(pk, w_key_norms, 1, 1, 3*BH_*N_, pkh, pkl);
    // 5) three inner causal attentions; fused epilogues write nq/nk (hi/lo) and nv (single)
    attn5_kernel<<<dim3(N_/64, BH_, 3), 128, ATTN5_SMEM>>>(pqh, pql, pkh, pkl, pvh,
                                                           pnh, pnl, w_nested_knorm, 0);
    // 6) outer causal attention; fused epilogue writes gathered (b*n, h*d) single fp16
    attn5_kernel<<<dim3(N_/64, BH_, 1), 128, ATTN5_SMEM>>>(pnh, pnl, pnh + SLAB_, pnl + SLAB_,
                                                           pnh + 2*SLAB_,
                                                           poh, nullptr, nullptr, 3);
    // 7) output projection (HMMA fp16, 2-term)
    hgemm_kernel<0><<<dim3(8, 32), 256, HG_SMEM>>>(poh, pwh + WO_OFF, pwl + WO_OFF, out, nullptr, DIM_, DIM_);
}

// round 12
// speedup vs baseline: 7.2992x; 1.2459x over previous
#include <cuda_runtime.h>
#include <cuda_fp16.h>
#include <math.h>
#include <stdint.h>

// Problem constants
#define B_  2
#define N_  2048
#define DIM_ 1024
#define H_  16
#define DH_ 64
#define BH_ (B_*H_)            // 32
#define ROWS_ (B_*N_)          // 4096
#define EPS_ 1.1920929e-07f

// ---------------------------------------------------------------------------
// Scratch (allocation-free: __device__ globals)
// ---------------------------------------------------------------------------
__device__ float g_q[(size_t)BH_*N_*DH_];          // (b,h,n,d) fp32
__device__ float g_k[(size_t)3*BH_*N_*DH_];        // (e,b,h,n,d) fp32
__device__ float g_cos[N_*32];
__device__ float g_sin[N_*32];
// fp16 operands
__device__ __half g_xh[(size_t)ROWS_*DIM_];        // rmsnorm'd tokens (single)
__device__ __half g_wh[8388608];                   // wq|wk|wv|wout (single fp16)
__device__ __half g_oh[(size_t)ROWS_*DIM_];        // gathered (bn, hd) single
__device__ __half g_qh[4194304],  g_ql[4194304];
__device__ __half g_kh[12582912], g_kl[12582912];
__device__ __half g_vh[12582912];                  // v single fp16
__device__ __half g_nh[12582912];                  // nq|nk|nv hi (nv single)
__device__ __half g_nl[8388608];                   // nq|nk lo

#define WQ_OFF 0
#define WK_OFF 1048576
#define WV_OFF 4194304
#define WO_OFF 7340032
#define SLAB_ 4194304

// ---------------------------------------------------------------------------
// PTX helpers
// ---------------------------------------------------------------------------
__device__ __forceinline__ uint32_t smem_u32(const void* p) {
    uint32_t a;
    asm("{ .reg .u64 t; cvta.to.shared.u64 t, %1; cvt.u32.u64 %0, t; }" : "=r"(a) : "l"(p));
    return a;
}
__device__ __forceinline__ void ldsm4(uint32_t* r, uint32_t addr) {
    asm volatile("ldmatrix.sync.aligned.m8n8.x4.shared.b16 {%0,%1,%2,%3}, [%4];"
                 : "=r"(r[0]), "=r"(r[1]), "=r"(r[2]), "=r"(r[3]) : "r"(addr));
}
__device__ __forceinline__ void ldsm4t(uint32_t* r, uint32_t addr) {
    asm volatile("ldmatrix.sync.aligned.m8n8.x4.trans.shared.b16 {%0,%1,%2,%3}, [%4];"
                 : "=r"(r[0]), "=r"(r[1]), "=r"(r[2]), "=r"(r[3]) : "r"(addr));
}
__device__ __forceinline__ void mma16816(float* c, const uint32_t* a, const uint32_t* b) {
    asm volatile("mma.sync.aligned.m16n8k16.row.col.f32.f16.f16.f32 "
                 "{%0,%1,%2,%3}, {%4,%5,%6,%7}, {%8,%9}, {%0,%1,%2,%3};"
                 : "+f"(c[0]), "+f"(c[1]), "+f"(c[2]), "+f"(c[3])
                 : "r"(a[0]), "r"(a[1]), "r"(a[2]), "r"(a[3]), "r"(b[0]), "r"(b[1]));
}
__device__ __forceinline__ void cpa16(uint32_t saddr, const void* g) {
    asm volatile("cp.async.cg.shared.global [%0], [%1], 16;" :: "r"(saddr), "l"(g));
}
#define CP_COMMIT() asm volatile("cp.async.commit_group;")
#define CP_WAIT1()  asm volatile("cp.async.wait_group 1;")
__device__ __forceinline__ void split1(float f, __half& h, __half& l) {
    h = __float2half_rn(f);
    l = __float2half_rn(f - __half2float(h));
}
__device__ __forceinline__ uint32_t packhf(float a, float b) {
    __half2 t = __floats2half2_rn(a, b);
    return *reinterpret_cast<uint32_t*>(&t);
}
__device__ __forceinline__ uint32_t pack2(__half a, __half b) {
    return (uint32_t)*reinterpret_cast<unsigned short*>(&a)
         | ((uint32_t)*reinterpret_cast<unsigned short*>(&b) << 16);
}
__device__ __forceinline__ uint32_t splitpack_hi(float a, float b, uint32_t& lo) {
    __half ha, la, hb, lb;
    split1(a, ha, la);
    split1(b, hb, lb);
    lo = pack2(la, lb);
    return pack2(ha, hb);
}

// ---------------------------------------------------------------------------
// RMSNorm over DIM=1024 -> single fp16 (one block per row)
// ---------------------------------------------------------------------------
__global__ void rmsnorm_half_kernel(const float* __restrict__ in,
                                    const float* __restrict__ w,
                                    __half* __restrict__ xh) {
    int row = blockIdx.x;
    int i4 = threadIdx.x << 2;
    float4 v = *(const float4*)&in[(size_t)row*DIM_ + i4];
    float s = v.x*v.x + v.y*v.y + v.z*v.z + v.w*v.w;
    __shared__ float sm[8];
    for (int o = 16; o > 0; o >>= 1) s += __shfl_xor_sync(~0u, s, o);
    if ((threadIdx.x & 31) == 0) sm[threadIdx.x >> 5] = s;
    __syncthreads();
    if (threadIdx.x < 8) {
        s = sm[threadIdx.x];
        for (int o = 4; o > 0; o >>= 1) s += __shfl_xor_sync(0xffu, s, o);
        if (threadIdx.x == 0) sm[0] = s;
    }
    __syncthreads();
    float inv = rsqrtf(sm[0] * (1.f/DIM_) + EPS_);
    float4 wv = *(const float4*)&w[i4];
    uint32_t p0 = packhf(v.x*inv*wv.x, v.y*inv*wv.y);
    uint32_t p1 = packhf(v.z*inv*wv.z, v.w*inv*wv.w);
    *(uint2*)&xh[(size_t)row*DIM_ + i4] = make_uint2(p0, p1);
}

// ---------------------------------------------------------------------------
// Elementwise fp32 -> fp16 convert (weights, single precision term)
// ---------------------------------------------------------------------------
__global__ void cvt_kernel(const float* __restrict__ in,
                           __half* __restrict__ out, int n4) {
    int i = blockIdx.x*256 + threadIdx.x;
    if (i >= n4) return;
    float4 v = ((const float4*)in)[i];
    uint32_t p0 = packhf(v.x, v.y);
    uint32_t p1 = packhf(v.z, v.w);
    *(uint2*)&out[(size_t)i*4] = make_uint2(p0, p1);
}

// ---------------------------------------------------------------------------
// Fused (optional rmsnorm_dh) + rope + fp16 split. One warp per row of 64.
// ---------------------------------------------------------------------------
__global__ void fused_rrs_kernel(const float* __restrict__ x, const float* __restrict__ w,
                                 int do_norm, int use_e, int total_rows,
                                 __half* __restrict__ hi,
                                 __half* __restrict__ lo) {
    int warp = (blockIdx.x * blockDim.x + threadIdx.x) >> 5;
    if (warp >= total_rows) return;
    int lane = threadIdx.x & 31;
    float2 v = ((const float2*)(x + ((size_t)warp << 6)))[lane];
    if (do_norm) {
        float s = v.x*v.x + v.y*v.y;
        for (int o = 16; o > 0; o >>= 1) s += __shfl_xor_sync(~0u, s, o);
        float inv = rsqrtf(s * (1.f/DH_) + EPS_);
        const float* ww = w + (use_e ? (warp / (BH_*N_)) * DH_ : 0);
        v.x *= inv * ww[2*lane];
        v.y *= inv * ww[2*lane+1];
    }
    int n = warp & (N_-1);
    float c = g_cos[(n<<5) + lane], sn = g_sin[(n<<5) + lane];
    float rx = v.x*c - v.y*sn, ry = v.y*c + v.x*sn;
    uint32_t lop;
    uint32_t hip = splitpack_hi(rx, ry, lop);
    ((uint32_t*)hi)[(warp << 5) + lane] = hip;
    ((uint32_t*)lo)[(warp << 5) + lane] = lop;
}

// ---------------------------------------------------------------------------
// RoPE table
// ---------------------------------------------------------------------------
__global__ void rope_table_kernel() {
    int idx = blockIdx.x * blockDim.x + threadIdx.x;
    if (idx >= N_*32) return;
    int n = idx >> 5, t = idx & 31;
    float inv_freq = powf(10000.f, -(2.f * (float)t) / 64.f);
    float ang = (float)n * inv_freq;
    g_cos[idx] = cosf(ang);
    g_sin[idx] = sinf(ang);
}

// ---------------------------------------------------------------------------
// HMMA GEMM: single fp16 x single fp16 (1 term). CTA 128x128, 8 warps (2x4),
// 3-stage cp.async pipeline, ldsm4t for B.
// CMODE: 0 = row-major fp32, 1 = q layout fp32, 2 = kv layout fp32,
//        3 = kv layout single fp16 (Ch)
// Stage layout (bytes): A[0,18432) W[18432,35840)
// ---------------------------------------------------------------------------
#define HGSTAGE_B 35840
#define HG_SMEM (HGSTAGE_B*3)     // 107520 bytes

template<int CMODE>
__global__ __launch_bounds__(256) void hgemm_kernel(
    const __half* __restrict__ Ah,
    const __half* __restrict__ Wh,
    float* __restrict__ C, __half* __restrict__ Ch,
    int K, int Nc) {
    extern __shared__ __half smb[];
    int tid = threadIdx.x, lane = tid & 31, wid = tid >> 5;
    int wr = wid & 1, wc = wid >> 1;
    int brow = blockIdx.y*128, bcol = blockIdx.x*128;
    uint32_t sbase = smem_u32(smb);

    float acc[4][4][4];
    #pragma unroll
    for (int mi = 0; mi < 4; mi++)
        #pragma unroll
        for (int ni = 0; ni < 4; ni++)
            #pragma unroll
            for (int j = 0; j < 4; j++) acc[mi][ni][j] = 0.f;

    int arow = wr*64 + (lane & 15);
    int acol = (lane >> 4) << 3;
    int brl  = lane & 15;
    int bq8  = (lane >> 4) << 3;

    auto issue = [&](int c, int stg) {
        uint32_t bu = sbase + stg*HGSTAGE_B;
        #pragma unroll
        for (int it = 0; it < 4; it++) {
            int idx = tid + it*256;
            int r = idx >> 3, kc = (idx & 7) << 3;
            size_t ga = (size_t)(brow + r)*K + c*64 + kc;
            cpa16(bu + ((r*72 + kc) << 1), Ah + ga);
            int kb = idx >> 4, nc2 = (idx & 15) << 3;
            size_t gb = (size_t)(c*64 + kb)*Nc + bcol + nc2;
            cpa16(bu + 18432 + ((kb*136 + nc2) << 1), Wh + gb);
        }
        CP_COMMIT();
    };

    int nchunks = K >> 6;
    issue(0, 0);
    if (nchunks > 1) issue(1, 1); else CP_COMMIT();
    for (int c = 0; c < nchunks; c++) {
        CP_WAIT1();
        __syncthreads();
        if (c + 2 < nchunks) issue(c + 2, (c + 2) % 3); else CP_COMMIT();
        uint32_t bu = sbase + (c % 3)*HGSTAGE_B;
        uint32_t sa = bu, sb_h = bu + 18432;
        #pragma unroll
        for (int kk = 0; kk < 4; kk++) {
            int k0 = kk << 4;
            uint32_t ah[4][4];
            #pragma unroll
            for (int mi = 0; mi < 4; mi++) {
                uint32_t off = (uint32_t)(((arow + mi*16)*72 + k0 + acol) << 1);
                ldsm4(ah[mi], sa + off);
            }
            #pragma unroll
            for (int nip = 0; nip < 2; nip++) {
                uint32_t t4h[4];
                uint32_t off = (uint32_t)((((k0 + brl)*136) + wc*32 + nip*16 + bq8) << 1);
                ldsm4t(t4h, sb_h + off);
                uint32_t b0h[2] = {t4h[0], t4h[1]}, b1h[2] = {t4h[2], t4h[3]};
                #pragma unroll
                for (int mi = 0; mi < 4; mi++) {
                    mma16816(acc[mi][2*nip],   ah[mi], b0h);
                    mma16816(acc[mi][2*nip+1], ah[mi], b1h);
                }
            }
        }
    }

    int g = lane >> 2, t2 = (lane & 3) << 1;
    #pragma unroll
    for (int mi = 0; mi < 4; mi++) {
        int row = brow + wr*64 + mi*16 + g;
        #pragma unroll
        for (int ni = 0; ni < 4; ni++) {
            int col = bcol + wc*32 + ni*8 + t2;
            if (CMODE == 3) {
                int b = row >> 11, n = row & 2047;
                int e = col >> 10, h = (col >> 6) & 15, d = col & 63;
                size_t i0 = (((((size_t)e*B_ + b)*H_ + h)*N_ + n) << 6) + d;
                *(uint32_t*)&Ch[i0]            = packhf(acc[mi][ni][0], acc[mi][ni][1]);
                *(uint32_t*)&Ch[i0 + (8 << 6)] = packhf(acc[mi][ni][2], acc[mi][ni][3]);
            } else {
                float* p0; float* p1;
                if (CMODE == 0) {
                    p0 = &C[(size_t)row * Nc + col];
                    p1 = &C[(size_t)(row+8) * Nc + col];
                } else if (CMODE == 1) {
                    int b = row >> 11, n = row & 2047;
                    int h = col >> 6, d = col & 63;
                    p0 = &C[((((size_t)b*H_ + h)*N_ + n) << 6) + d];
                    p1 = p0 + (8 << 6);
                } else {
                    int b = row >> 11, n = row & 2047;
                    int e = col >> 10, h = (col >> 6) & 15, d = col & 63;
                    p0 = &C[(((((size_t)e*B_ + b)*H_ + h)*N_ + n) << 6) + d];
                    p1 = p0 + (8 << 6);
                }
                *(float2*)p0 = make_float2(acc[mi][ni][0], acc[mi][ni][1]);
                *(float2*)p1 = make_float2(acc[mi][ni][2], acc[mi][ni][3]);
            }
        }
    }
}

// ---------------------------------------------------------------------------
// HMMA causal flash attention: 64 q-rows/block, 4 warps (128 thr),
// 3-stage cp.async pipeline, 2 CTAs/SM. fp16 operands.
// S = Qh*Kh + Qh*Kl + Ql*Kh; P fp16 * V (single fp16).
// Fused epilogue modes (mode = mode_base + blockIdx.z):
//   0: rope + split (slab)            [inner nq]  -> OH,OL
//   1: rmsnorm + rope + split (slab)  [inner nk]  -> OH,OL
//   2: plain single fp16 (slab)       [inner nv]  -> OH
//   3: gathered (b*n, h*d) single     [outer out] -> OH
// Stage layout (bytes): Kh 0 | Kl 9216 | V 18432  (27648/stage)
// ---------------------------------------------------------------------------
#define ATT_STAGE_B 27648
#define ATTN5_SMEM (ATT_STAGE_B*3)   // 82944

__global__ __launch_bounds__(128) void attn5_kernel(
    const __half* __restrict__ Qh, const __half* __restrict__ Ql,
    const __half* __restrict__ Kh, const __half* __restrict__ Kl,
    const __half* __restrict__ V,
    __half* __restrict__ OH, __half* __restrict__ OL,
    const float* __restrict__ wnorm, int mode_base) {
    extern __shared__ __half smb[];
    int tid = threadIdx.x, lane = tid & 31, w = tid >> 5;   // w in 0..3
    size_t matq = blockIdx.y;
    size_t mat  = blockIdx.y + (size_t)blockIdx.z * BH_;
    const __half* qh = Qh + (matq << 17);
    const __half* ql = Ql + (matq << 17);
    const __half* kh = Kh + (mat << 17);
    const __half* kl = Kl + (mat << 17);
    const __half* v  = V  + (mat << 17);
    int q0 = blockIdx.x * 64;
    uint32_t sbase = smem_u32(smb);

    // Stage Q hi/lo (64 rows) into stage area, lift to registers
    #pragma unroll
    for (int it = 0; it < 4; it++) {
        int idx = tid + it*128;
        int r = idx >> 3, c8 = (idx & 7) << 3;
        *(uint4*)(smb + r*72 + c8)        = *(const uint4*)(qh + ((size_t)(q0 + r) << 6) + c8);
        *(uint4*)(smb + 4608 + r*72 + c8) = *(const uint4*)(ql + ((size_t)(q0 + r) << 6) + c8);
    }
    __syncthreads();
    uint32_t qfh[4][4], qfl[4][4];
    {
        int ar = w*16 + (lane & 15);
        int ac = (lane >> 4) << 3;
        #pragma unroll
        for (int kc = 0; kc < 4; kc++) {
            uint32_t off = (uint32_t)((ar*72 + kc*16 + ac) << 1);
            ldsm4(qfh[kc], sbase + off);
            ldsm4(qfl[kc], sbase + 9216 + off);
        }
    }
    __syncthreads();

    auto issue = [&](int k0, int stg) {
        uint32_t bu = sbase + stg*ATT_STAGE_B;
        #pragma unroll
        for (int it = 0; it < 4; it++) {
            int idx = tid + it*128;
            int r = idx >> 3, c8 = (idx & 7) << 3;
            size_t gi = ((size_t)(k0 + r) << 6) + c8;
            uint32_t so = (uint32_t)((r*72 + c8) << 1);
            cpa16(bu + so,          kh + gi);
            cpa16(bu + 9216  + so,  kl + gi);
            cpa16(bu + 18432 + so,  v  + gi);
        }
        CP_COMMIT();
    };

    float m0 = -INFINITY, m1 = -INFINITY, l0 = 0.f, l1 = 0.f;
    float oa[8][4];
    #pragma unroll
    for (int dt = 0; dt < 8; dt++)
        #pragma unroll
        for (int j = 0; j < 4; j++) oa[dt][j] = 0.f;

    int g = lane >> 2;
    int qr0 = q0 + w*16 + g, qr1 = qr0 + 8;
    int cbase = (lane & 3) << 1;
    int br = lane & 15, bc = (lane >> 4) << 3;

    int nt = blockIdx.x + 1;
    issue(0, 0);
    if (nt > 1) issue(64, 1); else CP_COMMIT();
    for (int t = 0; t < nt; t++) {
        int k0 = t << 6;
        CP_WAIT1();
        __syncthreads();
        if (t + 2 < nt) issue((t + 2) << 6, (t + 2) % 3); else CP_COMMIT();
        uint32_t bu = sbase + (t % 3)*ATT_STAGE_B;
        uint32_t skh_u = bu, skl_u = bu + 9216, sv_u = bu + 18432;

        // --- S phase ---
        float s[8][4];
        #pragma unroll
        for (int ntt = 0; ntt < 8; ntt++)
            #pragma unroll
            for (int j = 0; j < 4; j++) s[ntt][j] = 0.f;
        #pragma unroll
        for (int ntp = 0; ntp < 4; ntp++) {
            #pragma unroll
            for (int kc = 0; kc < 4; kc++) {
                uint32_t r4h[4], r4l[4];
                uint32_t off = (uint32_t)(((ntp*16 + br)*72 + kc*16 + bc) << 1);
                ldsm4(r4h, skh_u + off);
                ldsm4(r4l, skl_u + off);
                uint32_t be[2]  = {r4h[0], r4h[2]}, bo[2]  = {r4h[1], r4h[3]};
                uint32_t bel[2] = {r4l[0], r4l[2]}, bol[2] = {r4l[1], r4l[3]};
                mma16816(s[2*ntp],   qfh[kc], be);
                mma16816(s[2*ntp],   qfh[kc], bel);
                mma16816(s[2*ntp],   qfl[kc], be);
                mma16816(s[2*ntp+1], qfh[kc], bo);
                mma16816(s[2*ntp+1], qfh[kc], bol);
                mma16816(s[2*ntp+1], qfl[kc], bo);
            }
        }

        // --- softmax ---
        if (k0 + 63 > q0) {
            #pragma unroll
            for (int ntt = 0; ntt < 8; ntt++) {
                int key = k0 + ntt*8 + cbase;
                s[ntt][0] = (key   <= qr0) ? s[ntt][0]*0.125f : -INFINITY;
                s[ntt][1] = (key+1 <= qr0) ? s[ntt][1]*0.125f : -INFINITY;
                s[ntt][2] = (key   <= qr1) ? s[ntt][2]*0.125f : -INFINITY;
                s[ntt][3] = (key+1 <= qr1) ? s[ntt][3]*0.125f : -INFINITY;
            }
        } else {
            #pragma unroll
            for (int ntt = 0; ntt < 8; ntt++)
                #pragma unroll
                for (int j = 0; j < 4; j++) s[ntt][j] *= 0.125f;
        }
        float mt0 = m0, mt1 = m1;
        #pragma unroll
        for (int ntt = 0; ntt < 8; ntt++) {
            mt0 = fmaxf(mt0, fmaxf(s[ntt][0], s[ntt][1]));
            mt1 = fmaxf(mt1, fmaxf(s[ntt][2], s[ntt][3]));
        }
        mt0 = fmaxf(mt0, __shfl_xor_sync(~0u, mt0, 1));
        mt0 = fmaxf(mt0, __shfl_xor_sync(~0u, mt0, 2));
        mt1 = fmaxf(mt1, __shfl_xor_sync(~0u, mt1, 1));
        mt1 = fmaxf(mt1, __shfl_xor_sync(~0u, mt1, 2));
        float c0 = __expf(m0 - mt0), c1 = __expf(m1 - mt1);
        m0 = mt0; m1 = mt1;
        float ps0 = 0.f, ps1 = 0.f;
        uint32_t pf[4][4];
        #pragma unroll
        for (int kp = 0; kp < 4; kp++) {
            float p00 = __expf(s[2*kp][0]   - m0), p01 = __expf(s[2*kp][1]   - m0);
            float p10 = __expf(s[2*kp][2]   - m1), p11 = __expf(s[2*kp][3]   - m1);
            float p20 = __expf(s[2*kp+1][0] - m0), p21 = __expf(s[2*kp+1][1] - m0);
            float p30 = __expf(s[2*kp+1][2] - m1), p31 = __expf(s[2*kp+1][3] - m1);
            ps0 += p00 + p01 + p20 + p21;
            ps1 += p10 + p11 + p30 + p31;
            pf[kp][0] = packhf(p00, p01);
            pf[kp][1] = packhf(p10, p11);
            pf[kp][2] = packhf(p20, p21);
            pf[kp][3] = packhf(p30, p31);
        }
        l0 = l0*c0 + ps0;
        l1 = l1*c1 + ps1;
        #pragma unroll
        for (int dt = 0; dt < 8; dt++) {
            oa[dt][0] *= c0; oa[dt][1] *= c0;
            oa[dt][2] *= c1; oa[dt][3] *= c1;
        }

        // --- PV phase: single-V, 2 MMAs per (dtp,kc) ---
        #pragma unroll
        for (int dtp = 0; dtp < 4; dtp++) {
            #pragma unroll
            for (int kc = 0; kc < 4; kc++) {
                uint32_t t4[4];
                uint32_t off = (uint32_t)(((kc*16 + br)*72 + dtp*16 + bc) << 1);
                ldsm4t(t4, sv_u + off);
                uint32_t b0[2] = {t4[0], t4[1]}, b1[2] = {t4[2], t4[3]};
                mma16816(oa[2*dtp],   pf[kc], b0);
                mma16816(oa[2*dtp+1], pf[kc], b1);
            }
        }
    }

    l0 += __shfl_xor_sync(~0u, l0, 1);
    l0 += __shfl_xor_sync(~0u, l0, 2);
    l1 += __shfl_xor_sync(~0u, l1, 1);
    l1 += __shfl_xor_sync(~0u, l1, 2);
    float i0 = 1.f / l0, i1 = 1.f / l1;
    int mode = mode_base + blockIdx.z;

    float xv[8][4];
    #pragma unroll
    for (int dt = 0; dt < 8; dt++) {
        xv[dt][0] = oa[dt][0]*i0; xv[dt][1] = oa[dt][1]*i0;
        xv[dt][2] = oa[dt][2]*i1; xv[dt][3] = oa[dt][3]*i1;
    }

    if (mode == 1) {
        float s0 = 0.f, s1 = 0.f;
        #pragma unroll
        for (int dt = 0; dt < 8; dt++) {
            s0 += xv[dt][0]*xv[dt][0] + xv[dt][1]*xv[dt][1];
            s1 += xv[dt][2]*xv[dt][2] + xv[dt][3]*xv[dt][3];
        }
        s0 += __shfl_xor_sync(~0u, s0, 1);
        s0 += __shfl_xor_sync(~0u, s0, 2);
        s1 += __shfl_xor_sync(~0u, s1, 1);
        s1 += __shfl_xor_sync(~0u, s1, 2);
        float inv0 = rsqrtf(s0 * (1.f/DH_) + EPS_);
        float inv1 = rsqrtf(s1 * (1.f/DH_) + EPS_);
        #pragma unroll
        for (int dt = 0; dt < 8; dt++) {
            int col = dt*8 + cbase;
            float wa = wnorm[col], wb = wnorm[col+1];
            xv[dt][0] *= inv0*wa; xv[dt][1] *= inv0*wb;
            xv[dt][2] *= inv1*wa; xv[dt][3] *= inv1*wb;
        }
    }
    if (mode <= 1) {
        #pragma unroll
        for (int dt = 0; dt < 8; dt++) {
            int tt = dt*4 + (lane & 3);
            float ca = g_cos[(qr0 << 5) + tt], sa = g_sin[(qr0 << 5) + tt];
            float cb = g_cos[(qr1 << 5) + tt], sb = g_sin[(qr1 << 5) + tt];
            float x0 = xv[dt][0], y0 = xv[dt][1];
            float x1 = xv[dt][2], y1 = xv[dt][3];
            xv[dt][0] = x0*ca - y0*sa; xv[dt][1] = y0*ca + x0*sa;
            xv[dt][2] = x1*cb - y1*sb; xv[dt][3] = y1*cb + x1*sb;
        }
        __half* oh = OH + (mat << 17);
        __half* ol = OL + (mat << 17);
        #pragma unroll
        for (int dt = 0; dt < 8; dt++) {
            int col = dt*8 + cbase;
            uint32_t lo0, lo1;
            uint32_t hi0 = splitpack_hi(xv[dt][0], xv[dt][1], lo0);
            uint32_t hi1 = splitpack_hi(xv[dt][2], xv[dt][3], lo1);
            *(uint32_t*)&oh[((size_t)qr0 << 6) + col] = hi0;
            *(uint32_t*)&ol[((size_t)qr0 << 6) + col] = lo0;
            *(uint32_t*)&oh[((size_t)qr1 << 6) + col] = hi1;
            *(uint32_t*)&ol[((size_t)qr1 << 6) + col] = lo1;
        }
    } else if (mode == 2) {
        __half* oh = OH + (mat << 17);
        #pragma unroll
        for (int dt = 0; dt < 8; dt++) {
            int col = dt*8 + cbase;
            *(uint32_t*)&oh[((size_t)qr0 << 6) + col] = packhf(xv[dt][0], xv[dt][1]);
            *(uint32_t*)&oh[((size_t)qr1 << 6) + col] = packhf(xv[dt][2], xv[dt][3]);
        }
    } else {
        int b = (int)(mat >> 4), h = (int)(mat & 15);
        size_t base0 = ((size_t)b*N_ + qr0)*DIM_ + h*64;
        size_t base1 = ((size_t)b*N_ + qr1)*DIM_ + h*64;
        #pragma unroll
        for (int dt = 0; dt < 8; dt++) {
            int col = dt*8 + cbase;
            *(uint32_t*)&OH[base0 + col] = packhf(xv[dt][0], xv[dt][1]);
            *(uint32_t*)&OH[base1 + col] = packhf(xv[dt][2], xv[dt][3]);
        }
    }
}

// ---------------------------------------------------------------------------
// Launch
// ---------------------------------------------------------------------------
extern "C" void kernel_launch(void* const* d_in, const int* in_sizes, int n_in,
                              void* d_out, int out_size) {
    const float* tokens        = (const float*)d_in[0];
    const float* w_norm        = (const float*)d_in[1];
    const float* w_q           = (const float*)d_in[2];
    const float* w_k           = (const float*)d_in[3];
    const float* w_v           = (const float*)d_in[4];
    const float* w_key_norms   = (const float*)d_in[5];
    const float* w_nested_knorm= (const float*)d_in[6];
    const float* w_out         = (const float*)d_in[7];
    float* out = (float*)d_out;

    float *pq, *pk;
    __half *pxh, *pwh, *poh;
    __half *pqh, *pql, *pkh, *pkl, *pvh, *pnh, *pnl;
    cudaGetSymbolAddress((void**)&pq, g_q);
    cudaGetSymbolAddress((void**)&pk, g_k);
    cudaGetSymbolAddress((void**)&pxh, g_xh);
    cudaGetSymbolAddress((void**)&pwh, g_wh);
    cudaGetSymbolAddress((void**)&poh, g_oh);
    cudaGetSymbolAddress((void**)&pqh, g_qh);
    cudaGetSymbolAddress((void**)&pql, g_ql);
    cudaGetSymbolAddress((void**)&pkh, g_kh);
    cudaGetSymbolAddress((void**)&pkl, g_kl);
    cudaGetSymbolAddress((void**)&pvh, g_vh);
    cudaGetSymbolAddress((void**)&pnh, g_nh);
    cudaGetSymbolAddress((void**)&pnl, g_nl);

    static int attr_set = 0;
    if (!attr_set) {
        cudaFuncSetAttribute(hgemm_kernel<0>, cudaFuncAttributeMaxDynamicSharedMemorySize, HG_SMEM);
        cudaFuncSetAttribute(hgemm_kernel<1>, cudaFuncAttributeMaxDynamicSharedMemorySize, HG_SMEM);
        cudaFuncSetAttribute(hgemm_kernel<2>, cudaFuncAttributeMaxDynamicSharedMemorySize, HG_SMEM);
        cudaFuncSetAttribute(hgemm_kernel<3>, cudaFuncAttributeMaxDynamicSharedMemorySize, HG_SMEM);
        cudaFuncSetAttribute(attn5_kernel, cudaFuncAttributeMaxDynamicSharedMemorySize, ATTN5_SMEM);
        attr_set = 1;
    }

    // 1) x = rmsnorm(tokens) -> single fp16
    rmsnorm_half_kernel<<<ROWS_, 256>>>(tokens, w_norm, pxh);
    // 2) rope tables + weight converts (single fp16)
    rope_table_kernel<<<(N_*32 + 255)/256, 256>>>();
    cvt_kernel<<<1024, 256>>>(w_q,   pwh + WQ_OFF, 262144);
    cvt_kernel<<<3072, 256>>>(w_k,   pwh + WK_OFF, 786432);
    cvt_kernel<<<3072, 256>>>(w_v,   pwh + WV_OFF, 786432);
    cvt_kernel<<<1024, 256>>>(w_out, pwh + WO_OFF, 262144);
    // 3) q/k/v projections (HMMA fp16, 1-term); v written single fp16
    hgemm_kernel<1><<<dim3(8, 32),  256, HG_SMEM>>>(pxh, pwh + WQ_OFF, pq, nullptr, DIM_, DIM_);
    hgemm_kernel<2><<<dim3(24, 32), 256, HG_SMEM>>>(pxh, pwh + WK_OFF, pk, nullptr, DIM_, 3*DIM_);
    hgemm_kernel<3><<<dim3(24, 32), 256, HG_SMEM>>>(pxh, pwh + WV_OFF, nullptr, pvh, DIM_, 3*DIM_);
    // 4) fused rope(+rmsnorm) + fp16 split for q, k
    fused_rrs_kernel<<<(BH_*N_*32 + 255)/256, 256>>>(pq, nullptr, 0, 0, BH_*N_, pqh, pql);
    fused_rrs_kernel<<<(3*BH_*N_*32 + 255)/256, 256>>>(pk, w_key_norms, 1, 1, 3*BH_*N_, pkh, pkl);
    // 5) three inner causal attentions; fused epilogues write nq/nk (hi/lo) and nv (single)
    attn5_kernel<<<dim3(N_/64, BH_, 3), 128, ATTN5_SMEM>>>(pqh, pql, pkh, pkl, pvh,
                                                           pnh, pnl, w_nested_knorm, 0);
    // 6) outer causal attention; fused epilogue writes gathered (b*n, h*d) single fp16
    attn5_kernel<<<dim3(N_/64, BH_, 1), 128, ATTN5_SMEM>>>(pnh, pnl, pnh + SLAB_, pnl + SLAB_,
                                                           pnh + 2*SLAB_,
                                                           poh, nullptr, nullptr, 3);
    // 7) output projection (HMMA fp16, 1-term)
    hgemm_kernel<0><<<dim3(8, 32), 256, HG_SMEM>>>(poh, pwh + WO_OFF, out, nullptr, DIM_, DIM_);
}

// round 13
// speedup vs baseline: 9.4543x; 1.2953x over previous
#include <cuda_runtime.h>
#include <cuda_fp16.h>
#include <math.h>
#include <stdint.h>

// Problem constants
#define B_  2
#define N_  2048
#define DIM_ 1024
#define H_  16
#define DH_ 64
#define BH_ (B_*H_)            // 32
#define ROWS_ (B_*N_)          // 4096
#define EPS_ 1.1920929e-07f

// ---------------------------------------------------------------------------
// Scratch (allocation-free: __device__ globals)
// ---------------------------------------------------------------------------
__device__ float g_k[(size_t)3*BH_*N_*DH_];        // (e,b,h,n,d) fp32
__device__ float g_cos[N_*32];
__device__ float g_sin[N_*32];
// fp16 operands
__device__ __half g_xh[(size_t)ROWS_*DIM_];        // rmsnorm'd tokens (single)
__device__ __half g_wh[8388608];                   // wq|wk|wv|wout (single fp16)
__device__ __half g_oh[(size_t)ROWS_*DIM_];        // gathered (bn, hd) single
__device__ __half g_qh[4194304],  g_ql[4194304];
__device__ __half g_kh[12582912];                  // k single fp16
__device__ __half g_vh[12582912];                  // v single fp16
__device__ __half g_nh[12582912];                  // nq|nk|nv (nk,nv single)
__device__ __half g_nl[4194304];                   // nq lo

#define WQ_OFF 0
#define WK_OFF 1048576
#define WV_OFF 4194304
#define WO_OFF 7340032
#define SLAB_ 4194304

// ---------------------------------------------------------------------------
// PTX helpers
// ---------------------------------------------------------------------------
__device__ __forceinline__ uint32_t smem_u32(const void* p) {
    uint32_t a;
    asm("{ .reg .u64 t; cvta.to.shared.u64 t, %1; cvt.u32.u64 %0, t; }" : "=r"(a) : "l"(p));
    return a;
}
__device__ __forceinline__ void ldsm4(uint32_t* r, uint32_t addr) {
    asm volatile("ldmatrix.sync.aligned.m8n8.x4.shared.b16 {%0,%1,%2,%3}, [%4];"
                 : "=r"(r[0]), "=r"(r[1]), "=r"(r[2]), "=r"(r[3]) : "r"(addr));
}
__device__ __forceinline__ void ldsm4t(uint32_t* r, uint32_t addr) {
    asm volatile("ldmatrix.sync.aligned.m8n8.x4.trans.shared.b16 {%0,%1,%2,%3}, [%4];"
                 : "=r"(r[0]), "=r"(r[1]), "=r"(r[2]), "=r"(r[3]) : "r"(addr));
}
__device__ __forceinline__ void mma16816(float* c, const uint32_t* a, const uint32_t* b) {
    asm volatile("mma.sync.aligned.m16n8k16.row.col.f32.f16.f16.f32 "
                 "{%0,%1,%2,%3}, {%4,%5,%6,%7}, {%8,%9}, {%0,%1,%2,%3};"
                 : "+f"(c[0]), "+f"(c[1]), "+f"(c[2]), "+f"(c[3])
                 : "r"(a[0]), "r"(a[1]), "r"(a[2]), "r"(a[3]), "r"(b[0]), "r"(b[1]));
}
__device__ __forceinline__ void cpa16(uint32_t saddr, const void* g) {
    asm volatile("cp.async.cg.shared.global [%0], [%1], 16;" :: "r"(saddr), "l"(g));
}
#define CP_COMMIT() asm volatile("cp.async.commit_group;")
#define CP_WAIT1()  asm volatile("cp.async.wait_group 1;")
__device__ __forceinline__ void split1(float f, __half& h, __half& l) {
    h = __float2half_rn(f);
    l = __float2half_rn(f - __half2float(h));
}
__device__ __forceinline__ uint32_t packhf(float a, float b) {
    __half2 t = __floats2half2_rn(a, b);
    return *reinterpret_cast<uint32_t*>(&t);
}
__device__ __forceinline__ uint32_t pack2(__half a, __half b) {
    return (uint32_t)*reinterpret_cast<unsigned short*>(&a)
         | ((uint32_t)*reinterpret_cast<unsigned short*>(&b) << 16);
}
__device__ __forceinline__ uint32_t splitpack_hi(float a, float b, uint32_t& lo) {
    __half ha, la, hb, lb;
    split1(a, ha, la);
    split1(b, hb, lb);
    lo = pack2(la, lb);
    return pack2(ha, hb);
}

// ---------------------------------------------------------------------------
// RMSNorm over DIM=1024 -> single fp16 (one block per row)
// ---------------------------------------------------------------------------
__global__ void rmsnorm_half_kernel(const float* __restrict__ in,
                                    const float* __restrict__ w,
                                    __half* __restrict__ xh) {
    int row = blockIdx.x;
    int i4 = threadIdx.x << 2;
    float4 v = *(const float4*)&in[(size_t)row*DIM_ + i4];
    float s = v.x*v.x + v.y*v.y + v.z*v.z + v.w*v.w;
    __shared__ float sm[8];
    for (int o = 16; o > 0; o >>= 1) s += __shfl_xor_sync(~0u, s, o);
    if ((threadIdx.x & 31) == 0) sm[threadIdx.x >> 5] = s;
    __syncthreads();
    if (threadIdx.x < 8) {
        s = sm[threadIdx.x];
        for (int o = 4; o > 0; o >>= 1) s += __shfl_xor_sync(0xffu, s, o);
        if (threadIdx.x == 0) sm[0] = s;
    }
    __syncthreads();
    float inv = rsqrtf(sm[0] * (1.f/DIM_) + EPS_);
    float4 wv = *(const float4*)&w[i4];
    uint32_t p0 = packhf(v.x*inv*wv.x, v.y*inv*wv.y);
    uint32_t p1 = packhf(v.z*inv*wv.z, v.w*inv*wv.w);
    *(uint2*)&xh[(size_t)row*DIM_ + i4] = make_uint2(p0, p1);
}

// ---------------------------------------------------------------------------
// Elementwise fp32 -> fp16 convert (weights)
// ---------------------------------------------------------------------------
__global__ void cvt_kernel(const float* __restrict__ in,
                           __half* __restrict__ out, int n4) {
    int i = blockIdx.x*256 + threadIdx.x;
    if (i >= n4) return;
    float4 v = ((const float4*)in)[i];
    uint32_t p0 = packhf(v.x, v.y);
    uint32_t p1 = packhf(v.z, v.w);
    *(uint2*)&out[(size_t)i*4] = make_uint2(p0, p1);
}

// ---------------------------------------------------------------------------
// Fused rmsnorm_dh + rope + fp16 (single) for k. One warp per row of 64.
// ---------------------------------------------------------------------------
__global__ void fused_rrs_kernel(const float* __restrict__ x, const float* __restrict__ w,
                                 int use_e, int total_rows,
                                 __half* __restrict__ hi) {
    int warp = (blockIdx.x * blockDim.x + threadIdx.x) >> 5;
    if (warp >= total_rows) return;
    int lane = threadIdx.x & 31;
    float2 v = ((const float2*)(x + ((size_t)warp << 6)))[lane];
    float s = v.x*v.x + v.y*v.y;
    for (int o = 16; o > 0; o >>= 1) s += __shfl_xor_sync(~0u, s, o);
    float inv = rsqrtf(s * (1.f/DH_) + EPS_);
    const float* ww = w + (use_e ? (warp / (BH_*N_)) * DH_ : 0);
    v.x *= inv * ww[2*lane];
    v.y *= inv * ww[2*lane+1];
    int n = warp & (N_-1);
    float c = g_cos[(n<<5) + lane], sn = g_sin[(n<<5) + lane];
    float rx = v.x*c - v.y*sn, ry = v.y*c + v.x*sn;
    ((uint32_t*)hi)[(warp << 5) + lane] = packhf(rx, ry);
}

// ---------------------------------------------------------------------------
// RoPE table
// ---------------------------------------------------------------------------
__global__ void rope_table_kernel() {
    int idx = blockIdx.x * blockDim.x + threadIdx.x;
    if (idx >= N_*32) return;
    int n = idx >> 5, t = idx & 31;
    float inv_freq = powf(10000.f, -(2.f * (float)t) / 64.f);
    float ang = (float)n * inv_freq;
    g_cos[idx] = cosf(ang);
    g_sin[idx] = sinf(ang);
}

// ---------------------------------------------------------------------------
// HMMA GEMM: single fp16 x single fp16. CTA 128x128, 8 warps (2x4),
// 3-stage cp.async pipeline, ldsm4t for B.
// CMODE: 0 = row-major fp32, 2 = kv layout fp32,
//        3 = kv layout single fp16 (Ch),
//        4 = q layout, fused rope + hi/lo fp16 split (Ch/Cl)
// Stage layout (bytes): A[0,18432) W[18432,35840)
// ---------------------------------------------------------------------------
#define HGSTAGE_B 35840
#define HG_SMEM (HGSTAGE_B*3)     // 107520 bytes

template<int CMODE>
__global__ __launch_bounds__(256) void hgemm_kernel(
    const __half* __restrict__ Ah,
    const __half* __restrict__ Wh,
    float* __restrict__ C, __half* __restrict__ Ch, __half* __restrict__ Cl,
    int K, int Nc) {
    extern __shared__ __half smb[];
    int tid = threadIdx.x, lane = tid & 31, wid = tid >> 5;
    int wr = wid & 1, wc = wid >> 1;
    int brow = blockIdx.y*128, bcol = blockIdx.x*128;
    uint32_t sbase = smem_u32(smb);

    float acc[4][4][4];
    #pragma unroll
    for (int mi = 0; mi < 4; mi++)
        #pragma unroll
        for (int ni = 0; ni < 4; ni++)
            #pragma unroll
            for (int j = 0; j < 4; j++) acc[mi][ni][j] = 0.f;

    int arow = wr*64 + (lane & 15);
    int acol = (lane >> 4) << 3;
    int brl  = lane & 15;
    int bq8  = (lane >> 4) << 3;

    auto issue = [&](int c, int stg) {
        uint32_t bu = sbase + stg*HGSTAGE_B;
        #pragma unroll
        for (int it = 0; it < 4; it++) {
            int idx = tid + it*256;
            int r = idx >> 3, kc = (idx & 7) << 3;
            size_t ga = (size_t)(brow + r)*K + c*64 + kc;
            cpa16(bu + ((r*72 + kc) << 1), Ah + ga);
            int kb = idx >> 4, nc2 = (idx & 15) << 3;
            size_t gb = (size_t)(c*64 + kb)*Nc + bcol + nc2;
            cpa16(bu + 18432 + ((kb*136 + nc2) << 1), Wh + gb);
        }
        CP_COMMIT();
    };

    int nchunks = K >> 6;
    issue(0, 0);
    if (nchunks > 1) issue(1, 1); else CP_COMMIT();
    for (int c = 0; c < nchunks; c++) {
        CP_WAIT1();
        __syncthreads();
        if (c + 2 < nchunks) issue(c + 2, (c + 2) % 3); else CP_COMMIT();
        uint32_t bu = sbase + (c % 3)*HGSTAGE_B;
        uint32_t sa = bu, sb_h = bu + 18432;
        #pragma unroll
        for (int kk = 0; kk < 4; kk++) {
            int k0 = kk << 4;
            uint32_t ah[4][4];
            #pragma unroll
            for (int mi = 0; mi < 4; mi++) {
                uint32_t off = (uint32_t)(((arow + mi*16)*72 + k0 + acol) << 1);
                ldsm4(ah[mi], sa + off);
            }
            #pragma unroll
            for (int nip = 0; nip < 2; nip++) {
                uint32_t t4h[4];
                uint32_t off = (uint32_t)((((k0 + brl)*136) + wc*32 + nip*16 + bq8) << 1);
                ldsm4t(t4h, sb_h + off);
                uint32_t b0h[2] = {t4h[0], t4h[1]}, b1h[2] = {t4h[2], t4h[3]};
                #pragma unroll
                for (int mi = 0; mi < 4; mi++) {
                    mma16816(acc[mi][2*nip],   ah[mi], b0h);
                    mma16816(acc[mi][2*nip+1], ah[mi], b1h);
                }
            }
        }
    }

    int g = lane >> 2, t2 = (lane & 3) << 1;
    #pragma unroll
    for (int mi = 0; mi < 4; mi++) {
        int row = brow + wr*64 + mi*16 + g;
        #pragma unroll
        for (int ni = 0; ni < 4; ni++) {
            int col = bcol + wc*32 + ni*8 + t2;
            if (CMODE == 3) {
                int b = row >> 11, n = row & 2047;
                int e = col >> 10, h = (col >> 6) & 15, d = col & 63;
                size_t i0 = (((((size_t)e*B_ + b)*H_ + h)*N_ + n) << 6) + d;
                *(uint32_t*)&Ch[i0]            = packhf(acc[mi][ni][0], acc[mi][ni][1]);
                *(uint32_t*)&Ch[i0 + (8 << 6)] = packhf(acc[mi][ni][2], acc[mi][ni][3]);
            } else if (CMODE == 4) {
                int b = row >> 11, n = row & 2047;
                int h = col >> 6, d = col & 63;
                int tt = d >> 1;
                float ca = g_cos[(n<<5) + tt], sa = g_sin[(n<<5) + tt];
                float cb = g_cos[((n+8)<<5) + tt], sb = g_sin[((n+8)<<5) + tt];
                float x0 = acc[mi][ni][0], y0 = acc[mi][ni][1];
                float x1 = acc[mi][ni][2], y1 = acc[mi][ni][3];
                float r0x = x0*ca - y0*sa, r0y = y0*ca + x0*sa;
                float r1x = x1*cb - y1*sb, r1y = y1*cb + x1*sb;
                size_t i0 = ((((size_t)b*H_ + h)*N_ + n) << 6) + d;
                uint32_t lo0, lo1;
                uint32_t hi0 = splitpack_hi(r0x, r0y, lo0);
                uint32_t hi1 = splitpack_hi(r1x, r1y, lo1);
                *(uint32_t*)&Ch[i0] = hi0;
                *(uint32_t*)&Cl[i0] = lo0;
                *(uint32_t*)&Ch[i0 + (8 << 6)] = hi1;
                *(uint32_t*)&Cl[i0 + (8 << 6)] = lo1;
            } else {
                float* p0; float* p1;
                if (CMODE == 0) {
                    p0 = &C[(size_t)row * Nc + col];
                    p1 = &C[(size_t)(row+8) * Nc + col];
                } else {
                    int b = row >> 11, n = row & 2047;
                    int e = col >> 10, h = (col >> 6) & 15, d = col & 63;
                    p0 = &C[(((((size_t)e*B_ + b)*H_ + h)*N_ + n) << 6) + d];
                    p1 = p0 + (8 << 6);
                }
                *(float2*)p0 = make_float2(acc[mi][ni][0], acc[mi][ni][1]);
                *(float2*)p1 = make_float2(acc[mi][ni][2], acc[mi][ni][3]);
            }
        }
    }
}

// ---------------------------------------------------------------------------
// HMMA causal flash attention: 64 q-rows/block, 4 warps (128 thr),
// 3-stage cp.async pipeline. fp16 operands.
// S = Qh*Kh + Ql*Kh (K single fp16); P fp16 * V (single fp16).
// Fused epilogue modes (mode = mode_base + blockIdx.z):
//   0: rope + hi/lo split (slab)       [inner nq]  -> OH,OL
//   1: rmsnorm + rope + single (slab)  [inner nk]  -> OH
//   2: plain single fp16 (slab)        [inner nv]  -> OH
//   3: gathered (b*n, h*d) single      [outer out] -> OH
// Stage layout (bytes): Kh 0 | V 9216  (18432/stage)
// ---------------------------------------------------------------------------
#define ATT_STAGE_B 18432
#define ATTN5_SMEM (ATT_STAGE_B*3)   // 55296

__global__ __launch_bounds__(128) void attn5_kernel(
    const __half* __restrict__ Qh, const __half* __restrict__ Ql,
    const __half* __restrict__ Kh,
    const __half* __restrict__ V,
    __half* __restrict__ OH, __half* __restrict__ OL,
    const float* __restrict__ wnorm, int mode_base) {
    extern __shared__ __half smb[];
    int tid = threadIdx.x, lane = tid & 31, w = tid >> 5;   // w in 0..3
    size_t matq = blockIdx.y;
    size_t mat  = blockIdx.y + (size_t)blockIdx.z * BH_;
    const __half* qh = Qh + (matq << 17);
    const __half* ql = Ql + (matq << 17);
    const __half* kh = Kh + (mat << 17);
    const __half* v  = V  + (mat << 17);
    int q0 = blockIdx.x * 64;
    uint32_t sbase = smem_u32(smb);

    // Stage Q hi/lo (64 rows) into stage area, lift to registers
    #pragma unroll
    for (int it = 0; it < 4; it++) {
        int idx = tid + it*128;
        int r = idx >> 3, c8 = (idx & 7) << 3;
        *(uint4*)(smb + r*72 + c8)        = *(const uint4*)(qh + ((size_t)(q0 + r) << 6) + c8);
        *(uint4*)(smb + 4608 + r*72 + c8) = *(const uint4*)(ql + ((size_t)(q0 + r) << 6) + c8);
    }
    __syncthreads();
    uint32_t qfh[4][4], qfl[4][4];
    {
        int ar = w*16 + (lane & 15);
        int ac = (lane >> 4) << 3;
        #pragma unroll
        for (int kc = 0; kc < 4; kc++) {
            uint32_t off = (uint32_t)((ar*72 + kc*16 + ac) << 1);
            ldsm4(qfh[kc], sbase + off);
            ldsm4(qfl[kc], sbase + 9216 + off);
        }
    }
    __syncthreads();

    auto issue = [&](int k0, int stg) {
        uint32_t bu = sbase + stg*ATT_STAGE_B;
        #pragma unroll
        for (int it = 0; it < 4; it++) {
            int idx = tid + it*128;
            int r = idx >> 3, c8 = (idx & 7) << 3;
            size_t gi = ((size_t)(k0 + r) << 6) + c8;
            uint32_t so = (uint32_t)((r*72 + c8) << 1);
            cpa16(bu + so,         kh + gi);
            cpa16(bu + 9216 + so,  v  + gi);
        }
        CP_COMMIT();
    };

    float m0 = -INFINITY, m1 = -INFINITY, l0 = 0.f, l1 = 0.f;
    float oa[8][4];
    #pragma unroll
    for (int dt = 0; dt < 8; dt++)
        #pragma unroll
        for (int j = 0; j < 4; j++) oa[dt][j] = 0.f;

    int g = lane >> 2;
    int qr0 = q0 + w*16 + g, qr1 = qr0 + 8;
    int cbase = (lane & 3) << 1;
    int br = lane & 15, bc = (lane >> 4) << 3;

    int nt = blockIdx.x + 1;
    issue(0, 0);
    if (nt > 1) issue(64, 1); else CP_COMMIT();
    for (int t = 0; t < nt; t++) {
        int k0 = t << 6;
        CP_WAIT1();
        __syncthreads();
        if (t + 2 < nt) issue((t + 2) << 6, (t + 2) % 3); else CP_COMMIT();
        uint32_t bu = sbase + (t % 3)*ATT_STAGE_B;
        uint32_t skh_u = bu, sv_u = bu + 9216;

        // --- S phase: 2-term (Qh + Ql) x Kh ---
        float s[8][4];
        #pragma unroll
        for (int ntt = 0; ntt < 8; ntt++)
            #pragma unroll
            for (int j = 0; j < 4; j++) s[ntt][j] = 0.f;
        #pragma unroll
        for (int ntp = 0; ntp < 4; ntp++) {
            #pragma unroll
            for (int kc = 0; kc < 4; kc++) {
                uint32_t r4h[4];
                uint32_t off = (uint32_t)(((ntp*16 + br)*72 + kc*16 + bc) << 1);
                ldsm4(r4h, skh_u + off);
                uint32_t be[2] = {r4h[0], r4h[2]}, bo[2] = {r4h[1], r4h[3]};
                mma16816(s[2*ntp],   qfh[kc], be);
                mma16816(s[2*ntp],   qfl[kc], be);
                mma16816(s[2*ntp+1], qfh[kc], bo);
                mma16816(s[2*ntp+1], qfl[kc], bo);
            }
        }

        // --- softmax ---
        if (k0 + 63 > q0) {
            #pragma unroll
            for (int ntt = 0; ntt < 8; ntt++) {
                int key = k0 + ntt*8 + cbase;
                s[ntt][0] = (key   <= qr0) ? s[ntt][0]*0.125f : -INFINITY;
                s[ntt][1] = (key+1 <= qr0) ? s[ntt][1]*0.125f : -INFINITY;
                s[ntt][2] = (key   <= qr1) ? s[ntt][2]*0.125f : -INFINITY;
                s[ntt][3] = (key+1 <= qr1) ? s[ntt][3]*0.125f : -INFINITY;
            }
        } else {
            #pragma unroll
            for (int ntt = 0; ntt < 8; ntt++)
                #pragma unroll
                for (int j = 0; j < 4; j++) s[ntt][j] *= 0.125f;
        }
        float mt0 = m0, mt1 = m1;
        #pragma unroll
        for (int ntt = 0; ntt < 8; ntt++) {
            mt0 = fmaxf(mt0, fmaxf(s[ntt][0], s[ntt][1]));
            mt1 = fmaxf(mt1, fmaxf(s[ntt][2], s[ntt][3]));
        }
        mt0 = fmaxf(mt0, __shfl_xor_sync(~0u, mt0, 1));
        mt0 = fmaxf(mt0, __shfl_xor_sync(~0u, mt0, 2));
        mt1 = fmaxf(mt1, __shfl_xor_sync(~0u, mt1, 1));
        mt1 = fmaxf(mt1, __shfl_xor_sync(~0u, mt1, 2));
        float c0 = __expf(m0 - mt0), c1 = __expf(m1 - mt1);
        m0 = mt0; m1 = mt1;
        float ps0 = 0.f, ps1 = 0.f;
        uint32_t pf[4][4];
        #pragma unroll
        for (int kp = 0; kp < 4; kp++) {
            float p00 = __expf(s[2*kp][0]   - m0), p01 = __expf(s[2*kp][1]   - m0);
            float p10 = __expf(s[2*kp][2]   - m1), p11 = __expf(s[2*kp][3]   - m1);
            float p20 = __expf(s[2*kp+1][0] - m0), p21 = __expf(s[2*kp+1][1] - m0);
            float p30 = __expf(s[2*kp+1][2] - m1), p31 = __expf(s[2*kp+1][3] - m1);
            ps0 += p00 + p01 + p20 + p21;
            ps1 += p10 + p11 + p30 + p31;
            pf[kp][0] = packhf(p00, p01);
            pf[kp][1] = packhf(p10, p11);
            pf[kp][2] = packhf(p20, p21);
            pf[kp][3] = packhf(p30, p31);
        }
        l0 = l0*c0 + ps0;
        l1 = l1*c1 + ps1;
        #pragma unroll
        for (int dt = 0; dt < 8; dt++) {
            oa[dt][0] *= c0; oa[dt][1] *= c0;
            oa[dt][2] *= c1; oa[dt][3] *= c1;
        }

        // --- PV phase: single-V ---
        #pragma unroll
        for (int dtp = 0; dtp < 4; dtp++) {
            #pragma unroll
            for (int kc = 0; kc < 4; kc++) {
                uint32_t t4[4];
                uint32_t off = (uint32_t)(((kc*16 + br)*72 + dtp*16 + bc) << 1);
                ldsm4t(t4, sv_u + off);
                uint32_t b0[2] = {t4[0], t4[1]}, b1[2] = {t4[2], t4[3]};
                mma16816(oa[2*dtp],   pf[kc], b0);
                mma16816(oa[2*dtp+1], pf[kc], b1);
            }
        }
    }

    l0 += __shfl_xor_sync(~0u, l0, 1);
    l0 += __shfl_xor_sync(~0u, l0, 2);
    l1 += __shfl_xor_sync(~0u, l1, 1);
    l1 += __shfl_xor_sync(~0u, l1, 2);
    float i0 = 1.f / l0, i1 = 1.f / l1;
    int mode = mode_base + blockIdx.z;

    float xv[8][4];
    #pragma unroll
    for (int dt = 0; dt < 8; dt++) {
        xv[dt][0] = oa[dt][0]*i0; xv[dt][1] = oa[dt][1]*i0;
        xv[dt][2] = oa[dt][2]*i1; xv[dt][3] = oa[dt][3]*i1;
    }

    if (mode == 1) {
        float s0 = 0.f, s1 = 0.f;
        #pragma unroll
        for (int dt = 0; dt < 8; dt++) {
            s0 += xv[dt][0]*xv[dt][0] + xv[dt][1]*xv[dt][1];
            s1 += xv[dt][2]*xv[dt][2] + xv[dt][3]*xv[dt][3];
        }
        s0 += __shfl_xor_sync(~0u, s0, 1);
        s0 += __shfl_xor_sync(~0u, s0, 2);
        s1 += __shfl_xor_sync(~0u, s1, 1);
        s1 += __shfl_xor_sync(~0u, s1, 2);
        float inv0 = rsqrtf(s0 * (1.f/DH_) + EPS_);
        float inv1 = rsqrtf(s1 * (1.f/DH_) + EPS_);
        #pragma unroll
        for (int dt = 0; dt < 8; dt++) {
            int col = dt*8 + cbase;
            float wa = wnorm[col], wb = wnorm[col+1];
            xv[dt][0] *= inv0*wa; xv[dt][1] *= inv0*wb;
            xv[dt][2] *= inv1*wa; xv[dt][3] *= inv1*wb;
        }
    }
    if (mode <= 1) {
        #pragma unroll
        for (int dt = 0; dt < 8; dt++) {
            int tt = dt*4 + (lane & 3);
            float ca = g_cos[(qr0 << 5) + tt], sa = g_sin[(qr0 << 5) + tt];
            float cb = g_cos[(qr1 << 5) + tt], sb = g_sin[(qr1 << 5) + tt];
            float x0 = xv[dt][0], y0 = xv[dt][1];
            float x1 = xv[dt][2], y1 = xv[dt][3];
            xv[dt][0] = x0*ca - y0*sa; xv[dt][1] = y0*ca + x0*sa;
            xv[dt][2] = x1*cb - y1*sb; xv[dt][3] = y1*cb + x1*sb;
        }
    }

    if (mode == 0) {
        // hi/lo split outputs (slab layout) — nq
        __half* oh = OH + (mat << 17);
        __half* ol = OL + (mat << 17);
        #pragma unroll
        for (int dt = 0; dt < 8; dt++) {
            int col = dt*8 + cbase;
            uint32_t lo0, lo1;
            uint32_t hi0 = splitpack_hi(xv[dt][0], xv[dt][1], lo0);
            uint32_t hi1 = splitpack_hi(xv[dt][2], xv[dt][3], lo1);
            *(uint32_t*)&oh[((size_t)qr0 << 6) + col] = hi0;
            *(uint32_t*)&ol[((size_t)qr0 << 6) + col] = lo0;
            *(uint32_t*)&oh[((size_t)qr1 << 6) + col] = hi1;
            *(uint32_t*)&ol[((size_t)qr1 << 6) + col] = lo1;
        }
    } else if (mode <= 2) {
        // single fp16 slab — nk (mode 1, post-transform) / nv (mode 2)
        __half* oh = OH + (mat << 17);
        #pragma unroll
        for (int dt = 0; dt < 8; dt++) {
            int col = dt*8 + cbase;
            *(uint32_t*)&oh[((size_t)qr0 << 6) + col] = packhf(xv[dt][0], xv[dt][1]);
            *(uint32_t*)&oh[((size_t)qr1 << 6) + col] = packhf(xv[dt][2], xv[dt][3]);
        }
    } else {
        int b = (int)(mat >> 4), h = (int)(mat & 15);
        size_t base0 = ((size_t)b*N_ + qr0)*DIM_ + h*64;
        size_t base1 = ((size_t)b*N_ + qr1)*DIM_ + h*64;
        #pragma unroll
        for (int dt = 0; dt < 8; dt++) {
            int col = dt*8 + cbase;
            *(uint32_t*)&OH[base0 + col] = packhf(xv[dt][0], xv[dt][1]);
            *(uint32_t*)&OH[base1 + col] = packhf(xv[dt][2], xv[dt][3]);
        }
    }
}

// ---------------------------------------------------------------------------
// Launch
// ---------------------------------------------------------------------------
extern "C" void kernel_launch(void* const* d_in, const int* in_sizes, int n_in,
                              void* d_out, int out_size) {
    const float* tokens        = (const float*)d_in[0];
    const float* w_norm        = (const float*)d_in[1];
    const float* w_q           = (const float*)d_in[2];
    const float* w_k           = (const float*)d_in[3];
    const float* w_v           = (const float*)d_in[4];
    const float* w_key_norms   = (const float*)d_in[5];
    const float* w_nested_knorm= (const float*)d_in[6];
    const float* w_out         = (const float*)d_in[7];
    float* out = (float*)d_out;

    float *pk;
    __half *pxh, *pwh, *poh;
    __half *pqh, *pql, *pkh, *pvh, *pnh, *pnl;
    cudaGetSymbolAddress((void**)&pk, g_k);
    cudaGetSymbolAddress((void**)&pxh, g_xh);
    cudaGetSymbolAddress((void**)&pwh, g_wh);
    cudaGetSymbolAddress((void**)&poh, g_oh);
    cudaGetSymbolAddress((void**)&pqh, g_qh);
    cudaGetSymbolAddress((void**)&pql, g_ql);
    cudaGetSymbolAddress((void**)&pkh, g_kh);
    cudaGetSymbolAddress((void**)&pvh, g_vh);
    cudaGetSymbolAddress((void**)&pnh, g_nh);
    cudaGetSymbolAddress((void**)&pnl, g_nl);

    static int attr_set = 0;
    if (!attr_set) {
        cudaFuncSetAttribute(hgemm_kernel<0>, cudaFuncAttributeMaxDynamicSharedMemorySize, HG_SMEM);
        cudaFuncSetAttribute(hgemm_kernel<2>, cudaFuncAttributeMaxDynamicSharedMemorySize, HG_SMEM);
        cudaFuncSetAttribute(hgemm_kernel<3>, cudaFuncAttributeMaxDynamicSharedMemorySize, HG_SMEM);
        cudaFuncSetAttribute(hgemm_kernel<4>, cudaFuncAttributeMaxDynamicSharedMemorySize, HG_SMEM);
        cudaFuncSetAttribute(attn5_kernel, cudaFuncAttributeMaxDynamicSharedMemorySize, ATTN5_SMEM);
        attr_set = 1;
    }

    // 1) x = rmsnorm(tokens) -> single fp16
    rmsnorm_half_kernel<<<ROWS_, 256>>>(tokens, w_norm, pxh);
    // 2) rope tables + weight converts (single fp16)
    rope_table_kernel<<<(N_*32 + 255)/256, 256>>>();
    cvt_kernel<<<1024, 256>>>(w_q,   pwh + WQ_OFF, 262144);
    cvt_kernel<<<3072, 256>>>(w_k,   pwh + WK_OFF, 786432);
    cvt_kernel<<<3072, 256>>>(w_v,   pwh + WV_OFF, 786432);
    cvt_kernel<<<1024, 256>>>(w_out, pwh + WO_OFF, 262144);
    // 3) projections (HMMA fp16):
    //    q: fused rope + hi/lo split epilogue (no fp32 round trip)
    //    k: fp32 (rmsnorm+rope follow), v: single fp16 direct
    hgemm_kernel<4><<<dim3(8, 32),  256, HG_SMEM>>>(pxh, pwh + WQ_OFF, nullptr, pqh, pql, DIM_, DIM_);
    hgemm_kernel<2><<<dim3(24, 32), 256, HG_SMEM>>>(pxh, pwh + WK_OFF, pk, nullptr, nullptr, DIM_, 3*DIM_);
    hgemm_kernel<3><<<dim3(24, 32), 256, HG_SMEM>>>(pxh, pwh + WV_OFF, nullptr, pvh, nullptr, DIM_, 3*DIM_);
    // 4) fused rmsnorm + rope + fp16 (single) for k
    fused_rrs_kernel<<<(3*BH_*N_*32 + 255)/256, 256>>>(pk, w_key_norms, 1, 3*BH_*N_, pkh);
    // 5) three inner causal attentions; epilogues: nq hi/lo+rope, nk single+rmsnorm+rope, nv single
    attn5_kernel<<<dim3(N_/64, BH_, 3), 128, ATTN5_SMEM>>>(pqh, pql, pkh, pvh,
                                                           pnh, pnl, w_nested_knorm, 0);
    // 6) outer causal attention; epilogue writes gathered (b*n, h*d) single fp16
    attn5_kernel<<<dim3(N_/64, BH_, 1), 128, ATTN5_SMEM>>>(pnh, pnl, pnh + SLAB_,
                                                           pnh + 2*SLAB_,
                                                           poh, nullptr, nullptr, 3);
    // 7) output projection (HMMA fp16)
    hgemm_kernel<0><<<dim3(8, 32), 256, HG_SMEM>>>(poh, pwh + WO_OFF, out, nullptr, nullptr, DIM_, DIM_);
}

// round 14
// speedup vs baseline: 10.4683x; 1.1073x over previous
#include <cuda_runtime.h>
#include <cuda_fp16.h>
#include <math.h>
#include <stdint.h>

// Problem constants
#define B_  2
#define N_  2048
#define DIM_ 1024
#define H_  16
#define DH_ 64
#define BH_ (B_*H_)            // 32
#define ROWS_ (B_*N_)          // 4096
#define EPS_ 1.1920929e-07f

// ---------------------------------------------------------------------------
// Scratch (allocation-free: __device__ globals)
// ---------------------------------------------------------------------------
__device__ float g_k[(size_t)3*BH_*N_*DH_];        // (e,b,h,n,d) fp32
__device__ float g_cos[N_*32];
__device__ float g_sin[N_*32];
// fp16 operands
__device__ __half g_xh[(size_t)ROWS_*DIM_];        // rmsnorm'd tokens (single)
__device__ __half g_wh[8388608];                   // wq|wk|wv|wout (single fp16)
__device__ __half g_oh[(size_t)ROWS_*DIM_];        // gathered (bn, hd) single
__device__ __half g_qh[4194304];                   // q single fp16 (rope'd)
__device__ __half g_kh[12582912];                  // k single fp16
__device__ __half g_vh[12582912];                  // v single fp16
__device__ __half g_nh[12582912];                  // nq|nk|nv single fp16

#define WQ_OFF 0
#define WK_OFF 1048576
#define WV_OFF 4194304
#define WO_OFF 7340032
#define SLAB_ 4194304

// ---------------------------------------------------------------------------
// PTX helpers
// ---------------------------------------------------------------------------
__device__ __forceinline__ uint32_t smem_u32(const void* p) {
    uint32_t a;
    asm("{ .reg .u64 t; cvta.to.shared.u64 t, %1; cvt.u32.u64 %0, t; }" : "=r"(a) : "l"(p));
    return a;
}
__device__ __forceinline__ void ldsm4(uint32_t* r, uint32_t addr) {
    asm volatile("ldmatrix.sync.aligned.m8n8.x4.shared.b16 {%0,%1,%2,%3}, [%4];"
                 : "=r"(r[0]), "=r"(r[1]), "=r"(r[2]), "=r"(r[3]) : "r"(addr));
}
__device__ __forceinline__ void ldsm4t(uint32_t* r, uint32_t addr) {
    asm volatile("ldmatrix.sync.aligned.m8n8.x4.trans.shared.b16 {%0,%1,%2,%3}, [%4];"
                 : "=r"(r[0]), "=r"(r[1]), "=r"(r[2]), "=r"(r[3]) : "r"(addr));
}
__device__ __forceinline__ void mma16816(float* c, const uint32_t* a, const uint32_t* b) {
    asm volatile("mma.sync.aligned.m16n8k16.row.col.f32.f16.f16.f32 "
                 "{%0,%1,%2,%3}, {%4,%5,%6,%7}, {%8,%9}, {%0,%1,%2,%3};"
                 : "+f"(c[0]), "+f"(c[1]), "+f"(c[2]), "+f"(c[3])
                 : "r"(a[0]), "r"(a[1]), "r"(a[2]), "r"(a[3]), "r"(b[0]), "r"(b[1]));
}
__device__ __forceinline__ void cpa16(uint32_t saddr, const void* g) {
    asm volatile("cp.async.cg.shared.global [%0], [%1], 16;" :: "r"(saddr), "l"(g));
}
#define CP_COMMIT() asm volatile("cp.async.commit_group;")
#define CP_WAIT1()  asm volatile("cp.async.wait_group 1;")
__device__ __forceinline__ uint32_t packhf(float a, float b) {
    __half2 t = __floats2half2_rn(a, b);
    return *reinterpret_cast<uint32_t*>(&t);
}

// ---------------------------------------------------------------------------
// RMSNorm over DIM=1024 -> single fp16 (one block per row)
// ---------------------------------------------------------------------------
__global__ void rmsnorm_half_kernel(const float* __restrict__ in,
                                    const float* __restrict__ w,
                                    __half* __restrict__ xh) {
    int row = blockIdx.x;
    int i4 = threadIdx.x << 2;
    float4 v = *(const float4*)&in[(size_t)row*DIM_ + i4];
    float s = v.x*v.x + v.y*v.y + v.z*v.z + v.w*v.w;
    __shared__ float sm[8];
    for (int o = 16; o > 0; o >>= 1) s += __shfl_xor_sync(~0u, s, o);
    if ((threadIdx.x & 31) == 0) sm[threadIdx.x >> 5] = s;
    __syncthreads();
    if (threadIdx.x < 8) {
        s = sm[threadIdx.x];
        for (int o = 4; o > 0; o >>= 1) s += __shfl_xor_sync(0xffu, s, o);
        if (threadIdx.x == 0) sm[0] = s;
    }
    __syncthreads();
    float inv = rsqrtf(sm[0] * (1.f/DIM_) + EPS_);
    float4 wv = *(const float4*)&w[i4];
    uint32_t p0 = packhf(v.x*inv*wv.x, v.y*inv*wv.y);
    uint32_t p1 = packhf(v.z*inv*wv.z, v.w*inv*wv.w);
    *(uint2*)&xh[(size_t)row*DIM_ + i4] = make_uint2(p0, p1);
}

// ---------------------------------------------------------------------------
// Elementwise fp32 -> fp16 convert (weights)
// ---------------------------------------------------------------------------
__global__ void cvt_kernel(const float* __restrict__ in,
                           __half* __restrict__ out, int n4) {
    int i = blockIdx.x*256 + threadIdx.x;
    if (i >= n4) return;
    float4 v = ((const float4*)in)[i];
    uint32_t p0 = packhf(v.x, v.y);
    uint32_t p1 = packhf(v.z, v.w);
    *(uint2*)&out[(size_t)i*4] = make_uint2(p0, p1);
}

// ---------------------------------------------------------------------------
// Fused rmsnorm_dh + rope + fp16 (single) for k. One warp per row of 64.
// ---------------------------------------------------------------------------
__global__ void fused_rrs_kernel(const float* __restrict__ x, const float* __restrict__ w,
                                 int use_e, int total_rows,
                                 __half* __restrict__ hi) {
    int warp = (blockIdx.x * blockDim.x + threadIdx.x) >> 5;
    if (warp >= total_rows) return;
    int lane = threadIdx.x & 31;
    float2 v = ((const float2*)(x + ((size_t)warp << 6)))[lane];
    float s = v.x*v.x + v.y*v.y;
    for (int o = 16; o > 0; o >>= 1) s += __shfl_xor_sync(~0u, s, o);
    float inv = rsqrtf(s * (1.f/DH_) + EPS_);
    const float* ww = w + (use_e ? (warp / (BH_*N_)) * DH_ : 0);
    v.x *= inv * ww[2*lane];
    v.y *= inv * ww[2*lane+1];
    int n = warp & (N_-1);
    float c = g_cos[(n<<5) + lane], sn = g_sin[(n<<5) + lane];
    float rx = v.x*c - v.y*sn, ry = v.y*c + v.x*sn;
    ((uint32_t*)hi)[(warp << 5) + lane] = packhf(rx, ry);
}

// ---------------------------------------------------------------------------
// RoPE table
// ---------------------------------------------------------------------------
__global__ void rope_table_kernel() {
    int idx = blockIdx.x * blockDim.x + threadIdx.x;
    if (idx >= N_*32) return;
    int n = idx >> 5, t = idx & 31;
    float inv_freq = powf(10000.f, -(2.f * (float)t) / 64.f);
    float ang = (float)n * inv_freq;
    g_cos[idx] = cosf(ang);
    g_sin[idx] = sinf(ang);
}

// ---------------------------------------------------------------------------
// HMMA GEMM: single fp16 x single fp16. CTA 128x128, 8 warps (2x4),
// 3-stage cp.async pipeline, ldsm4t for B.
// CMODE: 0 = row-major fp32, 2 = kv layout fp32,
//        3 = kv layout single fp16 (Ch),
//        4 = q layout, fused rope, single fp16 (Ch)
// Stage layout (bytes): A[0,18432) W[18432,35840)
// ---------------------------------------------------------------------------
#define HGSTAGE_B 35840
#define HG_SMEM (HGSTAGE_B*3)     // 107520 bytes

template<int CMODE>
__global__ __launch_bounds__(256) void hgemm_kernel(
    const __half* __restrict__ Ah,
    const __half* __restrict__ Wh,
    float* __restrict__ C, __half* __restrict__ Ch,
    int K, int Nc) {
    extern __shared__ __half smb[];
    int tid = threadIdx.x, lane = tid & 31, wid = tid >> 5;
    int wr = wid & 1, wc = wid >> 1;
    int brow = blockIdx.y*128, bcol = blockIdx.x*128;
    uint32_t sbase = smem_u32(smb);

    float acc[4][4][4];
    #pragma unroll
    for (int mi = 0; mi < 4; mi++)
        #pragma unroll
        for (int ni = 0; ni < 4; ni++)
            #pragma unroll
            for (int j = 0; j < 4; j++) acc[mi][ni][j] = 0.f;

    int arow = wr*64 + (lane & 15);
    int acol = (lane >> 4) << 3;
    int brl  = lane & 15;
    int bq8  = (lane >> 4) << 3;

    auto issue = [&](int c, int stg) {
        uint32_t bu = sbase + stg*HGSTAGE_B;
        #pragma unroll
        for (int it = 0; it < 4; it++) {
            int idx = tid + it*256;
            int r = idx >> 3, kc = (idx & 7) << 3;
            size_t ga = (size_t)(brow + r)*K + c*64 + kc;
            cpa16(bu + ((r*72 + kc) << 1), Ah + ga);
            int kb = idx >> 4, nc2 = (idx & 15) << 3;
            size_t gb = (size_t)(c*64 + kb)*Nc + bcol + nc2;
            cpa16(bu + 18432 + ((kb*136 + nc2) << 1), Wh + gb);
        }
        CP_COMMIT();
    };

    int nchunks = K >> 6;
    issue(0, 0);
    if (nchunks > 1) issue(1, 1); else CP_COMMIT();
    for (int c = 0; c < nchunks; c++) {
        CP_WAIT1();
        __syncthreads();
        if (c + 2 < nchunks) issue(c + 2, (c + 2) % 3); else CP_COMMIT();
        uint32_t bu = sbase + (c % 3)*HGSTAGE_B;
        uint32_t sa = bu, sb_h = bu + 18432;
        #pragma unroll
        for (int kk = 0; kk < 4; kk++) {
            int k0 = kk << 4;
            uint32_t ah[4][4];
            #pragma unroll
            for (int mi = 0; mi < 4; mi++) {
                uint32_t off = (uint32_t)(((arow + mi*16)*72 + k0 + acol) << 1);
                ldsm4(ah[mi], sa + off);
            }
            #pragma unroll
            for (int nip = 0; nip < 2; nip++) {
                uint32_t t4h[4];
                uint32_t off = (uint32_t)((((k0 + brl)*136) + wc*32 + nip*16 + bq8) << 1);
                ldsm4t(t4h, sb_h + off);
                uint32_t b0h[2] = {t4h[0], t4h[1]}, b1h[2] = {t4h[2], t4h[3]};
                #pragma unroll
                for (int mi = 0; mi < 4; mi++) {
                    mma16816(acc[mi][2*nip],   ah[mi], b0h);
                    mma16816(acc[mi][2*nip+1], ah[mi], b1h);
                }
            }
        }
    }

    int g = lane >> 2, t2 = (lane & 3) << 1;
    #pragma unroll
    for (int mi = 0; mi < 4; mi++) {
        int row = brow + wr*64 + mi*16 + g;
        #pragma unroll
        for (int ni = 0; ni < 4; ni++) {
            int col = bcol + wc*32 + ni*8 + t2;
            if (CMODE == 3) {
                int b = row >> 11, n = row & 2047;
                int e = col >> 10, h = (col >> 6) & 15, d = col & 63;
                size_t i0 = (((((size_t)e*B_ + b)*H_ + h)*N_ + n) << 6) + d;
                *(uint32_t*)&Ch[i0]            = packhf(acc[mi][ni][0], acc[mi][ni][1]);
                *(uint32_t*)&Ch[i0 + (8 << 6)] = packhf(acc[mi][ni][2], acc[mi][ni][3]);
            } else if (CMODE == 4) {
                int b = row >> 11, n = row & 2047;
                int h = col >> 6, d = col & 63;
                int tt = d >> 1;
                float ca = g_cos[(n<<5) + tt], sa = g_sin[(n<<5) + tt];
                float cb = g_cos[((n+8)<<5) + tt], sb = g_sin[((n+8)<<5) + tt];
                float x0 = acc[mi][ni][0], y0 = acc[mi][ni][1];
                float x1 = acc[mi][ni][2], y1 = acc[mi][ni][3];
                size_t i0 = ((((size_t)b*H_ + h)*N_ + n) << 6) + d;
                *(uint32_t*)&Ch[i0]            = packhf(x0*ca - y0*sa, y0*ca + x0*sa);
                *(uint32_t*)&Ch[i0 + (8 << 6)] = packhf(x1*cb - y1*sb, y1*cb + x1*sb);
            } else {
                float* p0; float* p1;
                if (CMODE == 0) {
                    p0 = &C[(size_t)row * Nc + col];
                    p1 = &C[(size_t)(row+8) * Nc + col];
                } else {
                    int b = row >> 11, n = row & 2047;
                    int e = col >> 10, h = (col >> 6) & 15, d = col & 63;
                    p0 = &C[(((((size_t)e*B_ + b)*H_ + h)*N_ + n) << 6) + d];
                    p1 = p0 + (8 << 6);
                }
                *(float2*)p0 = make_float2(acc[mi][ni][0], acc[mi][ni][1]);
                *(float2*)p1 = make_float2(acc[mi][ni][2], acc[mi][ni][3]);
            }
        }
    }
}

// ---------------------------------------------------------------------------
// HMMA causal flash attention: 64 q-rows/block, 4 warps (128 thr),
// 3-stage cp.async pipeline. All operands single fp16.
// S = Q*K (1 term); P fp16 * V.
// Fused epilogue modes (mode = mode_base + blockIdx.z):
//   0: rope + single (slab)            [inner nq]  -> OH
//   1: rmsnorm + rope + single (slab)  [inner nk]  -> OH
//   2: plain single fp16 (slab)        [inner nv]  -> OH
//   3: gathered (b*n, h*d) single      [outer out] -> OH
// Stage layout (bytes): Kh 0 | V 9216  (18432/stage)
// ---------------------------------------------------------------------------
#define ATT_STAGE_B 18432
#define ATTN5_SMEM (ATT_STAGE_B*3)   // 55296

__global__ __launch_bounds__(128) void attn5_kernel(
    const __half* __restrict__ Qh,
    const __half* __restrict__ Kh,
    const __half* __restrict__ V,
    __half* __restrict__ OH,
    const float* __restrict__ wnorm, int mode_base) {
    extern __shared__ __half smb[];
    int tid = threadIdx.x, lane = tid & 31, w = tid >> 5;   // w in 0..3
    size_t matq = blockIdx.y;
    size_t mat  = blockIdx.y + (size_t)blockIdx.z * BH_;
    const __half* qh = Qh + (matq << 17);
    const __half* kh = Kh + (mat << 17);
    const __half* v  = V  + (mat << 17);
    int q0 = blockIdx.x * 64;
    uint32_t sbase = smem_u32(smb);

    // Stage Q (64 rows) into stage area, lift to registers
    #pragma unroll
    for (int it = 0; it < 4; it++) {
        int idx = tid + it*128;
        int r = idx >> 3, c8 = (idx & 7) << 3;
        *(uint4*)(smb + r*72 + c8) = *(const uint4*)(qh + ((size_t)(q0 + r) << 6) + c8);
    }
    __syncthreads();
    uint32_t qf[4][4];
    {
        int ar = w*16 + (lane & 15);
        int ac = (lane >> 4) << 3;
        #pragma unroll
        for (int kc = 0; kc < 4; kc++) {
            uint32_t off = (uint32_t)((ar*72 + kc*16 + ac) << 1);
            ldsm4(qf[kc], sbase + off);
        }
    }
    __syncthreads();

    auto issue = [&](int k0, int stg) {
        uint32_t bu = sbase + stg*ATT_STAGE_B;
        #pragma unroll
        for (int it = 0; it < 4; it++) {
            int idx = tid + it*128;
            int r = idx >> 3, c8 = (idx & 7) << 3;
            size_t gi = ((size_t)(k0 + r) << 6) + c8;
            uint32_t so = (uint32_t)((r*72 + c8) << 1);
            cpa16(bu + so,         kh + gi);
            cpa16(bu + 9216 + so,  v  + gi);
        }
        CP_COMMIT();
    };

    float m0 = -INFINITY, m1 = -INFINITY, l0 = 0.f, l1 = 0.f;
    float oa[8][4];
    #pragma unroll
    for (int dt = 0; dt < 8; dt++)
        #pragma unroll
        for (int j = 0; j < 4; j++) oa[dt][j] = 0.f;

    int g = lane >> 2;
    int qr0 = q0 + w*16 + g, qr1 = qr0 + 8;
    int cbase = (lane & 3) << 1;
    int br = lane & 15, bc = (lane >> 4) << 3;

    int nt = blockIdx.x + 1;
    issue(0, 0);
    if (nt > 1) issue(64, 1); else CP_COMMIT();
    for (int t = 0; t < nt; t++) {
        int k0 = t << 6;
        CP_WAIT1();
        __syncthreads();
        if (t + 2 < nt) issue((t + 2) << 6, (t + 2) % 3); else CP_COMMIT();
        uint32_t bu = sbase + (t % 3)*ATT_STAGE_B;
        uint32_t skh_u = bu, sv_u = bu + 9216;

        // --- S phase: 1-term Q x K ---
        float s[8][4];
        #pragma unroll
        for (int ntt = 0; ntt < 8; ntt++)
            #pragma unroll
            for (int j = 0; j < 4; j++) s[ntt][j] = 0.f;
        #pragma unroll
        for (int ntp = 0; ntp < 4; ntp++) {
            #pragma unroll
            for (int kc = 0; kc < 4; kc++) {
                uint32_t r4h[4];
                uint32_t off = (uint32_t)(((ntp*16 + br)*72 + kc*16 + bc) << 1);
                ldsm4(r4h, skh_u + off);
                uint32_t be[2] = {r4h[0], r4h[2]}, bo[2] = {r4h[1], r4h[3]};
                mma16816(s[2*ntp],   qf[kc], be);
                mma16816(s[2*ntp+1], qf[kc], bo);
            }
        }

        // --- softmax ---
        if (k0 + 63 > q0) {
            #pragma unroll
            for (int ntt = 0; ntt < 8; ntt++) {
                int key = k0 + ntt*8 + cbase;
                s[ntt][0] = (key   <= qr0) ? s[ntt][0]*0.125f : -INFINITY;
                s[ntt][1] = (key+1 <= qr0) ? s[ntt][1]*0.125f : -INFINITY;
                s[ntt][2] = (key   <= qr1) ? s[ntt][2]*0.125f : -INFINITY;
                s[ntt][3] = (key+1 <= qr1) ? s[ntt][3]*0.125f : -INFINITY;
            }
        } else {
            #pragma unroll
            for (int ntt = 0; ntt < 8; ntt++)
                #pragma unroll
                for (int j = 0; j < 4; j++) s[ntt][j] *= 0.125f;
        }
        float mt0 = m0, mt1 = m1;
        #pragma unroll
        for (int ntt = 0; ntt < 8; ntt++) {
            mt0 = fmaxf(mt0, fmaxf(s[ntt][0], s[ntt][1]));
            mt1 = fmaxf(mt1, fmaxf(s[ntt][2], s[ntt][3]));
        }
        mt0 = fmaxf(mt0, __shfl_xor_sync(~0u, mt0, 1));
        mt0 = fmaxf(mt0, __shfl_xor_sync(~0u, mt0, 2));
        mt1 = fmaxf(mt1, __shfl_xor_sync(~0u, mt1, 1));
        mt1 = fmaxf(mt1, __shfl_xor_sync(~0u, mt1, 2));
        float c0 = __expf(m0 - mt0), c1 = __expf(m1 - mt1);
        m0 = mt0; m1 = mt1;
        float ps0 = 0.f, ps1 = 0.f;
        uint32_t pf[4][4];
        #pragma unroll
        for (int kp = 0; kp < 4; kp++) {
            float p00 = __expf(s[2*kp][0]   - m0), p01 = __expf(s[2*kp][1]   - m0);
            float p10 = __expf(s[2*kp][2]   - m1), p11 = __expf(s[2*kp][3]   - m1);
            float p20 = __expf(s[2*kp+1][0] - m0), p21 = __expf(s[2*kp+1][1] - m0);
            float p30 = __expf(s[2*kp+1][2] - m1), p31 = __expf(s[2*kp+1][3] - m1);
            ps0 += p00 + p01 + p20 + p21;
            ps1 += p10 + p11 + p30 + p31;
            pf[kp][0] = packhf(p00, p01);
            pf[kp][1] = packhf(p10, p11);
            pf[kp][2] = packhf(p20, p21);
            pf[kp][3] = packhf(p30, p31);
        }
        l0 = l0*c0 + ps0;
        l1 = l1*c1 + ps1;
        #pragma unroll
        for (int dt = 0; dt < 8; dt++) {
            oa[dt][0] *= c0; oa[dt][1] *= c0;
            oa[dt][2] *= c1; oa[dt][3] *= c1;
        }

        // --- PV phase: single-V ---
        #pragma unroll
        for (int dtp = 0; dtp < 4; dtp++) {
            #pragma unroll
            for (int kc = 0; kc < 4; kc++) {
                uint32_t t4[4];
                uint32_t off = (uint32_t)(((kc*16 + br)*72 + dtp*16 + bc) << 1);
                ldsm4t(t4, sv_u + off);
                uint32_t b0[2] = {t4[0], t4[1]}, b1[2] = {t4[2], t4[3]};
                mma16816(oa[2*dtp],   pf[kc], b0);
                mma16816(oa[2*dtp+1], pf[kc], b1);
            }
        }
    }

    l0 += __shfl_xor_sync(~0u, l0, 1);
    l0 += __shfl_xor_sync(~0u, l0, 2);
    l1 += __shfl_xor_sync(~0u, l1, 1);
    l1 += __shfl_xor_sync(~0u, l1, 2);
    float i0 = 1.f / l0, i1 = 1.f / l1;
    int mode = mode_base + blockIdx.z;

    float xv[8][4];
    #pragma unroll
    for (int dt = 0; dt < 8; dt++) {
        xv[dt][0] = oa[dt][0]*i0; xv[dt][1] = oa[dt][1]*i0;
        xv[dt][2] = oa[dt][2]*i1; xv[dt][3] = oa[dt][3]*i1;
    }

    if (mode == 1) {
        float s0 = 0.f, s1 = 0.f;
        #pragma unroll
        for (int dt = 0; dt < 8; dt++) {
            s0 += xv[dt][0]*xv[dt][0] + xv[dt][1]*xv[dt][1];
            s1 += xv[dt][2]*xv[dt][2] + xv[dt][3]*xv[dt][3];
        }
        s0 += __shfl_xor_sync(~0u, s0, 1);
        s0 += __shfl_xor_sync(~0u, s0, 2);
        s1 += __shfl_xor_sync(~0u, s1, 1);
        s1 += __shfl_xor_sync(~0u, s1, 2);
        float inv0 = rsqrtf(s0 * (1.f/DH_) + EPS_);
        float inv1 = rsqrtf(s1 * (1.f/DH_) + EPS_);
        #pragma unroll
        for (int dt = 0; dt < 8; dt++) {
            int col = dt*8 + cbase;
            float wa = wnorm[col], wb = wnorm[col+1];
            xv[dt][0] *= inv0*wa; xv[dt][1] *= inv0*wb;
            xv[dt][2] *= inv1*wa; xv[dt][3] *= inv1*wb;
        }
    }
    if (mode <= 1) {
        #pragma unroll
        for (int dt = 0; dt < 8; dt++) {
            int tt = dt*4 + (lane & 3);
            float ca = g_cos[(qr0 << 5) + tt], sa = g_sin[(qr0 << 5) + tt];
            float cb = g_cos[(qr1 << 5) + tt], sb = g_sin[(qr1 << 5) + tt];
            float x0 = xv[dt][0], y0 = xv[dt][1];
            float x1 = xv[dt][2], y1 = xv[dt][3];
            xv[dt][0] = x0*ca - y0*sa; xv[dt][1] = y0*ca + x0*sa;
            xv[dt][2] = x1*cb - y1*sb; xv[dt][3] = y1*cb + x1*sb;
        }
    }

    if (mode <= 2) {
        // single fp16 slab — nq (rope'd), nk (rmsnorm+rope'd), nv
        __half* oh = OH + (mat << 17);
        #pragma unroll
        for (int dt = 0; dt < 8; dt++) {
            int col = dt*8 + cbase;
            *(uint32_t*)&oh[((size_t)qr0 << 6) + col] = packhf(xv[dt][0], xv[dt][1]);
            *(uint32_t*)&oh[((size_t)qr1 << 6) + col] = packhf(xv[dt][2], xv[dt][3]);
        }
    } else {
        int b = (int)(mat >> 4), h = (int)(mat & 15);
        size_t base0 = ((size_t)b*N_ + qr0)*DIM_ + h*64;
        size_t base1 = ((size_t)b*N_ + qr1)*DIM_ + h*64;
        #pragma unroll
        for (int dt = 0; dt < 8; dt++) {
            int col = dt*8 + cbase;
            *(uint32_t*)&OH[base0 + col] = packhf(xv[dt][0], xv[dt][1]);
            *(uint32_t*)&OH[base1 + col] = packhf(xv[dt][2], xv[dt][3]);
        }
    }
}

// ---------------------------------------------------------------------------
// Launch
// ---------------------------------------------------------------------------
extern "C" void kernel_launch(void* const* d_in, const int* in_sizes, int n_in,
                              void* d_out, int out_size) {
    const float* tokens        = (const float*)d_in[0];
    const float* w_norm        = (const float*)d_in[1];
    const float* w_q           = (const float*)d_in[2];
    const float* w_k           = (const float*)d_in[3];
    const float* w_v           = (const float*)d_in[4];
    const float* w_key_norms   = (const float*)d_in[5];
    const float* w_nested_knorm= (const float*)d_in[6];
    const float* w_out         = (const float*)d_in[7];
    float* out = (float*)d_out;

    float *pk;
    __half *pxh, *pwh, *poh;
    __half *pqh, *pkh, *pvh, *pnh;
    cudaGetSymbolAddress((void**)&pk, g_k);
    cudaGetSymbolAddress((void**)&pxh, g_xh);
    cudaGetSymbolAddress((void**)&pwh, g_wh);
    cudaGetSymbolAddress((void**)&poh, g_oh);
    cudaGetSymbolAddress((void**)&pqh, g_qh);
    cudaGetSymbolAddress((void**)&pkh, g_kh);
    cudaGetSymbolAddress((void**)&pvh, g_vh);
    cudaGetSymbolAddress((void**)&pnh, g_nh);

    static int attr_set = 0;
    if (!attr_set) {
        cudaFuncSetAttribute(hgemm_kernel<0>, cudaFuncAttributeMaxDynamicSharedMemorySize, HG_SMEM);
        cudaFuncSetAttribute(hgemm_kernel<2>, cudaFuncAttributeMaxDynamicSharedMemorySize, HG_SMEM);
        cudaFuncSetAttribute(hgemm_kernel<3>, cudaFuncAttributeMaxDynamicSharedMemorySize, HG_SMEM);
        cudaFuncSetAttribute(hgemm_kernel<4>, cudaFuncAttributeMaxDynamicSharedMemorySize, HG_SMEM);
        cudaFuncSetAttribute(attn5_kernel, cudaFuncAttributeMaxDynamicSharedMemorySize, ATTN5_SMEM);
        attr_set = 1;
    }

    // 1) x = rmsnorm(tokens) -> single fp16
    rmsnorm_half_kernel<<<ROWS_, 256>>>(tokens, w_norm, pxh);
    // 2) rope tables + weight converts (single fp16)
    rope_table_kernel<<<(N_*32 + 255)/256, 256>>>();
    cvt_kernel<<<1024, 256>>>(w_q,   pwh + WQ_OFF, 262144);
    cvt_kernel<<<3072, 256>>>(w_k,   pwh + WK_OFF, 786432);
    cvt_kernel<<<3072, 256>>>(w_v,   pwh + WV_OFF, 786432);
    cvt_kernel<<<1024, 256>>>(w_out, pwh + WO_OFF, 262144);
    // 3) projections (HMMA fp16):
    //    q: fused rope epilogue, single fp16 (no fp32 round trip)
    //    k: fp32 (rmsnorm+rope follow), v: single fp16 direct
    hgemm_kernel<4><<<dim3(8, 32),  256, HG_SMEM>>>(pxh, pwh + WQ_OFF, nullptr, pqh, DIM_, DIM_);
    hgemm_kernel<2><<<dim3(24, 32), 256, HG_SMEM>>>(pxh, pwh + WK_OFF, pk, nullptr, DIM_, 3*DIM_);
    hgemm_kernel<3><<<dim3(24, 32), 256, HG_SMEM>>>(pxh, pwh + WV_OFF, nullptr, pvh, DIM_, 3*DIM_);
    // 4) fused rmsnorm + rope + fp16 (single) for k
    fused_rrs_kernel<<<(3*BH_*N_*32 + 255)/256, 256>>>(pk, w_key_norms, 1, 3*BH_*N_, pkh);
    // 5) three inner causal attentions; epilogues: nq rope, nk rmsnorm+rope, nv plain (all single)
    attn5_kernel<<<dim3(N_/64, BH_, 3), 128, ATTN5_SMEM>>>(pqh, pkh, pvh,
                                                           pnh, w_nested_knorm, 0);
    // 6) outer causal attention; epilogue writes gathered (b*n, h*d) single fp16
    attn5_kernel<<<dim3(N_/64, BH_, 1), 128, ATTN5_SMEM>>>(pnh, pnh + SLAB_, pnh + 2*SLAB_,
                                                           poh, nullptr, 3);
    // 7) output projection (HMMA fp16)
    hgemm_kernel<0><<<dim3(8, 32), 256, HG_SMEM>>>(poh, pwh + WO_OFF, out, nullptr, DIM_, DIM_);
}

// round 15
// speedup vs baseline: 10.9094x; 1.0421x over previous
#include <cuda_runtime.h>
#include <cuda_fp16.h>
#include <math.h>
#include <stdint.h>

// Problem constants
#define B_  2
#define N_  2048
#define DIM_ 1024
#define H_  16
#define DH_ 64
#define BH_ (B_*H_)            // 32
#define ROWS_ (B_*N_)          // 4096
#define EPS_ 1.1920929e-07f

// ---------------------------------------------------------------------------
// Scratch (allocation-free: __device__ globals)
// ---------------------------------------------------------------------------
__device__ float g_cos[N_*32];
__device__ float g_sin[N_*32];
// fp16 operands
__device__ __half g_xh[(size_t)ROWS_*DIM_];        // rmsnorm'd tokens (single)
__device__ __half g_wh[8388608];                   // wq|wk|wv|wout (single fp16)
__device__ __half g_oh[(size_t)ROWS_*DIM_];        // gathered (bn, hd) single
__device__ __half g_qh[4194304];                   // q single fp16 (rope'd, pre-scaled)
__device__ __half g_kh[12582912];                  // k single fp16 (rmsnorm+rope'd)
__device__ __half g_vh[12582912];                  // v single fp16
__device__ __half g_nh[12582912];                  // nq|nk|nv single fp16

#define WQ_OFF 0
#define WK_OFF 1048576
#define WV_OFF 4194304
#define WO_OFF 7340032
#define SLAB_ 4194304

// ---------------------------------------------------------------------------
// PTX helpers
// ---------------------------------------------------------------------------
__device__ __forceinline__ uint32_t smem_u32(const void* p) {
    uint32_t a;
    asm("{ .reg .u64 t; cvta.to.shared.u64 t, %1; cvt.u32.u64 %0, t; }" : "=r"(a) : "l"(p));
    return a;
}
__device__ __forceinline__ void ldsm4(uint32_t* r, uint32_t addr) {
    asm volatile("ldmatrix.sync.aligned.m8n8.x4.shared.b16 {%0,%1,%2,%3}, [%4];"
                 : "=r"(r[0]), "=r"(r[1]), "=r"(r[2]), "=r"(r[3]) : "r"(addr));
}
__device__ __forceinline__ void ldsm4t(uint32_t* r, uint32_t addr) {
    asm volatile("ldmatrix.sync.aligned.m8n8.x4.trans.shared.b16 {%0,%1,%2,%3}, [%4];"
                 : "=r"(r[0]), "=r"(r[1]), "=r"(r[2]), "=r"(r[3]) : "r"(addr));
}
__device__ __forceinline__ void mma16816(float* c, const uint32_t* a, const uint32_t* b) {
    asm volatile("mma.sync.aligned.m16n8k16.row.col.f32.f16.f16.f32 "
                 "{%0,%1,%2,%3}, {%4,%5,%6,%7}, {%8,%9}, {%0,%1,%2,%3};"
                 : "+f"(c[0]), "+f"(c[1]), "+f"(c[2]), "+f"(c[3])
                 : "r"(a[0]), "r"(a[1]), "r"(a[2]), "r"(a[3]), "r"(b[0]), "r"(b[1]));
}
__device__ __forceinline__ void cpa16(uint32_t saddr, const void* g) {
    asm volatile("cp.async.cg.shared.global [%0], [%1], 16;" :: "r"(saddr), "l"(g));
}
#define CP_COMMIT() asm volatile("cp.async.commit_group;")
#define CP_WAIT1()  asm volatile("cp.async.wait_group 1;")
__device__ __forceinline__ uint32_t packhf(float a, float b) {
    __half2 t = __floats2half2_rn(a, b);
    return *reinterpret_cast<uint32_t*>(&t);
}

// ---------------------------------------------------------------------------
// RMSNorm over DIM=1024 -> single fp16 (one block per row)
// ---------------------------------------------------------------------------
__global__ void rmsnorm_half_kernel(const float* __restrict__ in,
                                    const float* __restrict__ w,
                                    __half* __restrict__ xh) {
    int row = blockIdx.x;
    int i4 = threadIdx.x << 2;
    float4 v = *(const float4*)&in[(size_t)row*DIM_ + i4];
    float s = v.x*v.x + v.y*v.y + v.z*v.z + v.w*v.w;
    __shared__ float sm[8];
    for (int o = 16; o > 0; o >>= 1) s += __shfl_xor_sync(~0u, s, o);
    if ((threadIdx.x & 31) == 0) sm[threadIdx.x >> 5] = s;
    __syncthreads();
    if (threadIdx.x < 8) {
        s = sm[threadIdx.x];
        for (int o = 4; o > 0; o >>= 1) s += __shfl_xor_sync(0xffu, s, o);
        if (threadIdx.x == 0) sm[0] = s;
    }
    __syncthreads();
    float inv = rsqrtf(sm[0] * (1.f/DIM_) + EPS_);
    float4 wv = *(const float4*)&w[i4];
    uint32_t p0 = packhf(v.x*inv*wv.x, v.y*inv*wv.y);
    uint32_t p1 = packhf(v.z*inv*wv.z, v.w*inv*wv.w);
    *(uint2*)&xh[(size_t)row*DIM_ + i4] = make_uint2(p0, p1);
}

// ---------------------------------------------------------------------------
// Elementwise fp32 -> fp16 convert (weights)
// ---------------------------------------------------------------------------
__global__ void cvt_kernel(const float* __restrict__ in,
                           __half* __restrict__ out, int n4) {
    int i = blockIdx.x*256 + threadIdx.x;
    if (i >= n4) return;
    float4 v = ((const float4*)in)[i];
    uint32_t p0 = packhf(v.x, v.y);
    uint32_t p1 = packhf(v.z, v.w);
    *(uint2*)&out[(size_t)i*4] = make_uint2(p0, p1);
}

// ---------------------------------------------------------------------------
// RoPE table
// ---------------------------------------------------------------------------
__global__ void rope_table_kernel() {
    int idx = blockIdx.x * blockDim.x + threadIdx.x;
    if (idx >= N_*32) return;
    int n = idx >> 5, t = idx & 31;
    float inv_freq = powf(10000.f, -(2.f * (float)t) / 64.f);
    float ang = (float)n * inv_freq;
    g_cos[idx] = cosf(ang);
    g_sin[idx] = sinf(ang);
}

// ---------------------------------------------------------------------------
// HMMA GEMM: single fp16 x single fp16. CTA 128x128, 8 warps (2x4),
// 3-stage cp.async pipeline, ldsm4t for B.
// CMODE: 0 = row-major fp32,
//        3 = kv layout single fp16 (Ch),
//        4 = q layout, fused rope + 0.125 scale, single fp16 (Ch)
//        5 = kv layout, fused rmsnorm(w_key_norms[e]) + rope, single fp16 (Ch)
// Stage layout (bytes): A[0,18432) W[18432,35840)
// ---------------------------------------------------------------------------
#define HGSTAGE_B 35840
#define HG_SMEM (HGSTAGE_B*3)     // 107520 bytes

template<int CMODE>
__global__ __launch_bounds__(256) void hgemm_kernel(
    const __half* __restrict__ Ah,
    const __half* __restrict__ Wh,
    float* __restrict__ C, __half* __restrict__ Ch,
    const float* __restrict__ wkn,
    int K, int Nc) {
    extern __shared__ __half smb[];
    int tid = threadIdx.x, lane = tid & 31, wid = tid >> 5;
    int wr = wid & 1, wc = wid >> 1;
    int brow = blockIdx.y*128, bcol = blockIdx.x*128;
    uint32_t sbase = smem_u32(smb);

    float acc[4][4][4];
    #pragma unroll
    for (int mi = 0; mi < 4; mi++)
        #pragma unroll
        for (int ni = 0; ni < 4; ni++)
            #pragma unroll
            for (int j = 0; j < 4; j++) acc[mi][ni][j] = 0.f;

    int arow = wr*64 + (lane & 15);
    int acol = (lane >> 4) << 3;
    int brl  = lane & 15;
    int bq8  = (lane >> 4) << 3;

    auto issue = [&](int c, int stg) {
        uint32_t bu = sbase + stg*HGSTAGE_B;
        #pragma unroll
        for (int it = 0; it < 4; it++) {
            int idx = tid + it*256;
            int r = idx >> 3, kc = (idx & 7) << 3;
            size_t ga = (size_t)(brow + r)*K + c*64 + kc;
            cpa16(bu + ((r*72 + kc) << 1), Ah + ga);
            int kb = idx >> 4, nc2 = (idx & 15) << 3;
            size_t gb = (size_t)(c*64 + kb)*Nc + bcol + nc2;
            cpa16(bu + 18432 + ((kb*136 + nc2) << 1), Wh + gb);
        }
        CP_COMMIT();
    };

    int nchunks = K >> 6;
    issue(0, 0);
    if (nchunks > 1) issue(1, 1); else CP_COMMIT();
    for (int c = 0; c < nchunks; c++) {
        CP_WAIT1();
        __syncthreads();
        if (c + 2 < nchunks) issue(c + 2, (c + 2) % 3); else CP_COMMIT();
        uint32_t bu = sbase + (c % 3)*HGSTAGE_B;
        uint32_t sa = bu, sb_h = bu + 18432;
        #pragma unroll
        for (int kk = 0; kk < 4; kk++) {
            int k0 = kk << 4;
            uint32_t ah[4][4];
            #pragma unroll
            for (int mi = 0; mi < 4; mi++) {
                uint32_t off = (uint32_t)(((arow + mi*16)*72 + k0 + acol) << 1);
                ldsm4(ah[mi], sa + off);
            }
            #pragma unroll
            for (int nip = 0; nip < 2; nip++) {
                uint32_t t4h[4];
                uint32_t off = (uint32_t)((((k0 + brl)*136) + wc*32 + nip*16 + bq8) << 1);
                ldsm4t(t4h, sb_h + off);
                uint32_t b0h[2] = {t4h[0], t4h[1]}, b1h[2] = {t4h[2], t4h[3]};
                #pragma unroll
                for (int mi = 0; mi < 4; mi++) {
                    mma16816(acc[mi][2*nip],   ah[mi], b0h);
                    mma16816(acc[mi][2*nip+1], ah[mi], b1h);
                }
            }
        }
    }

    int g = lane >> 2, t2 = (lane & 3) << 1;

    // CMODE 5: cross-warp rmsnorm over the 64-col head (2 warps per head)
    float inv_n[4][2];
    if (CMODE == 5) {
        __syncthreads();   // pipeline done; reuse smem as reduction buffer
        float* buf = (float*)smb;   // [wid][mi][rowoff][g] = 8*4*2*8 floats
        float sos[4][2];
        #pragma unroll
        for (int mi = 0; mi < 4; mi++) {
            float s0 = 0.f, s1 = 0.f;
            #pragma unroll
            for (int ni = 0; ni < 4; ni++) {
                s0 += acc[mi][ni][0]*acc[mi][ni][0] + acc[mi][ni][1]*acc[mi][ni][1];
                s1 += acc[mi][ni][2]*acc[mi][ni][2] + acc[mi][ni][3]*acc[mi][ni][3];
            }
            s0 += __shfl_xor_sync(~0u, s0, 1);
            s0 += __shfl_xor_sync(~0u, s0, 2);
            s1 += __shfl_xor_sync(~0u, s1, 1);
            s1 += __shfl_xor_sync(~0u, s1, 2);
            sos[mi][0] = s0; sos[mi][1] = s1;
            if ((lane & 3) == 0) {
                buf[((wid*4 + mi)*2 + 0)*8 + g] = s0;
                buf[((wid*4 + mi)*2 + 1)*8 + g] = s1;
            }
        }
        __syncthreads();
        int pw = wid ^ 2;    // partner warp: same wr, wc^1
        #pragma unroll
        for (int mi = 0; mi < 4; mi++) {
            float p0 = buf[((pw*4 + mi)*2 + 0)*8 + g];
            float p1 = buf[((pw*4 + mi)*2 + 1)*8 + g];
            inv_n[mi][0] = rsqrtf((sos[mi][0] + p0) * (1.f/DH_) + EPS_);
            inv_n[mi][1] = rsqrtf((sos[mi][1] + p1) * (1.f/DH_) + EPS_);
        }
    }

    #pragma unroll
    for (int mi = 0; mi < 4; mi++) {
        int row = brow + wr*64 + mi*16 + g;
        #pragma unroll
        for (int ni = 0; ni < 4; ni++) {
            int col = bcol + wc*32 + ni*8 + t2;
            if (CMODE == 3) {
                int b = row >> 11, n = row & 2047;
                int e = col >> 10, h = (col >> 6) & 15, d = col & 63;
                size_t i0 = (((((size_t)e*B_ + b)*H_ + h)*N_ + n) << 6) + d;
                *(uint32_t*)&Ch[i0]            = packhf(acc[mi][ni][0], acc[mi][ni][1]);
                *(uint32_t*)&Ch[i0 + (8 << 6)] = packhf(acc[mi][ni][2], acc[mi][ni][3]);
            } else if (CMODE == 4) {
                int b = row >> 11, n = row & 2047;
                int h = col >> 6, d = col & 63;
                int tt = d >> 1;
                float ca = g_cos[(n<<5) + tt], sa = g_sin[(n<<5) + tt];
                float cb = g_cos[((n+8)<<5) + tt], sb = g_sin[((n+8)<<5) + tt];
                float x0 = acc[mi][ni][0], y0 = acc[mi][ni][1];
                float x1 = acc[mi][ni][2], y1 = acc[mi][ni][3];
                size_t i0 = ((((size_t)b*H_ + h)*N_ + n) << 6) + d;
                *(uint32_t*)&Ch[i0]            = packhf((x0*ca - y0*sa)*0.125f, (y0*ca + x0*sa)*0.125f);
                *(uint32_t*)&Ch[i0 + (8 << 6)] = packhf((x1*cb - y1*sb)*0.125f, (y1*cb + x1*sb)*0.125f);
            } else if (CMODE == 5) {
                int b = row >> 11, n = row & 2047;
                int e = col >> 10, h = (col >> 6) & 15, d = col & 63;
                int tt = d >> 1;
                float wa = wkn[e*DH_ + d], wb = wkn[e*DH_ + d + 1];
                float x0 = acc[mi][ni][0]*inv_n[mi][0]*wa, y0 = acc[mi][ni][1]*inv_n[mi][0]*wb;
                float x1 = acc[mi][ni][2]*inv_n[mi][1]*wa, y1 = acc[mi][ni][3]*inv_n[mi][1]*wb;
                float ca = g_cos[(n<<5) + tt], sa = g_sin[(n<<5) + tt];
                float cb = g_cos[((n+8)<<5) + tt], sb = g_sin[((n+8)<<5) + tt];
                size_t i0 = (((((size_t)e*B_ + b)*H_ + h)*N_ + n) << 6) + d;
                *(uint32_t*)&Ch[i0]            = packhf(x0*ca - y0*sa, y0*ca + x0*sa);
                *(uint32_t*)&Ch[i0 + (8 << 6)] = packhf(x1*cb - y1*sb, y1*cb + x1*sb);
            } else {
                float* p0 = &C[(size_t)row * Nc + col];
                float* p1 = &C[(size_t)(row+8) * Nc + col];
                *(float2*)p0 = make_float2(acc[mi][ni][0], acc[mi][ni][1]);
                *(float2*)p1 = make_float2(acc[mi][ni][2], acc[mi][ni][3]);
            }
        }
    }
}

// ---------------------------------------------------------------------------
// HMMA causal flash attention: 64 q-rows/block, 4 warps (128 thr),
// 3-stage cp.async pipeline. All operands single fp16; Q pre-scaled by 0.125.
// Fused epilogue modes (mode = mode_base + blockIdx.z):
//   0: rope + 0.125 scale, single (slab)  [inner nq]  -> OH
//   1: rmsnorm + rope + single (slab)     [inner nk]  -> OH
//   2: plain single fp16 (slab)           [inner nv]  -> OH
//   3: gathered (b*n, h*d) single         [outer out] -> OH
// Stage layout (bytes): Kh 0 | V 9216  (18432/stage)
// ---------------------------------------------------------------------------
#define ATT_STAGE_B 18432
#define ATTN5_SMEM (ATT_STAGE_B*3)   // 55296

__global__ __launch_bounds__(128) void attn5_kernel(
    const __half* __restrict__ Qh,
    const __half* __restrict__ Kh,
    const __half* __restrict__ V,
    __half* __restrict__ OH,
    const float* __restrict__ wnorm, int mode_base) {
    extern __shared__ __half smb[];
    int tid = threadIdx.x, lane = tid & 31, w = tid >> 5;   // w in 0..3
    size_t matq = blockIdx.y;
    size_t mat  = blockIdx.y + (size_t)blockIdx.z * BH_;
    const __half* qh = Qh + (matq << 17);
    const __half* kh = Kh + (mat << 17);
    const __half* v  = V  + (mat << 17);
    int q0 = blockIdx.x * 64;
    uint32_t sbase = smem_u32(smb);

    // Stage Q (64 rows) into stage area, lift to registers
    #pragma unroll
    for (int it = 0; it < 4; it++) {
        int idx = tid + it*128;
        int r = idx >> 3, c8 = (idx & 7) << 3;
        *(uint4*)(smb + r*72 + c8) = *(const uint4*)(qh + ((size_t)(q0 + r) << 6) + c8);
    }
    __syncthreads();
    uint32_t qf[4][4];
    {
        int ar = w*16 + (lane & 15);
        int ac = (lane >> 4) << 3;
        #pragma unroll
        for (int kc = 0; kc < 4; kc++) {
            uint32_t off = (uint32_t)((ar*72 + kc*16 + ac) << 1);
            ldsm4(qf[kc], sbase + off);
        }
    }
    __syncthreads();

    auto issue = [&](int k0, int stg) {
        uint32_t bu = sbase + stg*ATT_STAGE_B;
        #pragma unroll
        for (int it = 0; it < 4; it++) {
            int idx = tid + it*128;
            int r = idx >> 3, c8 = (idx & 7) << 3;
            size_t gi = ((size_t)(k0 + r) << 6) + c8;
            uint32_t so = (uint32_t)((r*72 + c8) << 1);
            cpa16(bu + so,         kh + gi);
            cpa16(bu + 9216 + so,  v  + gi);
        }
        CP_COMMIT();
    };

    float m0 = -INFINITY, m1 = -INFINITY, l0 = 0.f, l1 = 0.f;
    float oa[8][4];
    #pragma unroll
    for (int dt = 0; dt < 8; dt++)
        #pragma unroll
        for (int j = 0; j < 4; j++) oa[dt][j] = 0.f;

    int g = lane >> 2;
    int qr0 = q0 + w*16 + g, qr1 = qr0 + 8;
    int cbase = (lane & 3) << 1;
    int br = lane & 15, bc = (lane >> 4) << 3;

    int nt = blockIdx.x + 1;
    issue(0, 0);
    if (nt > 1) issue(64, 1); else CP_COMMIT();
    for (int t = 0; t < nt; t++) {
        int k0 = t << 6;
        CP_WAIT1();
        __syncthreads();
        if (t + 2 < nt) issue((t + 2) << 6, (t + 2) % 3); else CP_COMMIT();
        uint32_t bu = sbase + (t % 3)*ATT_STAGE_B;
        uint32_t skh_u = bu, sv_u = bu + 9216;

        // --- S phase: 1-term Q x K (Q pre-scaled) ---
        float s[8][4];
        #pragma unroll
        for (int ntt = 0; ntt < 8; ntt++)
            #pragma unroll
            for (int j = 0; j < 4; j++) s[ntt][j] = 0.f;
        #pragma unroll
        for (int ntp = 0; ntp < 4; ntp++) {
            #pragma unroll
            for (int kc = 0; kc < 4; kc++) {
                uint32_t r4h[4];
                uint32_t off = (uint32_t)(((ntp*16 + br)*72 + kc*16 + bc) << 1);
                ldsm4(r4h, skh_u + off);
                uint32_t be[2] = {r4h[0], r4h[2]}, bo[2] = {r4h[1], r4h[3]};
                mma16816(s[2*ntp],   qf[kc], be);
                mma16816(s[2*ntp+1], qf[kc], bo);
            }
        }

        // --- softmax (scale already folded into Q) ---
        if (k0 + 63 > q0) {
            #pragma unroll
            for (int ntt = 0; ntt < 8; ntt++) {
                int key = k0 + ntt*8 + cbase;
                if (key   > qr0) s[ntt][0] = -INFINITY;
                if (key+1 > qr0) s[ntt][1] = -INFINITY;
                if (key   > qr1) s[ntt][2] = -INFINITY;
                if (key+1 > qr1) s[ntt][3] = -INFINITY;
            }
        }
        float mt0 = m0, mt1 = m1;
        #pragma unroll
        for (int ntt = 0; ntt < 8; ntt++) {
            mt0 = fmaxf(mt0, fmaxf(s[ntt][0], s[ntt][1]));
            mt1 = fmaxf(mt1, fmaxf(s[ntt][2], s[ntt][3]));
        }
        mt0 = fmaxf(mt0, __shfl_xor_sync(~0u, mt0, 1));
        mt0 = fmaxf(mt0, __shfl_xor_sync(~0u, mt0, 2));
        mt1 = fmaxf(mt1, __shfl_xor_sync(~0u, mt1, 1));
        mt1 = fmaxf(mt1, __shfl_xor_sync(~0u, mt1, 2));
        float c0 = __expf(m0 - mt0), c1 = __expf(m1 - mt1);
        m0 = mt0; m1 = mt1;
        float ps0 = 0.f, ps1 = 0.f;
        uint32_t pf[4][4];
        #pragma unroll
        for (int kp = 0; kp < 4; kp++) {
            float p00 = __expf(s[2*kp][0]   - m0), p01 = __expf(s[2*kp][1]   - m0);
            float p10 = __expf(s[2*kp][2]   - m1), p11 = __expf(s[2*kp][3]   - m1);
            float p20 = __expf(s[2*kp+1][0] - m0), p21 = __expf(s[2*kp+1][1] - m0);
            float p30 = __expf(s[2*kp+1][2] - m1), p31 = __expf(s[2*kp+1][3] - m1);
            ps0 += p00 + p01 + p20 + p21;
            ps1 += p10 + p11 + p30 + p31;
            pf[kp][0] = packhf(p00, p01);
            pf[kp][1] = packhf(p10, p11);
            pf[kp][2] = packhf(p20, p21);
            pf[kp][3] = packhf(p30, p31);
        }
        l0 = l0*c0 + ps0;
        l1 = l1*c1 + ps1;
        #pragma unroll
        for (int dt = 0; dt < 8; dt++) {
            oa[dt][0] *= c0; oa[dt][1] *= c0;
            oa[dt][2] *= c1; oa[dt][3] *= c1;
        }

        // --- PV phase: single-V ---
        #pragma unroll
        for (int dtp = 0; dtp < 4; dtp++) {
            #pragma unroll
            for (int kc = 0; kc < 4; kc++) {
                uint32_t t4[4];
                uint32_t off = (uint32_t)(((kc*16 + br)*72 + dtp*16 + bc) << 1);
                ldsm4t(t4, sv_u + off);
                uint32_t b0[2] = {t4[0], t4[1]}, b1[2] = {t4[2], t4[3]};
                mma16816(oa[2*dtp],   pf[kc], b0);
                mma16816(oa[2*dtp+1], pf[kc], b1);
            }
        }
    }

    l0 += __shfl_xor_sync(~0u, l0, 1);
    l0 += __shfl_xor_sync(~0u, l0, 2);
    l1 += __shfl_xor_sync(~0u, l1, 1);
    l1 += __shfl_xor_sync(~0u, l1, 2);
    float i0 = 1.f / l0, i1 = 1.f / l1;
    int mode = mode_base + blockIdx.z;

    float xv[8][4];
    #pragma unroll
    for (int dt = 0; dt < 8; dt++) {
        xv[dt][0] = oa[dt][0]*i0; xv[dt][1] = oa[dt][1]*i0;
        xv[dt][2] = oa[dt][2]*i1; xv[dt][3] = oa[dt][3]*i1;
    }

    if (mode == 1) {
        float s0 = 0.f, s1 = 0.f;
        #pragma unroll
        for (int dt = 0; dt < 8; dt++) {
            s0 += xv[dt][0]*xv[dt][0] + xv[dt][1]*xv[dt][1];
            s1 += xv[dt][2]*xv[dt][2] + xv[dt][3]*xv[dt][3];
        }
        s0 += __shfl_xor_sync(~0u, s0, 1);
        s0 += __shfl_xor_sync(~0u, s0, 2);
        s1 += __shfl_xor_sync(~0u, s1, 1);
        s1 += __shfl_xor_sync(~0u, s1, 2);
        float inv0 = rsqrtf(s0 * (1.f/DH_) + EPS_);
        float inv1 = rsqrtf(s1 * (1.f/DH_) + EPS_);
        #pragma unroll
        for (int dt = 0; dt < 8; dt++) {
            int col = dt*8 + cbase;
            float wa = wnorm[col], wb = wnorm[col+1];
            xv[dt][0] *= inv0*wa; xv[dt][1] *= inv0*wb;
            xv[dt][2] *= inv1*wa; xv[dt][3] *= inv1*wb;
        }
    }
    if (mode <= 1) {
        float qsc = (mode == 0) ? 0.125f : 1.f;   // nq is outer-attention Q: fold scale
        #pragma unroll
        for (int dt = 0; dt < 8; dt++) {
            int tt = dt*4 + (lane & 3);
            float ca = g_cos[(qr0 << 5) + tt], sa = g_sin[(qr0 << 5) + tt];
            float cb = g_cos[(qr1 << 5) + tt], sb = g_sin[(qr1 << 5) + tt];
            float x0 = xv[dt][0], y0 = xv[dt][1];
            float x1 = xv[dt][2], y1 = xv[dt][3];
            xv[dt][0] = (x0*ca - y0*sa)*qsc; xv[dt][1] = (y0*ca + x0*sa)*qsc;
            xv[dt][2] = (x1*cb - y1*sb)*qsc; xv[dt][3] = (y1*cb + x1*sb)*qsc;
        }
    }

    if (mode <= 2) {
        __half* oh = OH + (mat << 17);
        #pragma unroll
        for (int dt = 0; dt < 8; dt++) {
            int col = dt*8 + cbase;
            *(uint32_t*)&oh[((size_t)qr0 << 6) + col] = packhf(xv[dt][0], xv[dt][1]);
            *(uint32_t*)&oh[((size_t)qr1 << 6) + col] = packhf(xv[dt][2], xv[dt][3]);
        }
    } else {
        int b = (int)(mat >> 4), h = (int)(mat & 15);
        size_t base0 = ((size_t)b*N_ + qr0)*DIM_ + h*64;
        size_t base1 = ((size_t)b*N_ + qr1)*DIM_ + h*64;
        #pragma unroll
        for (int dt = 0; dt < 8; dt++) {
            int col = dt*8 + cbase;
            *(uint32_t*)&OH[base0 + col] = packhf(xv[dt][0], xv[dt][1]);
            *(uint32_t*)&OH[base1 + col] = packhf(xv[dt][2], xv[dt][3]);
        }
    }
}

// ---------------------------------------------------------------------------
// Launch
// ---------------------------------------------------------------------------
extern "C" void kernel_launch(void* const* d_in, const int* in_sizes, int n_in,
                              void* d_out, int out_size) {
    const float* tokens        = (const float*)d_in[0];
    const float* w_norm        = (const float*)d_in[1];
    const float* w_q           = (const float*)d_in[2];
    const float* w_k           = (const float*)d_in[3];
    const float* w_v           = (const float*)d_in[4];
    const float* w_key_norms   = (const float*)d_in[5];
    const float* w_nested_knorm= (const float*)d_in[6];
    const float* w_out         = (const float*)d_in[7];
    float* out = (float*)d_out;

    __half *pxh, *pwh, *poh;
    __half *pqh, *pkh, *pvh, *pnh;
    cudaGetSymbolAddress((void**)&pxh, g_xh);
    cudaGetSymbolAddress((void**)&pwh, g_wh);
    cudaGetSymbolAddress((void**)&poh, g_oh);
    cudaGetSymbolAddress((void**)&pqh, g_qh);
    cudaGetSymbolAddress((void**)&pkh, g_kh);
    cudaGetSymbolAddress((void**)&pvh, g_vh);
    cudaGetSymbolAddress((void**)&pnh, g_nh);

    static int attr_set = 0;
    if (!attr_set) {
        cudaFuncSetAttribute(hgemm_kernel<0>, cudaFuncAttributeMaxDynamicSharedMemorySize, HG_SMEM);
        cudaFuncSetAttribute(hgemm_kernel<3>, cudaFuncAttributeMaxDynamicSharedMemorySize, HG_SMEM);
        cudaFuncSetAttribute(hgemm_kernel<4>, cudaFuncAttributeMaxDynamicSharedMemorySize, HG_SMEM);
        cudaFuncSetAttribute(hgemm_kernel<5>, cudaFuncAttributeMaxDynamicSharedMemorySize, HG_SMEM);
        cudaFuncSetAttribute(attn5_kernel, cudaFuncAttributeMaxDynamicSharedMemorySize, ATTN5_SMEM);
        attr_set = 1;
    }

    // 1) x = rmsnorm(tokens) -> single fp16
    rmsnorm_half_kernel<<<ROWS_, 256>>>(tokens, w_norm, pxh);
    // 2) rope tables + weight converts (single fp16)
    rope_table_kernel<<<(N_*32 + 255)/256, 256>>>();
    cvt_kernel<<<1024, 256>>>(w_q,   pwh + WQ_OFF, 262144);
    cvt_kernel<<<3072, 256>>>(w_k,   pwh + WK_OFF, 786432);
    cvt_kernel<<<3072, 256>>>(w_v,   pwh + WV_OFF, 786432);
    cvt_kernel<<<1024, 256>>>(w_out, pwh + WO_OFF, 262144);
    // 3) projections (HMMA fp16), all epilogue-fused to final fp16 operands:
    //    q: rope + 0.125 scale;  k: rmsnorm(w_key_norms) + rope;  v: plain
    hgemm_kernel<4><<<dim3(8, 32),  256, HG_SMEM>>>(pxh, pwh + WQ_OFF, nullptr, pqh, nullptr, DIM_, DIM_);
    hgemm_kernel<5><<<dim3(24, 32), 256, HG_SMEM>>>(pxh, pwh + WK_OFF, nullptr, pkh, w_key_norms, DIM_, 3*DIM_);
    hgemm_kernel<3><<<dim3(24, 32), 256, HG_SMEM>>>(pxh, pwh + WV_OFF, nullptr, pvh, nullptr, DIM_, 3*DIM_);
    // 4) three inner causal attentions; epilogues: nq rope+scale, nk rmsnorm+rope, nv plain
    attn5_kernel<<<dim3(N_/64, BH_, 3), 128, ATTN5_SMEM>>>(pqh, pkh, pvh,
                                                           pnh, w_nested_knorm, 0);
    // 5) outer causal attention; epilogue writes gathered (b*n, h*d) single fp16
    attn5_kernel<<<dim3(N_/64, BH_, 1), 128, ATTN5_SMEM>>>(pnh, pnh + SLAB_, pnh + 2*SLAB_,
                                                           poh, nullptr, 3);
    // 6) output projection (HMMA fp16)
    hgemm_kernel<0><<<dim3(8, 32), 256, HG_SMEM>>>(poh, pwh + WO_OFF, out, nullptr, nullptr, DIM_, DIM_);
}

// round 16
// speedup vs baseline: 11.7226x; 1.0745x over previous
#include <cuda_runtime.h>
#include <cuda_fp16.h>
#include <math.h>
#include <stdint.h>

// Problem constants
#define B_  2
#define N_  2048
#define DIM_ 1024
#define H_  16
#define DH_ 64
#define BH_ (B_*H_)            // 32
#define ROWS_ (B_*N_)          // 4096
#define EPS_ 1.1920929e-07f
#define QSCALE_ (0.125f*1.44269504089f)   // 1/sqrt(64) * log2(e), folded into Q

// ---------------------------------------------------------------------------
// Scratch (allocation-free: __device__ globals)
// ---------------------------------------------------------------------------
__device__ float g_cos[N_*32];
__device__ float g_sin[N_*32];
__device__ __half g_xh[(size_t)ROWS_*DIM_];        // rmsnorm'd tokens (single)
__device__ __half g_wh[8388608];                   // wq | wk|wv interleaved | wout
__device__ __half g_oh[(size_t)ROWS_*DIM_];        // gathered (bn, hd) single
__device__ __half g_qh[4194304];                   // q (rope'd, pre-scaled)
__device__ __half g_kh[12582912];                  // k (rmsnorm+rope'd)
__device__ __half g_vh[12582912];                  // v
__device__ __half g_nh[12582912];                  // nq|nk|nv

#define WQ_OFF  0
#define WKV_OFF 1048576
#define WO_OFF  7340032
#define SLAB_   4194304

// ---------------------------------------------------------------------------
// PTX helpers
// ---------------------------------------------------------------------------
__device__ __forceinline__ uint32_t smem_u32(const void* p) {
    uint32_t a;
    asm("{ .reg .u64 t; cvta.to.shared.u64 t, %1; cvt.u32.u64 %0, t; }" : "=r"(a) : "l"(p));
    return a;
}
__device__ __forceinline__ void ldsm4(uint32_t* r, uint32_t addr) {
    asm volatile("ldmatrix.sync.aligned.m8n8.x4.shared.b16 {%0,%1,%2,%3}, [%4];"
                 : "=r"(r[0]), "=r"(r[1]), "=r"(r[2]), "=r"(r[3]) : "r"(addr));
}
__device__ __forceinline__ void ldsm4t(uint32_t* r, uint32_t addr) {
    asm volatile("ldmatrix.sync.aligned.m8n8.x4.trans.shared.b16 {%0,%1,%2,%3}, [%4];"
                 : "=r"(r[0]), "=r"(r[1]), "=r"(r[2]), "=r"(r[3]) : "r"(addr));
}
__device__ __forceinline__ void mma16816(float* c, const uint32_t* a, const uint32_t* b) {
    asm volatile("mma.sync.aligned.m16n8k16.row.col.f32.f16.f16.f32 "
                 "{%0,%1,%2,%3}, {%4,%5,%6,%7}, {%8,%9}, {%0,%1,%2,%3};"
                 : "+f"(c[0]), "+f"(c[1]), "+f"(c[2]), "+f"(c[3])
                 : "r"(a[0]), "r"(a[1]), "r"(a[2]), "r"(a[3]), "r"(b[0]), "r"(b[1]));
}
__device__ __forceinline__ void cpa16(uint32_t saddr, const void* g) {
    asm volatile("cp.async.cg.shared.global [%0], [%1], 16;" :: "r"(saddr), "l"(g));
}
#define CP_COMMIT() asm volatile("cp.async.commit_group;")
#define CP_WAIT1()  asm volatile("cp.async.wait_group 1;")
__device__ __forceinline__ uint32_t packhf(float a, float b) {
    __half2 t = __floats2half2_rn(a, b);
    return *reinterpret_cast<uint32_t*>(&t);
}

// ---------------------------------------------------------------------------
// Fused prep: rmsnorm(tokens)->fp16, rope tables, weight converts.
// Block ranges:
//   [0,4096)        rmsnorm row = blockIdx.x
//   [4096,4352)     rope table
//   [4352,5376)     w_q  -> g_wh[WQ_OFF]  (identity)
//   [5376,8448)     w_k  -> g_wh[WKV_OFF] interleaved [k][6144], cols 0..3071
//   [8448,11520)    w_v  -> g_wh[WKV_OFF] interleaved, cols 3072..6143
//   [11520,12544)   w_out-> g_wh[WO_OFF]  (identity)
// ---------------------------------------------------------------------------
__global__ void prep_kernel(const float* __restrict__ tokens,
                            const float* __restrict__ w_norm,
                            const float* __restrict__ w_q,
                            const float* __restrict__ w_k,
                            const float* __restrict__ w_v,
                            const float* __restrict__ w_out,
                            __half* __restrict__ xh,
                            __half* __restrict__ wh) {
    __shared__ float sm[8];
    int b = blockIdx.x, tid = threadIdx.x;
    if (b < 4096) {
        int row = b;
        int i4 = tid << 2;
        float4 v = *(const float4*)&tokens[(size_t)row*DIM_ + i4];
        float s = v.x*v.x + v.y*v.y + v.z*v.z + v.w*v.w;
        for (int o = 16; o > 0; o >>= 1) s += __shfl_xor_sync(~0u, s, o);
        if ((tid & 31) == 0) sm[tid >> 5] = s;
        __syncthreads();
        if (tid < 8) {
            s = sm[tid];
            for (int o = 4; o > 0; o >>= 1) s += __shfl_xor_sync(0xffu, s, o);
            if (tid == 0) sm[0] = s;
        }
        __syncthreads();
        float inv = rsqrtf(sm[0] * (1.f/DIM_) + EPS_);
        float4 wv = *(const float4*)&w_norm[i4];
        uint32_t p0 = packhf(v.x*inv*wv.x, v.y*inv*wv.y);
        uint32_t p1 = packhf(v.z*inv*wv.z, v.w*inv*wv.w);
        *(uint2*)&xh[(size_t)row*DIM_ + i4] = make_uint2(p0, p1);
    } else if (b < 4352) {
        int idx = (b - 4096)*256 + tid;
        int n = idx >> 5, t = idx & 31;
        float inv_freq = powf(10000.f, -(2.f * (float)t) / 64.f);
        float ang = (float)n * inv_freq;
        g_cos[idx] = cosf(ang);
        g_sin[idx] = sinf(ang);
    } else if (b < 5376) {
        int i = (b - 4352)*256 + tid;
        float4 v = ((const float4*)w_q)[i];
        *(uint2*)&wh[WQ_OFF + (size_t)i*4] = make_uint2(packhf(v.x, v.y), packhf(v.z, v.w));
    } else if (b < 8448) {
        int i = (b - 5376)*256 + tid;
        int linear = i << 2;
        int k = linear / 3072, n = linear - k*3072;
        float4 v = ((const float4*)w_k)[i];
        *(uint2*)&wh[WKV_OFF + (size_t)k*6144 + n] = make_uint2(packhf(v.x, v.y), packhf(v.z, v.w));
    } else if (b < 11520) {
        int i = (b - 8448)*256 + tid;
        int linear = i << 2;
        int k = linear / 3072, n = linear - k*3072;
        float4 v = ((const float4*)w_v)[i];
        *(uint2*)&wh[WKV_OFF + (size_t)k*6144 + 3072 + n] = make_uint2(packhf(v.x, v.y), packhf(v.z, v.w));
    } else {
        int i = (b - 11520)*256 + tid;
        float4 v = ((const float4*)w_out)[i];
        *(uint2*)&wh[WO_OFF + (size_t)i*4] = make_uint2(packhf(v.x, v.y), packhf(v.z, v.w));
    }
}

// ---------------------------------------------------------------------------
// HMMA GEMM: single fp16 x single fp16. CTA 128x128, 8 warps (2x4),
// 3-stage cp.async pipeline, ldsm4t for B.
// CMODE: 0 = row-major fp32 (out-projection)
//        4 = q layout, fused rope + QSCALE, single fp16 (Ch)
//        6 = merged kv: blocks with bcol<3072 -> k (rmsnorm+rope -> Ch),
//            else -> v plain (col-3072 -> Cv)
// Stage layout (bytes): A[0,18432) W[18432,35840)
// ---------------------------------------------------------------------------
#define HGSTAGE_B 35840
#define HG_SMEM (HGSTAGE_B*3)     // 107520 bytes

template<int CMODE>
__global__ __launch_bounds__(256) void hgemm_kernel(
    const __half* __restrict__ Ah,
    const __half* __restrict__ Wh,
    float* __restrict__ C, __half* __restrict__ Ch, __half* __restrict__ Cv,
    const float* __restrict__ wkn,
    int K, int Nc) {
    extern __shared__ __half smb[];
    int tid = threadIdx.x, lane = tid & 31, wid = tid >> 5;
    int wr = wid & 1, wc = wid >> 1;
    int brow = blockIdx.y*128, bcol = blockIdx.x*128;
    uint32_t sbase = smem_u32(smb);

    float acc[4][4][4];
    #pragma unroll
    for (int mi = 0; mi < 4; mi++)
        #pragma unroll
        for (int ni = 0; ni < 4; ni++)
            #pragma unroll
            for (int j = 0; j < 4; j++) acc[mi][ni][j] = 0.f;

    int arow = wr*64 + (lane & 15);
    int acol = (lane >> 4) << 3;
    int brl  = lane & 15;
    int bq8  = (lane >> 4) << 3;

    auto issue = [&](int c, int stg) {
        uint32_t bu = sbase + stg*HGSTAGE_B;
        #pragma unroll
        for (int it = 0; it < 4; it++) {
            int idx = tid + it*256;
            int r = idx >> 3, kc = (idx & 7) << 3;
            size_t ga = (size_t)(brow + r)*K + c*64 + kc;
            cpa16(bu + ((r*72 + kc) << 1), Ah + ga);
            int kb = idx >> 4, nc2 = (idx & 15) << 3;
            size_t gb = (size_t)(c*64 + kb)*Nc + bcol + nc2;
            cpa16(bu + 18432 + ((kb*136 + nc2) << 1), Wh + gb);
        }
        CP_COMMIT();
    };

    int nchunks = K >> 6;
    issue(0, 0);
    if (nchunks > 1) issue(1, 1); else CP_COMMIT();
    for (int c = 0; c < nchunks; c++) {
        CP_WAIT1();
        __syncthreads();
        if (c + 2 < nchunks) issue(c + 2, (c + 2) % 3); else CP_COMMIT();
        uint32_t bu = sbase + (c % 3)*HGSTAGE_B;
        uint32_t sa = bu, sb_h = bu + 18432;
        #pragma unroll
        for (int kk = 0; kk < 4; kk++) {
            int k0 = kk << 4;
            uint32_t ah[4][4];
            #pragma unroll
            for (int mi = 0; mi < 4; mi++) {
                uint32_t off = (uint32_t)(((arow + mi*16)*72 + k0 + acol) << 1);
                ldsm4(ah[mi], sa + off);
            }
            #pragma unroll
            for (int nip = 0; nip < 2; nip++) {
                uint32_t t4h[4];
                uint32_t off = (uint32_t)((((k0 + brl)*136) + wc*32 + nip*16 + bq8) << 1);
                ldsm4t(t4h, sb_h + off);
                uint32_t b0h[2] = {t4h[0], t4h[1]}, b1h[2] = {t4h[2], t4h[3]};
                #pragma unroll
                for (int mi = 0; mi < 4; mi++) {
                    mma16816(acc[mi][2*nip],   ah[mi], b0h);
                    mma16816(acc[mi][2*nip+1], ah[mi], b1h);
                }
            }
        }
    }

    int g = lane >> 2, t2 = (lane & 3) << 1;
    bool kpath = (CMODE == 6) && (bcol < 3072);

    // k path: cross-warp rmsnorm over the 64-col head (2 warps per head)
    float inv_n[4][2];
    if (kpath) {
        __syncthreads();   // pipeline done; reuse smem as reduction buffer
        float* buf = (float*)smb;
        float sos[4][2];
        #pragma unroll
        for (int mi = 0; mi < 4; mi++) {
            float s0 = 0.f, s1 = 0.f;
            #pragma unroll
            for (int ni = 0; ni < 4; ni++) {
                s0 += acc[mi][ni][0]*acc[mi][ni][0] + acc[mi][ni][1]*acc[mi][ni][1];
                s1 += acc[mi][ni][2]*acc[mi][ni][2] + acc[mi][ni][3]*acc[mi][ni][3];
            }
            s0 += __shfl_xor_sync(~0u, s0, 1);
            s0 += __shfl_xor_sync(~0u, s0, 2);
            s1 += __shfl_xor_sync(~0u, s1, 1);
            s1 += __shfl_xor_sync(~0u, s1, 2);
            sos[mi][0] = s0; sos[mi][1] = s1;
            if ((lane & 3) == 0) {
                buf[((wid*4 + mi)*2 + 0)*8 + g] = s0;
                buf[((wid*4 + mi)*2 + 1)*8 + g] = s1;
            }
        }
        __syncthreads();
        int pw = wid ^ 2;    // partner warp: same wr, wc^1
        #pragma unroll
        for (int mi = 0; mi < 4; mi++) {
            float p0 = buf[((pw*4 + mi)*2 + 0)*8 + g];
            float p1 = buf[((pw*4 + mi)*2 + 1)*8 + g];
            inv_n[mi][0] = rsqrtf((sos[mi][0] + p0) * (1.f/DH_) + EPS_);
            inv_n[mi][1] = rsqrtf((sos[mi][1] + p1) * (1.f/DH_) + EPS_);
        }
    }

    #pragma unroll
    for (int mi = 0; mi < 4; mi++) {
        int row = brow + wr*64 + mi*16 + g;
        #pragma unroll
        for (int ni = 0; ni < 4; ni++) {
            int col = bcol + wc*32 + ni*8 + t2;
            if (CMODE == 4) {
                int b = row >> 11, n = row & 2047;
                int h = col >> 6, d = col & 63;
                int tt = d >> 1;
                float ca = g_cos[(n<<5) + tt], sa = g_sin[(n<<5) + tt];
                float cb = g_cos[((n+8)<<5) + tt], sb = g_sin[((n+8)<<5) + tt];
                float x0 = acc[mi][ni][0], y0 = acc[mi][ni][1];
                float x1 = acc[mi][ni][2], y1 = acc[mi][ni][3];
                size_t i0 = ((((size_t)b*H_ + h)*N_ + n) << 6) + d;
                *(uint32_t*)&Ch[i0]            = packhf((x0*ca - y0*sa)*QSCALE_, (y0*ca + x0*sa)*QSCALE_);
                *(uint32_t*)&Ch[i0 + (8 << 6)] = packhf((x1*cb - y1*sb)*QSCALE_, (y1*cb + x1*sb)*QSCALE_);
            } else if (CMODE == 6) {
                int b = row >> 11, n = row & 2047;
                if (kpath) {
                    int e = col >> 10, h = (col >> 6) & 15, d = col & 63;
                    int tt = d >> 1;
                    float wa = wkn[e*DH_ + d], wb = wkn[e*DH_ + d + 1];
                    float x0 = acc[mi][ni][0]*inv_n[mi][0]*wa, y0 = acc[mi][ni][1]*inv_n[mi][0]*wb;
                    float x1 = acc[mi][ni][2]*inv_n[mi][1]*wa, y1 = acc[mi][ni][3]*inv_n[mi][1]*wb;
                    float ca = g_cos[(n<<5) + tt], sa = g_sin[(n<<5) + tt];
                    float cb = g_cos[((n+8)<<5) + tt], sb = g_sin[((n+8)<<5) + tt];
                    size_t i0 = (((((size_t)e*B_ + b)*H_ + h)*N_ + n) << 6) + d;
                    *(uint32_t*)&Ch[i0]            = packhf(x0*ca - y0*sa, y0*ca + x0*sa);
                    *(uint32_t*)&Ch[i0 + (8 << 6)] = packhf(x1*cb - y1*sb, y1*cb + x1*sb);
                } else {
                    int vcol = col - 3072;
                    int e = vcol >> 10, h = (vcol >> 6) & 15, d = vcol & 63;
                    size_t i0 = (((((size_t)e*B_ + b)*H_ + h)*N_ + n) << 6) + d;
                    *(uint32_t*)&Cv[i0]            = packhf(acc[mi][ni][0], acc[mi][ni][1]);
                    *(uint32_t*)&Cv[i0 + (8 << 6)] = packhf(acc[mi][ni][2], acc[mi][ni][3]);
                }
            } else {
                float* p0 = &C[(size_t)row * Nc + col];
                float* p1 = &C[(size_t)(row+8) * Nc + col];
                *(float2*)p0 = make_float2(acc[mi][ni][0], acc[mi][ni][1]);
                *(float2*)p1 = make_float2(acc[mi][ni][2], acc[mi][ni][3]);
            }
        }
    }
}

// ---------------------------------------------------------------------------
// HMMA causal flash attention: 64 q-rows/block, 4 warps (128 thr),
// 3-stage cp.async pipeline. All operands single fp16; Q pre-scaled by
// 0.125*log2(e) so softmax uses exp2.
// Fused epilogue modes (mode = mode_base + blockIdx.z):
//   0: rope + QSCALE, single (slab)       [inner nq]  -> OH
//   1: rmsnorm + rope + single (slab)     [inner nk]  -> OH
//   2: plain single fp16 (slab)           [inner nv]  -> OH
//   3: gathered (b*n, h*d) single         [outer out] -> OH
// Stage layout (bytes): Kh 0 | V 9216  (18432/stage)
// ---------------------------------------------------------------------------
#define ATT_STAGE_B 18432
#define ATTN5_SMEM (ATT_STAGE_B*3)   // 55296

__global__ __launch_bounds__(128) void attn5_kernel(
    const __half* __restrict__ Qh,
    const __half* __restrict__ Kh,
    const __half* __restrict__ V,
    __half* __restrict__ OH,
    const float* __restrict__ wnorm, int mode_base) {
    extern __shared__ __half smb[];
    int tid = threadIdx.x, lane = tid & 31, w = tid >> 5;   // w in 0..3
    size_t matq = blockIdx.y;
    size_t mat  = blockIdx.y + (size_t)blockIdx.z * BH_;
    const __half* qh = Qh + (matq << 17);
    const __half* kh = Kh + (mat << 17);
    const __half* v  = V  + (mat << 17);
    int q0 = blockIdx.x * 64;
    uint32_t sbase = smem_u32(smb);

    // Stage Q (64 rows) into stage area, lift to registers
    #pragma unroll
    for (int it = 0; it < 4; it++) {
        int idx = tid + it*128;
        int r = idx >> 3, c8 = (idx & 7) << 3;
        *(uint4*)(smb + r*72 + c8) = *(const uint4*)(qh + ((size_t)(q0 + r) << 6) + c8);
    }
    __syncthreads();
    uint32_t qf[4][4];
    {
        int ar = w*16 + (lane & 15);
        int ac = (lane >> 4) << 3;
        #pragma unroll
        for (int kc = 0; kc < 4; kc++) {
            uint32_t off = (uint32_t)((ar*72 + kc*16 + ac) << 1);
            ldsm4(qf[kc], sbase + off);
        }
    }
    __syncthreads();

    auto issue = [&](int k0, int stg) {
        uint32_t bu = sbase + stg*ATT_STAGE_B;
        #pragma unroll
        for (int it = 0; it < 4; it++) {
            int idx = tid + it*128;
            int r = idx >> 3, c8 = (idx & 7) << 3;
            size_t gi = ((size_t)(k0 + r) << 6) + c8;
            uint32_t so = (uint32_t)((r*72 + c8) << 1);
            cpa16(bu + so,         kh + gi);
            cpa16(bu + 9216 + so,  v  + gi);
        }
        CP_COMMIT();
    };

    float m0 = -INFINITY, m1 = -INFINITY, l0 = 0.f, l1 = 0.f;
    float oa[8][4];
    #pragma unroll
    for (int dt = 0; dt < 8; dt++)
        #pragma unroll
        for (int j = 0; j < 4; j++) oa[dt][j] = 0.f;

    int g = lane >> 2;
    int qr0 = q0 + w*16 + g, qr1 = qr0 + 8;
    int cbase = (lane & 3) << 1;
    int br = lane & 15, bc = (lane >> 4) << 3;

    int nt = blockIdx.x + 1;
    issue(0, 0);
    if (nt > 1) issue(64, 1); else CP_COMMIT();
    for (int t = 0; t < nt; t++) {
        int k0 = t << 6;
        CP_WAIT1();
        __syncthreads();
        if (t + 2 < nt) issue((t + 2) << 6, (t + 2) % 3); else CP_COMMIT();
        uint32_t bu = sbase + (t % 3)*ATT_STAGE_B;
        uint32_t skh_u = bu, sv_u = bu + 9216;

        // --- S phase: 1-term Q x K (Q pre-scaled, log2 domain) ---
        float s[8][4];
        #pragma unroll
        for (int ntt = 0; ntt < 8; ntt++)
            #pragma unroll
            for (int j = 0; j < 4; j++) s[ntt][j] = 0.f;
        #pragma unroll
        for (int ntp = 0; ntp < 4; ntp++) {
            #pragma unroll
            for (int kc = 0; kc < 4; kc++) {
                uint32_t r4h[4];
                uint32_t off = (uint32_t)(((ntp*16 + br)*72 + kc*16 + bc) << 1);
                ldsm4(r4h, skh_u + off);
                uint32_t be[2] = {r4h[0], r4h[2]}, bo[2] = {r4h[1], r4h[3]};
                mma16816(s[2*ntp],   qf[kc], be);
                mma16816(s[2*ntp+1], qf[kc], bo);
            }
        }

        // --- softmax (exp2; scale folded into Q) ---
        if (k0 + 63 > q0) {
            #pragma unroll
            for (int ntt = 0; ntt < 8; ntt++) {
                int key = k0 + ntt*8 + cbase;
                if (key   > qr0) s[ntt][0] = -INFINITY;
                if (key+1 > qr0) s[ntt][1] = -INFINITY;
                if (key   > qr1) s[ntt][2] = -INFINITY;
                if (key+1 > qr1) s[ntt][3] = -INFINITY;
            }
        }
        float mt0 = m0, mt1 = m1;
        #pragma unroll
        for (int ntt = 0; ntt < 8; ntt++) {
            mt0 = fmaxf(mt0, fmaxf(s[ntt][0], s[ntt][1]));
            mt1 = fmaxf(mt1, fmaxf(s[ntt][2], s[ntt][3]));
        }
        mt0 = fmaxf(mt0, __shfl_xor_sync(~0u, mt0, 1));
        mt0 = fmaxf(mt0, __shfl_xor_sync(~0u, mt0, 2));
        mt1 = fmaxf(mt1, __shfl_xor_sync(~0u, mt1, 1));
        mt1 = fmaxf(mt1, __shfl_xor_sync(~0u, mt1, 2));
        float c0 = exp2f(m0 - mt0), c1 = exp2f(m1 - mt1);
        m0 = mt0; m1 = mt1;
        float ps0 = 0.f, ps1 = 0.f;
        uint32_t pf[4][4];
        #pragma unroll
        for (int kp = 0; kp < 4; kp++) {
            float p00 = exp2f(s[2*kp][0]   - m0), p01 = exp2f(s[2*kp][1]   - m0);
            float p10 = exp2f(s[2*kp][2]   - m1), p11 = exp2f(s[2*kp][3]   - m1);
            float p20 = exp2f(s[2*kp+1][0] - m0), p21 = exp2f(s[2*kp+1][1] - m0);
            float p30 = exp2f(s[2*kp+1][2] - m1), p31 = exp2f(s[2*kp+1][3] - m1);
            ps0 += p00 + p01 + p20 + p21;
            ps1 += p10 + p11 + p30 + p31;
            pf[kp][0] = packhf(p00, p01);
            pf[kp][1] = packhf(p10, p11);
            pf[kp][2] = packhf(p20, p21);
            pf[kp][3] = packhf(p30, p31);
        }
        l0 = l0*c0 + ps0;
        l1 = l1*c1 + ps1;
        #pragma unroll
        for (int dt = 0; dt < 8; dt++) {
            oa[dt][0] *= c0; oa[dt][1] *= c0;
            oa[dt][2] *= c1; oa[dt][3] *= c1;
        }

        // --- PV phase: single-V ---
        #pragma unroll
        for (int dtp = 0; dtp < 4; dtp++) {
            #pragma unroll
            for (int kc = 0; kc < 4; kc++) {
                uint32_t t4[4];
                uint32_t off = (uint32_t)(((kc*16 + br)*72 + dtp*16 + bc) << 1);
                ldsm4t(t4, sv_u + off);
                uint32_t b0[2] = {t4[0], t4[1]}, b1[2] = {t4[2], t4[3]};
                mma16816(oa[2*dtp],   pf[kc], b0);
                mma16816(oa[2*dtp+1], pf[kc], b1);
            }
        }
    }

    l0 += __shfl_xor_sync(~0u, l0, 1);
    l0 += __shfl_xor_sync(~0u, l0, 2);
    l1 += __shfl_xor_sync(~0u, l1, 1);
    l1 += __shfl_xor_sync(~0u, l1, 2);
    float i0 = 1.f / l0, i1 = 1.f / l1;
    int mode = mode_base + blockIdx.z;

    float xv[8][4];
    #pragma unroll
    for (int dt = 0; dt < 8; dt++) {
        xv[dt][0] = oa[dt][0]*i0; xv[dt][1] = oa[dt][1]*i0;
        xv[dt][2] = oa[dt][2]*i1; xv[dt][3] = oa[dt][3]*i1;
    }

    if (mode == 1) {
        float s0 = 0.f, s1 = 0.f;
        #pragma unroll
        for (int dt = 0; dt < 8; dt++) {
            s0 += xv[dt][0]*xv[dt][0] + xv[dt][1]*xv[dt][1];
            s1 += xv[dt][2]*xv[dt][2] + xv[dt][3]*xv[dt][3];
        }
        s0 += __shfl_xor_sync(~0u, s0, 1);
        s0 += __shfl_xor_sync(~0u, s0, 2);
        s1 += __shfl_xor_sync(~0u, s1, 1);
        s1 += __shfl_xor_sync(~0u, s1, 2);
        float inv0 = rsqrtf(s0 * (1.f/DH_) + EPS_);
        float inv1 = rsqrtf(s1 * (1.f/DH_) + EPS_);
        #pragma unroll
        for (int dt = 0; dt < 8; dt++) {
            int col = dt*8 + cbase;
            float wa = wnorm[col], wb = wnorm[col+1];
            xv[dt][0] *= inv0*wa; xv[dt][1] *= inv0*wb;
            xv[dt][2] *= inv1*wa; xv[dt][3] *= inv1*wb;
        }
    }
    if (mode <= 1) {
        float qsc = (mode == 0) ? QSCALE_ : 1.f;   // nq is outer-attention Q
        #pragma unroll
        for (int dt = 0; dt < 8; dt++) {
            int tt = dt*4 + (lane & 3);
            float ca = g_cos[(qr0 << 5) + tt], sa = g_sin[(qr0 << 5) + tt];
            float cb = g_cos[(qr1 << 5) + tt], sb = g_sin[(qr1 << 5) + tt];
            float x0 = xv[dt][0], y0 = xv[dt][1];
            float x1 = xv[dt][2], y1 = xv[dt][3];
            xv[dt][0] = (x0*ca - y0*sa)*qsc; xv[dt][1] = (y0*ca + x0*sa)*qsc;
            xv[dt][2] = (x1*cb - y1*sb)*qsc; xv[dt][3] = (y1*cb + x1*sb)*qsc;
        }
    }

    if (mode <= 2) {
        __half* oh = OH + (mat << 17);
        #pragma unroll
        for (int dt = 0; dt < 8; dt++) {
            int col = dt*8 + cbase;
            *(uint32_t*)&oh[((size_t)qr0 << 6) + col] = packhf(xv[dt][0], xv[dt][1]);
            *(uint32_t*)&oh[((size_t)qr1 << 6) + col] = packhf(xv[dt][2], xv[dt][3]);
        }
    } else {
        int b = (int)(mat >> 4), h = (int)(mat & 15);
        size_t base0 = ((size_t)b*N_ + qr0)*DIM_ + h*64;
        size_t base1 = ((size_t)b*N_ + qr1)*DIM_ + h*64;
        #pragma unroll
        for (int dt = 0; dt < 8; dt++) {
            int col = dt*8 + cbase;
            *(uint32_t*)&OH[base0 + col] = packhf(xv[dt][0], xv[dt][1]);
            *(uint32_t*)&OH[base1 + col] = packhf(xv[dt][2], xv[dt][3]);
        }
    }
}

// ---------------------------------------------------------------------------
// Launch
// ---------------------------------------------------------------------------
extern "C" void kernel_launch(void* const* d_in, const int* in_sizes, int n_in,
                              void* d_out, int out_size) {
    const float* tokens        = (const float*)d_in[0];
    const float* w_norm        = (const float*)d_in[1];
    const float* w_q           = (const float*)d_in[2];
    const float* w_k           = (const float*)d_in[3];
    const float* w_v           = (const float*)d_in[4];
    const float* w_key_norms   = (const float*)d_in[5];
    const float* w_nested_knorm= (const float*)d_in[6];
    const float* w_out         = (const float*)d_in[7];
    float* out = (float*)d_out;

    __half *pxh, *pwh, *poh;
    __half *pqh, *pkh, *pvh, *pnh;
    cudaGetSymbolAddress((void**)&pxh, g_xh);
    cudaGetSymbolAddress((void**)&pwh, g_wh);
    cudaGetSymbolAddress((void**)&poh, g_oh);
    cudaGetSymbolAddress((void**)&pqh, g_qh);
    cudaGetSymbolAddress((void**)&pkh, g_kh);
    cudaGetSymbolAddress((void**)&pvh, g_vh);
    cudaGetSymbolAddress((void**)&pnh, g_nh);

    static int attr_set = 0;
    if (!attr_set) {
        cudaFuncSetAttribute(hgemm_kernel<0>, cudaFuncAttributeMaxDynamicSharedMemorySize, HG_SMEM);
        cudaFuncSetAttribute(hgemm_kernel<4>, cudaFuncAttributeMaxDynamicSharedMemorySize, HG_SMEM);
        cudaFuncSetAttribute(hgemm_kernel<6>, cudaFuncAttributeMaxDynamicSharedMemorySize, HG_SMEM);
        cudaFuncSetAttribute(attn5_kernel, cudaFuncAttributeMaxDynamicSharedMemorySize, ATTN5_SMEM);
        attr_set = 1;
    }

    // 1) fused prep: rmsnorm -> fp16, rope tables, weight converts (kv interleaved)
    prep_kernel<<<12544, 256>>>(tokens, w_norm, w_q, w_k, w_v, w_out, pxh, pwh);
    // 2) projections (HMMA fp16), epilogue-fused:
    //    q: rope + QSCALE;  merged k|v: rmsnorm(w_key_norms)+rope / plain
    hgemm_kernel<4><<<dim3(8, 32),  256, HG_SMEM>>>(pxh, pwh + WQ_OFF, nullptr, pqh, nullptr, nullptr, DIM_, DIM_);
    hgemm_kernel<6><<<dim3(48, 32), 256, HG_SMEM>>>(pxh, pwh + WKV_OFF, nullptr, pkh, pvh, w_key_norms, DIM_, 6144);
    // 3) three inner causal attentions; epilogues: nq rope+scale, nk rmsnorm+rope, nv plain
    attn5_kernel<<<dim3(N_/64, BH_, 3), 128, ATTN5_SMEM>>>(pqh, pkh, pvh,
                                                           pnh, w_nested_knorm, 0);
    // 4) outer causal attention; epilogue writes gathered (b*n, h*d) single fp16
    attn5_kernel<<<dim3(N_/64, BH_, 1), 128, ATTN5_SMEM>>>(pnh, pnh + SLAB_, pnh + 2*SLAB_,
                                                           poh, nullptr, 3);
    // 5) output projection (HMMA fp16)
    hgemm_kernel<0><<<dim3(8, 32), 256, HG_SMEM>>>(poh, pwh + WO_OFF, out, nullptr, nullptr, nullptr, DIM_, DIM_);
}